// round 1
// baseline (speedup 1.0000x reference)
#include <cuda_runtime.h>

// Problem constants
#define Bb 4
#define Lq 2052
#define Cc 1024
#define Hh 16
#define Dd 64
#define NREG 4
#define ROWS (Bb * Lq)          // 8208
#define ROPE_PLANE ((Lq - NREG) * Dd)  // 2048*64

// -------- scratch (device globals; no allocation allowed) ------------------
__device__ float g_qkv[(size_t)ROWS * 3 * Cc];   // [B*L, 3C]
__device__ float g_q[(size_t)Bb * Hh * Lq * Dd]; // [B,H,L,D]
__device__ float g_k[(size_t)Bb * Hh * Lq * Dd];
__device__ float g_v[(size_t)Bb * Hh * Lq * Dd];
__device__ float g_attn[(size_t)ROWS * Cc];      // [B,L,C]
__device__ float g_ln[(size_t)ROWS * Cc];

// ---------------------------------------------------------------------------
// Generic GEMM: C[M,N] = A[M,K] @ B[K,N] + bias[N]   (all row-major, fp32)
// 64x64 tile, BK=16, 256 threads, 4x4 microtile per thread.
// Requires: K % 16 == 0, N % 64 == 0. M may be ragged.
// ---------------------------------------------------------------------------
__global__ void gemm_bias_kernel(const float* __restrict__ A,
                                 const float* __restrict__ Bm,
                                 const float* __restrict__ bias,
                                 float* __restrict__ Cm,
                                 int M, int N, int K) {
    __shared__ float Ast[16][68];  // transposed: [k][m]
    __shared__ float Bs[16][68];   // [k][n]
    int tid = threadIdx.x;
    int m0 = blockIdx.y * 64, n0 = blockIdx.x * 64;
    int ty = tid >> 4, tx = tid & 15;

    float acc[4][4];
#pragma unroll
    for (int i = 0; i < 4; i++)
#pragma unroll
        for (int j = 0; j < 4; j++) acc[i][j] = 0.f;

    int am = tid >> 2, ak4 = (tid & 3) * 4;   // A: row am (0..63), k-cols ak4..+3
    int bk = tid >> 4, bn4 = (tid & 15) * 4;  // B: k-row bk (0..15), n-cols bn4..+3

    for (int k0 = 0; k0 < K; k0 += 16) {
        float4 av = make_float4(0.f, 0.f, 0.f, 0.f);
        if (m0 + am < M)
            av = *(const float4*)&A[(size_t)(m0 + am) * K + k0 + ak4];
        Ast[ak4 + 0][am] = av.x;
        Ast[ak4 + 1][am] = av.y;
        Ast[ak4 + 2][am] = av.z;
        Ast[ak4 + 3][am] = av.w;
        float4 bv = *(const float4*)&Bm[(size_t)(k0 + bk) * N + n0 + bn4];
        *(float4*)&Bs[bk][bn4] = bv;
        __syncthreads();
#pragma unroll
        for (int kk = 0; kk < 16; kk++) {
            float4 af = *(float4*)&Ast[kk][ty * 4];
            float4 bf = *(float4*)&Bs[kk][tx * 4];
            float a_[4] = {af.x, af.y, af.z, af.w};
            float b_[4] = {bf.x, bf.y, bf.z, bf.w};
#pragma unroll
            for (int i = 0; i < 4; i++)
#pragma unroll
                for (int j = 0; j < 4; j++) acc[i][j] += a_[i] * b_[j];
        }
        __syncthreads();
    }

#pragma unroll
    for (int i = 0; i < 4; i++) {
        int m = m0 + ty * 4 + i;
        if (m >= M) continue;
#pragma unroll
        for (int j = 0; j < 4; j++) {
            int n = n0 + tx * 4 + j;
            Cm[(size_t)m * N + n] = acc[i][j] + bias[n];
        }
    }
}

// ---------------------------------------------------------------------------
// RoPE + transpose: qkv[B*L, 3C] -> Q,K,V [B,H,L,D], rope applied to q,k for
// tokens l >= NREG.
// ---------------------------------------------------------------------------
__global__ void rope_kernel(const float* __restrict__ qkv,
                            const float* __restrict__ rope,
                            float* __restrict__ Q, float* __restrict__ K,
                            float* __restrict__ V) {
    int idx = blockIdx.x * blockDim.x + threadIdx.x;
    int total = Bb * Hh * Lq * Dd;
    if (idx >= total) return;
    int d = idx & 63;
    int l = (idx >> 6) % Lq;
    int h = (idx / (Dd * Lq)) % Hh;
    int b = idx / (Dd * Lq * Hh);

    size_t base = ((size_t)b * Lq + l) * (3 * Cc);
    int col = h * Dd + d;
    float q = qkv[base + col];
    float k = qkv[base + Cc + col];
    float v = qkv[base + 2 * Cc + col];
    if (l >= NREG) {
        int dp = d ^ 32;
        float sgn = (d < 32) ? -1.f : 1.f;
        float qp = qkv[base + h * Dd + dp];
        float kp = qkv[base + Cc + h * Dd + dp];
        float cv = rope[(size_t)(l - NREG) * Dd + d];
        float sv = rope[(size_t)ROPE_PLANE + (size_t)(l - NREG) * Dd + d];
        q = q * cv + sgn * qp * sv;
        k = k * cv + sgn * kp * sv;
    }
    size_t oidx = ((size_t)(b * Hh + h) * Lq + l) * Dd + d;
    Q[oidx] = q;
    K[oidx] = k;
    V[oidx] = v;
}

// ---------------------------------------------------------------------------
// Flash attention (fp32): per (b,h,qtile of 64), stream KV tiles of 64.
// 256 threads as 16x16; each thread owns a 4x4 S microtile and 4x4 O microtile.
// Output written directly to [B,L,C] layout for LayerNorm.
// smem: Qst/Kst (d-major), Vs (row-major), Ps — 4 * 64*68*4 = 69632 bytes.
// ---------------------------------------------------------------------------
#define FLASH_SMEM (4 * 64 * 68 * 4)

__global__ void flash_kernel(const float* __restrict__ Q,
                             const float* __restrict__ K,
                             const float* __restrict__ V,
                             float* __restrict__ O) {
    extern __shared__ float sm[];
    float(*Qst)[68] = (float(*)[68])sm;               // [d][q]
    float(*Kst)[68] = (float(*)[68])(sm + 64 * 68);    // [d][k]
    float(*Vs)[68] = (float(*)[68])(sm + 2 * 64 * 68); // [k][d]
    float(*Ps)[68] = (float(*)[68])(sm + 3 * 64 * 68); // [q][k]

    int tid = threadIdx.x;
    int q0 = blockIdx.x * 64;
    int h = blockIdx.y, b = blockIdx.z;
    const float* Qb = Q + ((size_t)(b * Hh + h) * Lq) * Dd;
    const float* Kb = K + ((size_t)(b * Hh + h) * Lq) * Dd;
    const float* Vb = V + ((size_t)(b * Hh + h) * Lq) * Dd;
    int ty = tid >> 4, tx = tid & 15;

    // Load Q tile transposed (zero-pad ragged rows)
    for (int p = 0; p < 4; p++) {
        int f = p * 256 + tid;
        int r = f >> 4, c4 = (f & 15) * 4;
        float4 v = make_float4(0.f, 0.f, 0.f, 0.f);
        if (q0 + r < Lq) v = *(const float4*)&Qb[(size_t)(q0 + r) * Dd + c4];
        Qst[c4 + 0][r] = v.x;
        Qst[c4 + 1][r] = v.y;
        Qst[c4 + 2][r] = v.z;
        Qst[c4 + 3][r] = v.w;
    }

    float m_[4], l_[4], o_[4][4];
#pragma unroll
    for (int i = 0; i < 4; i++) {
        m_[i] = -1e30f;
        l_[i] = 0.f;
#pragma unroll
        for (int j = 0; j < 4; j++) o_[i][j] = 0.f;
    }
    __syncthreads();

    int nk = (Lq + 63) / 64;  // 33
    for (int kt = 0; kt < nk; kt++) {
        int k0 = kt * 64;
        for (int p = 0; p < 4; p++) {
            int f = p * 256 + tid;
            int r = f >> 4, c4 = (f & 15) * 4;
            float4 kv = make_float4(0.f, 0.f, 0.f, 0.f);
            float4 vv = make_float4(0.f, 0.f, 0.f, 0.f);
            if (k0 + r < Lq) {
                kv = *(const float4*)&Kb[(size_t)(k0 + r) * Dd + c4];
                vv = *(const float4*)&Vb[(size_t)(k0 + r) * Dd + c4];
            }
            Kst[c4 + 0][r] = kv.x;
            Kst[c4 + 1][r] = kv.y;
            Kst[c4 + 2][r] = kv.z;
            Kst[c4 + 3][r] = kv.w;
            *(float4*)&Vs[r][c4] = vv;
        }
        __syncthreads();

        float s_[4][4];
#pragma unroll
        for (int i = 0; i < 4; i++)
#pragma unroll
            for (int j = 0; j < 4; j++) s_[i][j] = 0.f;

#pragma unroll 8
        for (int kk = 0; kk < 64; kk++) {
            float4 qf = *(float4*)&Qst[kk][ty * 4];
            float4 kf = *(float4*)&Kst[kk][tx * 4];
            float qa[4] = {qf.x, qf.y, qf.z, qf.w};
            float ka[4] = {kf.x, kf.y, kf.z, kf.w};
#pragma unroll
            for (int i = 0; i < 4; i++)
#pragma unroll
                for (int j = 0; j < 4; j++) s_[i][j] += qa[i] * ka[j];
        }

        const float scale = 0.125f;  // 1/sqrt(64)
#pragma unroll
        for (int i = 0; i < 4; i++)
#pragma unroll
            for (int j = 0; j < 4; j++) {
                int kg = k0 + tx * 4 + j;
                s_[i][j] = (kg < Lq) ? s_[i][j] * scale : -1e30f;
            }

#pragma unroll
        for (int i = 0; i < 4; i++) {
            float mx = fmaxf(fmaxf(s_[i][0], s_[i][1]), fmaxf(s_[i][2], s_[i][3]));
#pragma unroll
            for (int off = 8; off >= 1; off >>= 1)
                mx = fmaxf(mx, __shfl_xor_sync(0xffffffffu, mx, off));
            float mnew = fmaxf(m_[i], mx);
            float alpha = __expf(m_[i] - mnew);
            float rs = 0.f;
#pragma unroll
            for (int j = 0; j < 4; j++) {
                s_[i][j] = __expf(s_[i][j] - mnew);
                rs += s_[i][j];
            }
#pragma unroll
            for (int off = 8; off >= 1; off >>= 1)
                rs += __shfl_xor_sync(0xffffffffu, rs, off);
            l_[i] = l_[i] * alpha + rs;
            m_[i] = mnew;
#pragma unroll
            for (int j = 0; j < 4; j++) o_[i][j] *= alpha;
#pragma unroll
            for (int j = 0; j < 4; j++) Ps[ty * 4 + i][tx * 4 + j] = s_[i][j];
        }
        __syncthreads();

#pragma unroll 4
        for (int j = 0; j < 64; j++) {
            float4 vf = *(float4*)&Vs[j][tx * 4];
            float va[4] = {vf.x, vf.y, vf.z, vf.w};
#pragma unroll
            for (int i = 0; i < 4; i++) {
                float p = Ps[ty * 4 + i][j];
#pragma unroll
                for (int c = 0; c < 4; c++) o_[i][c] += p * va[c];
            }
        }
        __syncthreads();
    }

#pragma unroll
    for (int i = 0; i < 4; i++) {
        int l = q0 + ty * 4 + i;
        if (l >= Lq) continue;
        float inv = 1.f / l_[i];
#pragma unroll
        for (int c = 0; c < 4; c++) {
            O[((size_t)b * Lq + l) * Cc + h * Dd + tx * 4 + c] = o_[i][c] * inv;
        }
    }
}

// ---------------------------------------------------------------------------
// LayerNorm over C=1024 per row; 256 threads, float4 per thread.
// ---------------------------------------------------------------------------
__global__ void ln_kernel(const float* __restrict__ in,
                          const float* __restrict__ gamma,
                          const float* __restrict__ beta,
                          float* __restrict__ out) {
    int row = blockIdx.x;
    int tid = threadIdx.x;
    const float* r = in + (size_t)row * Cc;
    float4 v = *(const float4*)&r[tid * 4];
    float s = v.x + v.y + v.z + v.w;
    float s2 = v.x * v.x + v.y * v.y + v.z * v.z + v.w * v.w;
#pragma unroll
    for (int off = 16; off >= 1; off >>= 1) {
        s += __shfl_xor_sync(0xffffffffu, s, off);
        s2 += __shfl_xor_sync(0xffffffffu, s2, off);
    }
    __shared__ float ws[8], ws2[8];
    __shared__ float mean_s, rstd_s;
    int wid = tid >> 5, lane = tid & 31;
    if (lane == 0) {
        ws[wid] = s;
        ws2[wid] = s2;
    }
    __syncthreads();
    if (tid == 0) {
        float S = 0.f, S2 = 0.f;
#pragma unroll
        for (int i = 0; i < 8; i++) {
            S += ws[i];
            S2 += ws2[i];
        }
        float mean = S * (1.f / Cc);
        float var = S2 * (1.f / Cc) - mean * mean;
        mean_s = mean;
        rstd_s = rsqrtf(var + 1e-5f);
    }
    __syncthreads();
    float mean = mean_s, rstd = rstd_s;
    float4 g = *(const float4*)&gamma[tid * 4];
    float4 bt = *(const float4*)&beta[tid * 4];
    float4 o;
    o.x = (v.x - mean) * rstd * g.x + bt.x;
    o.y = (v.y - mean) * rstd * g.y + bt.y;
    o.z = (v.z - mean) * rstd * g.z + bt.z;
    o.w = (v.w - mean) * rstd * g.w + bt.w;
    *(float4*)&out[(size_t)row * Cc + tid * 4] = o;
}

// ---------------------------------------------------------------------------
extern "C" void kernel_launch(void* const* d_in, const int* in_sizes, int n_in,
                              void* d_out, int out_size) {
    const float* x = (const float*)d_in[0];
    const float* rope = (const float*)d_in[1];
    const float* Wqkv = (const float*)d_in[2];
    const float* bqkv = (const float*)d_in[3];
    const float* Wproj = (const float*)d_in[4];
    const float* bproj = (const float*)d_in[5];
    const float* gamma = (const float*)d_in[6];
    const float* beta = (const float*)d_in[7];
    float* out = (float*)d_out;

    float *qkv, *q, *k, *v, *attn, *ln;
    cudaGetSymbolAddress((void**)&qkv, g_qkv);
    cudaGetSymbolAddress((void**)&q, g_q);
    cudaGetSymbolAddress((void**)&k, g_k);
    cudaGetSymbolAddress((void**)&v, g_v);
    cudaGetSymbolAddress((void**)&attn, g_attn);
    cudaGetSymbolAddress((void**)&ln, g_ln);

    const int M = ROWS;  // 8208

    // 1) QKV GEMM: [8208,1024] @ [1024,3072] + bqkv
    gemm_bias_kernel<<<dim3(3 * Cc / 64, (M + 63) / 64), 256>>>(
        x, Wqkv, bqkv, qkv, M, 3 * Cc, Cc);

    // 2) RoPE + transpose to [B,H,L,D]
    int total = Bb * Hh * Lq * Dd;
    rope_kernel<<<(total + 255) / 256, 256>>>(qkv, rope, q, k, v);

    // 3) Flash attention -> [B,L,C]
    cudaFuncSetAttribute(flash_kernel, cudaFuncAttributeMaxDynamicSharedMemorySize,
                         FLASH_SMEM);
    flash_kernel<<<dim3((Lq + 63) / 64, Hh, Bb), 256, FLASH_SMEM>>>(q, k, v, attn);

    // 4) LayerNorm
    ln_kernel<<<M, 256>>>(attn, gamma, beta, ln);

    // 5) Projection GEMM: [8208,1024] @ [1024,1024] + bproj -> d_out
    gemm_bias_kernel<<<dim3(Cc / 64, (M + 63) / 64), 256>>>(
        ln, Wproj, bproj, out, M, Cc, Cc);
}

// round 2
// speedup vs baseline: 1.4804x; 1.4804x over previous
#include <cuda_runtime.h>

// Problem constants
#define Bb 4
#define Lq 2052
#define Cc 1024
#define Hh 16
#define Dd 64
#define NREG 4
#define ROWS (Bb * Lq)          // 8208
#define ROPE_PLANE ((Lq - NREG) * Dd)  // 2048*64

// -------- scratch (device globals; no allocation allowed) ------------------
__device__ float g_qkv[(size_t)ROWS * 3 * Cc];   // [B*L, 3C]
__device__ float g_q[(size_t)Bb * Hh * Lq * Dd]; // [B,H,L,D]
__device__ float g_k[(size_t)Bb * Hh * Lq * Dd];
__device__ float g_v[(size_t)Bb * Hh * Lq * Dd];
__device__ float g_attn[(size_t)ROWS * Cc];      // [B,L,C]
__device__ float g_ln[(size_t)ROWS * Cc];

// ---------------------------------------------------------------------------
// tf32 helpers
// ---------------------------------------------------------------------------
__device__ __forceinline__ unsigned f2tf32(float f) {
    unsigned u;
    asm("cvt.rna.tf32.f32 %0, %1;" : "=r"(u) : "f"(f));
    return u;
}

__device__ __forceinline__ void mma_tf32(float* c, const unsigned* a,
                                         const unsigned* b) {
    asm volatile(
        "mma.sync.aligned.m16n8k8.row.col.f32.tf32.tf32.f32 "
        "{%0,%1,%2,%3}, {%4,%5,%6,%7}, {%8,%9}, {%0,%1,%2,%3};"
        : "+f"(c[0]), "+f"(c[1]), "+f"(c[2]), "+f"(c[3])
        : "r"(a[0]), "r"(a[1]), "r"(a[2]), "r"(a[3]), "r"(b[0]), "r"(b[1]));
}

// ---------------------------------------------------------------------------
// tf32 tensor-core GEMM: C[M,N] = A[M,K] @ B[K,N] + bias[N]  (row-major fp32)
// Block tile 128x128, BK=32, 256 threads = 8 warps (2m x 4n), warp tile 64x32.
// mma.m16n8k8: per warp 4 m-frags x 4 n-frags. Requires K%32==0, N%128==0.
// ---------------------------------------------------------------------------
__global__ __launch_bounds__(256) void gemm_tf32_kernel(
    const float* __restrict__ A, const float* __restrict__ Bm,
    const float* __restrict__ bias, float* __restrict__ Cm,
    int M, int N, int K) {
    __shared__ unsigned As[128][36];   // [m][k], stride 36 (conflict-free)
    __shared__ unsigned Bs[32][132];   // [k][n], stride 132 (conflict-free)

    int tid = threadIdx.x;
    int warp = tid >> 5, lane = tid & 31;
    int g = lane >> 2, t = lane & 3;
    int wm = (warp >> 2) * 64, wn = (warp & 3) * 32;
    int m0 = blockIdx.y * 128, n0 = blockIdx.x * 128;

    float acc[4][4][4];
#pragma unroll
    for (int mt = 0; mt < 4; mt++)
#pragma unroll
        for (int nt = 0; nt < 4; nt++)
#pragma unroll
            for (int r = 0; r < 4; r++) acc[mt][nt][r] = 0.f;

    int arow = tid >> 3, acol = (tid & 7) * 4;   // A: rows arow+32p, cols acol..+3
    int brow = tid >> 5, bcol = (tid & 31) * 4;  // B: rows brow+8p,  cols bcol..+3

    for (int k0 = 0; k0 < K; k0 += 32) {
#pragma unroll
        for (int p = 0; p < 4; p++) {
            int r = arow + 32 * p;
            float4 v = make_float4(0.f, 0.f, 0.f, 0.f);
            if (m0 + r < M)
                v = *(const float4*)&A[(size_t)(m0 + r) * K + k0 + acol];
            As[r][acol + 0] = f2tf32(v.x);
            As[r][acol + 1] = f2tf32(v.y);
            As[r][acol + 2] = f2tf32(v.z);
            As[r][acol + 3] = f2tf32(v.w);
        }
#pragma unroll
        for (int p = 0; p < 4; p++) {
            int r = brow + 8 * p;
            float4 v = *(const float4*)&Bm[(size_t)(k0 + r) * N + n0 + bcol];
            Bs[r][bcol + 0] = f2tf32(v.x);
            Bs[r][bcol + 1] = f2tf32(v.y);
            Bs[r][bcol + 2] = f2tf32(v.z);
            Bs[r][bcol + 3] = f2tf32(v.w);
        }
        __syncthreads();

#pragma unroll
        for (int ks = 0; ks < 4; ks++) {
            unsigned af[4][4], bf[4][2];
#pragma unroll
            for (int mt = 0; mt < 4; mt++) {
                int row = wm + mt * 16 + g;
                int kc = ks * 8 + t;
                af[mt][0] = As[row][kc];
                af[mt][1] = As[row + 8][kc];
                af[mt][2] = As[row][kc + 4];
                af[mt][3] = As[row + 8][kc + 4];
            }
#pragma unroll
            for (int nt = 0; nt < 4; nt++) {
                int col = wn + nt * 8 + g;
                bf[nt][0] = Bs[ks * 8 + t][col];
                bf[nt][1] = Bs[ks * 8 + t + 4][col];
            }
#pragma unroll
            for (int mt = 0; mt < 4; mt++)
#pragma unroll
                for (int nt = 0; nt < 4; nt++)
                    mma_tf32(acc[mt][nt], af[mt], bf[nt]);
        }
        __syncthreads();
    }

    // Epilogue: c0:(row,col) c1:(row,col+1) c2:(row+8,col) c3:(row+8,col+1)
#pragma unroll
    for (int mt = 0; mt < 4; mt++) {
        int row = m0 + wm + mt * 16 + g;
#pragma unroll
        for (int nt = 0; nt < 4; nt++) {
            int col = n0 + wn + nt * 8 + t * 2;
            float b0 = bias[col], b1 = bias[col + 1];
            if (row < M) {
                *(float2*)&Cm[(size_t)row * N + col] =
                    make_float2(acc[mt][nt][0] + b0, acc[mt][nt][1] + b1);
            }
            if (row + 8 < M) {
                *(float2*)&Cm[(size_t)(row + 8) * N + col] =
                    make_float2(acc[mt][nt][2] + b0, acc[mt][nt][3] + b1);
            }
        }
    }
}

// ---------------------------------------------------------------------------
// RoPE + transpose: qkv[B*L, 3C] -> Q,K,V [B,H,L,D]
// ---------------------------------------------------------------------------
__global__ void rope_kernel(const float* __restrict__ qkv,
                            const float* __restrict__ rope,
                            float* __restrict__ Q, float* __restrict__ K,
                            float* __restrict__ V) {
    int idx = blockIdx.x * blockDim.x + threadIdx.x;
    int total = Bb * Hh * Lq * Dd;
    if (idx >= total) return;
    int d = idx & 63;
    int l = (idx >> 6) % Lq;
    int h = (idx / (Dd * Lq)) % Hh;
    int b = idx / (Dd * Lq * Hh);

    size_t base = ((size_t)b * Lq + l) * (3 * Cc);
    int col = h * Dd + d;
    float q = qkv[base + col];
    float k = qkv[base + Cc + col];
    float v = qkv[base + 2 * Cc + col];
    if (l >= NREG) {
        int dp = d ^ 32;
        float sgn = (d < 32) ? -1.f : 1.f;
        float qp = qkv[base + h * Dd + dp];
        float kp = qkv[base + Cc + h * Dd + dp];
        float cv = rope[(size_t)(l - NREG) * Dd + d];
        float sv = rope[(size_t)ROPE_PLANE + (size_t)(l - NREG) * Dd + d];
        q = q * cv + sgn * qp * sv;
        k = k * cv + sgn * kp * sv;
    }
    size_t oidx = ((size_t)(b * Hh + h) * Lq + l) * Dd + d;
    Q[oidx] = q;
    K[oidx] = k;
    V[oidx] = v;
}

// ---------------------------------------------------------------------------
// Flash attention (fp32), unchanged from round 1.
// ---------------------------------------------------------------------------
#define FLASH_SMEM (4 * 64 * 68 * 4)

__global__ void flash_kernel(const float* __restrict__ Q,
                             const float* __restrict__ K,
                             const float* __restrict__ V,
                             float* __restrict__ O) {
    extern __shared__ float sm[];
    float(*Qst)[68] = (float(*)[68])sm;               // [d][q]
    float(*Kst)[68] = (float(*)[68])(sm + 64 * 68);    // [d][k]
    float(*Vs)[68] = (float(*)[68])(sm + 2 * 64 * 68); // [k][d]
    float(*Ps)[68] = (float(*)[68])(sm + 3 * 64 * 68); // [q][k]

    int tid = threadIdx.x;
    int q0 = blockIdx.x * 64;
    int h = blockIdx.y, b = blockIdx.z;
    const float* Qb = Q + ((size_t)(b * Hh + h) * Lq) * Dd;
    const float* Kb = K + ((size_t)(b * Hh + h) * Lq) * Dd;
    const float* Vb = V + ((size_t)(b * Hh + h) * Lq) * Dd;
    int ty = tid >> 4, tx = tid & 15;

    for (int p = 0; p < 4; p++) {
        int f = p * 256 + tid;
        int r = f >> 4, c4 = (f & 15) * 4;
        float4 v = make_float4(0.f, 0.f, 0.f, 0.f);
        if (q0 + r < Lq) v = *(const float4*)&Qb[(size_t)(q0 + r) * Dd + c4];
        Qst[c4 + 0][r] = v.x;
        Qst[c4 + 1][r] = v.y;
        Qst[c4 + 2][r] = v.z;
        Qst[c4 + 3][r] = v.w;
    }

    float m_[4], l_[4], o_[4][4];
#pragma unroll
    for (int i = 0; i < 4; i++) {
        m_[i] = -1e30f;
        l_[i] = 0.f;
#pragma unroll
        for (int j = 0; j < 4; j++) o_[i][j] = 0.f;
    }
    __syncthreads();

    int nk = (Lq + 63) / 64;  // 33
    for (int kt = 0; kt < nk; kt++) {
        int k0 = kt * 64;
        for (int p = 0; p < 4; p++) {
            int f = p * 256 + tid;
            int r = f >> 4, c4 = (f & 15) * 4;
            float4 kv = make_float4(0.f, 0.f, 0.f, 0.f);
            float4 vv = make_float4(0.f, 0.f, 0.f, 0.f);
            if (k0 + r < Lq) {
                kv = *(const float4*)&Kb[(size_t)(k0 + r) * Dd + c4];
                vv = *(const float4*)&Vb[(size_t)(k0 + r) * Dd + c4];
            }
            Kst[c4 + 0][r] = kv.x;
            Kst[c4 + 1][r] = kv.y;
            Kst[c4 + 2][r] = kv.z;
            Kst[c4 + 3][r] = kv.w;
            *(float4*)&Vs[r][c4] = vv;
        }
        __syncthreads();

        float s_[4][4];
#pragma unroll
        for (int i = 0; i < 4; i++)
#pragma unroll
            for (int j = 0; j < 4; j++) s_[i][j] = 0.f;

#pragma unroll 8
        for (int kk = 0; kk < 64; kk++) {
            float4 qf = *(float4*)&Qst[kk][ty * 4];
            float4 kf = *(float4*)&Kst[kk][tx * 4];
            float qa[4] = {qf.x, qf.y, qf.z, qf.w};
            float ka[4] = {kf.x, kf.y, kf.z, kf.w};
#pragma unroll
            for (int i = 0; i < 4; i++)
#pragma unroll
                for (int j = 0; j < 4; j++) s_[i][j] += qa[i] * ka[j];
        }

        const float scale = 0.125f;  // 1/sqrt(64)
#pragma unroll
        for (int i = 0; i < 4; i++)
#pragma unroll
            for (int j = 0; j < 4; j++) {
                int kg = k0 + tx * 4 + j;
                s_[i][j] = (kg < Lq) ? s_[i][j] * scale : -1e30f;
            }

#pragma unroll
        for (int i = 0; i < 4; i++) {
            float mx = fmaxf(fmaxf(s_[i][0], s_[i][1]), fmaxf(s_[i][2], s_[i][3]));
#pragma unroll
            for (int off = 8; off >= 1; off >>= 1)
                mx = fmaxf(mx, __shfl_xor_sync(0xffffffffu, mx, off));
            float mnew = fmaxf(m_[i], mx);
            float alpha = __expf(m_[i] - mnew);
            float rs = 0.f;
#pragma unroll
            for (int j = 0; j < 4; j++) {
                s_[i][j] = __expf(s_[i][j] - mnew);
                rs += s_[i][j];
            }
#pragma unroll
            for (int off = 8; off >= 1; off >>= 1)
                rs += __shfl_xor_sync(0xffffffffu, rs, off);
            l_[i] = l_[i] * alpha + rs;
            m_[i] = mnew;
#pragma unroll
            for (int j = 0; j < 4; j++) o_[i][j] *= alpha;
#pragma unroll
            for (int j = 0; j < 4; j++) Ps[ty * 4 + i][tx * 4 + j] = s_[i][j];
        }
        __syncthreads();

#pragma unroll 4
        for (int j = 0; j < 64; j++) {
            float4 vf = *(float4*)&Vs[j][tx * 4];
            float va[4] = {vf.x, vf.y, vf.z, vf.w};
#pragma unroll
            for (int i = 0; i < 4; i++) {
                float p = Ps[ty * 4 + i][j];
#pragma unroll
                for (int c = 0; c < 4; c++) o_[i][c] += p * va[c];
            }
        }
        __syncthreads();
    }

#pragma unroll
    for (int i = 0; i < 4; i++) {
        int l = q0 + ty * 4 + i;
        if (l >= Lq) continue;
        float inv = 1.f / l_[i];
#pragma unroll
        for (int c = 0; c < 4; c++) {
            O[((size_t)b * Lq + l) * Cc + h * Dd + tx * 4 + c] = o_[i][c] * inv;
        }
    }
}

// ---------------------------------------------------------------------------
// LayerNorm over C=1024 per row; 256 threads, float4 per thread.
// ---------------------------------------------------------------------------
__global__ void ln_kernel(const float* __restrict__ in,
                          const float* __restrict__ gamma,
                          const float* __restrict__ beta,
                          float* __restrict__ out) {
    int row = blockIdx.x;
    int tid = threadIdx.x;
    const float* r = in + (size_t)row * Cc;
    float4 v = *(const float4*)&r[tid * 4];
    float s = v.x + v.y + v.z + v.w;
    float s2 = v.x * v.x + v.y * v.y + v.z * v.z + v.w * v.w;
#pragma unroll
    for (int off = 16; off >= 1; off >>= 1) {
        s += __shfl_xor_sync(0xffffffffu, s, off);
        s2 += __shfl_xor_sync(0xffffffffu, s2, off);
    }
    __shared__ float ws[8], ws2[8];
    __shared__ float mean_s, rstd_s;
    int wid = tid >> 5, lane = tid & 31;
    if (lane == 0) {
        ws[wid] = s;
        ws2[wid] = s2;
    }
    __syncthreads();
    if (tid == 0) {
        float S = 0.f, S2 = 0.f;
#pragma unroll
        for (int i = 0; i < 8; i++) {
            S += ws[i];
            S2 += ws2[i];
        }
        float mean = S * (1.f / Cc);
        float var = S2 * (1.f / Cc) - mean * mean;
        mean_s = mean;
        rstd_s = rsqrtf(var + 1e-5f);
    }
    __syncthreads();
    float mean = mean_s, rstd = rstd_s;
    float4 g = *(const float4*)&gamma[tid * 4];
    float4 bt = *(const float4*)&beta[tid * 4];
    float4 o;
    o.x = (v.x - mean) * rstd * g.x + bt.x;
    o.y = (v.y - mean) * rstd * g.y + bt.y;
    o.z = (v.z - mean) * rstd * g.z + bt.z;
    o.w = (v.w - mean) * rstd * g.w + bt.w;
    *(float4*)&out[(size_t)row * Cc + tid * 4] = o;
}

// ---------------------------------------------------------------------------
extern "C" void kernel_launch(void* const* d_in, const int* in_sizes, int n_in,
                              void* d_out, int out_size) {
    const float* x = (const float*)d_in[0];
    const float* rope = (const float*)d_in[1];
    const float* Wqkv = (const float*)d_in[2];
    const float* bqkv = (const float*)d_in[3];
    const float* Wproj = (const float*)d_in[4];
    const float* bproj = (const float*)d_in[5];
    const float* gamma = (const float*)d_in[6];
    const float* beta = (const float*)d_in[7];
    float* out = (float*)d_out;

    float *qkv, *q, *k, *v, *attn, *ln;
    cudaGetSymbolAddress((void**)&qkv, g_qkv);
    cudaGetSymbolAddress((void**)&q, g_q);
    cudaGetSymbolAddress((void**)&k, g_k);
    cudaGetSymbolAddress((void**)&v, g_v);
    cudaGetSymbolAddress((void**)&attn, g_attn);
    cudaGetSymbolAddress((void**)&ln, g_ln);

    const int M = ROWS;  // 8208

    // 1) QKV GEMM (tf32 tensor cores): [8208,1024] @ [1024,3072] + bqkv
    gemm_tf32_kernel<<<dim3(3 * Cc / 128, (M + 127) / 128), 256>>>(
        x, Wqkv, bqkv, qkv, M, 3 * Cc, Cc);

    // 2) RoPE + transpose to [B,H,L,D]
    int total = Bb * Hh * Lq * Dd;
    rope_kernel<<<(total + 255) / 256, 256>>>(qkv, rope, q, k, v);

    // 3) Flash attention -> [B,L,C]
    cudaFuncSetAttribute(flash_kernel, cudaFuncAttributeMaxDynamicSharedMemorySize,
                         FLASH_SMEM);
    flash_kernel<<<dim3((Lq + 63) / 64, Hh, Bb), 256, FLASH_SMEM>>>(q, k, v, attn);

    // 4) LayerNorm
    ln_kernel<<<M, 256>>>(attn, gamma, beta, ln);

    // 5) Projection GEMM (tf32 tensor cores): [8208,1024] @ [1024,1024] + bproj
    gemm_tf32_kernel<<<dim3(Cc / 128, (M + 127) / 128), 256>>>(
        ln, Wproj, bproj, out, M, Cc, Cc);
}

// round 3
// speedup vs baseline: 1.9881x; 1.3429x over previous
#include <cuda_runtime.h>
#include <cuda_bf16.h>

// Problem constants
#define Bb 4
#define Lq 2052
#define Cc 1024
#define Hh 16
#define Dd 64
#define NREG 4
#define ROWS (Bb * Lq)          // 8208
#define ROPE_PLANE ((Lq - NREG) * Dd)  // 2048*64

// -------- scratch (device globals; no allocation allowed) ------------------
__device__ float g_qkv[(size_t)ROWS * 3 * Cc];   // [B*L, 3C]
__device__ float g_q[(size_t)Bb * Hh * Lq * Dd]; // [B,H,L,D]
__device__ float g_k[(size_t)Bb * Hh * Lq * Dd];
__device__ float g_v[(size_t)Bb * Hh * Lq * Dd];
__device__ float g_attn[(size_t)ROWS * Cc];      // [B,L,C]
__device__ float g_ln[(size_t)ROWS * Cc];

// ---------------------------------------------------------------------------
// tf32 helpers (dense GEMMs)
// ---------------------------------------------------------------------------
__device__ __forceinline__ unsigned f2tf32(float f) {
    unsigned u;
    asm("cvt.rna.tf32.f32 %0, %1;" : "=r"(u) : "f"(f));
    return u;
}

__device__ __forceinline__ void mma_tf32(float* c, const unsigned* a,
                                         const unsigned* b) {
    asm volatile(
        "mma.sync.aligned.m16n8k8.row.col.f32.tf32.tf32.f32 "
        "{%0,%1,%2,%3}, {%4,%5,%6,%7}, {%8,%9}, {%0,%1,%2,%3};"
        : "+f"(c[0]), "+f"(c[1]), "+f"(c[2]), "+f"(c[3])
        : "r"(a[0]), "r"(a[1]), "r"(a[2]), "r"(a[3]), "r"(b[0]), "r"(b[1]));
}

// bf16 helpers (flash)
__device__ __forceinline__ void mma_bf16(float* c, const unsigned* a,
                                         const unsigned* b) {
    asm volatile(
        "mma.sync.aligned.m16n8k16.row.col.f32.bf16.bf16.f32 "
        "{%0,%1,%2,%3}, {%4,%5,%6,%7}, {%8,%9}, {%0,%1,%2,%3};"
        : "+f"(c[0]), "+f"(c[1]), "+f"(c[2]), "+f"(c[3])
        : "r"(a[0]), "r"(a[1]), "r"(a[2]), "r"(a[3]), "r"(b[0]), "r"(b[1]));
}

__device__ __forceinline__ unsigned pack_bf16(float x, float y) {
    __nv_bfloat162 t = __floats2bfloat162_rn(x, y);
    return *(unsigned*)&t;
}

// split pair into bf16 hi + bf16 residual, packed
__device__ __forceinline__ void split2(float x, float y, unsigned& hi,
                                       unsigned& lo) {
    __nv_bfloat16 hx = __float2bfloat16_rn(x);
    __nv_bfloat16 hy = __float2bfloat16_rn(y);
    float rx = x - __bfloat162float(hx);
    float ry = y - __bfloat162float(hy);
    __nv_bfloat162 h;
    h.x = hx;
    h.y = hy;
    hi = *(unsigned*)&h;
    lo = pack_bf16(rx, ry);
}

// ---------------------------------------------------------------------------
// tf32 tensor-core GEMM (unchanged from round 2)
// ---------------------------------------------------------------------------
__global__ __launch_bounds__(256) void gemm_tf32_kernel(
    const float* __restrict__ A, const float* __restrict__ Bm,
    const float* __restrict__ bias, float* __restrict__ Cm,
    int M, int N, int K) {
    __shared__ unsigned As[128][36];
    __shared__ unsigned Bs[32][132];

    int tid = threadIdx.x;
    int warp = tid >> 5, lane = tid & 31;
    int g = lane >> 2, t = lane & 3;
    int wm = (warp >> 2) * 64, wn = (warp & 3) * 32;
    int m0 = blockIdx.y * 128, n0 = blockIdx.x * 128;

    float acc[4][4][4];
#pragma unroll
    for (int mt = 0; mt < 4; mt++)
#pragma unroll
        for (int nt = 0; nt < 4; nt++)
#pragma unroll
            for (int r = 0; r < 4; r++) acc[mt][nt][r] = 0.f;

    int arow = tid >> 3, acol = (tid & 7) * 4;
    int brow = tid >> 5, bcol = (tid & 31) * 4;

    for (int k0 = 0; k0 < K; k0 += 32) {
#pragma unroll
        for (int p = 0; p < 4; p++) {
            int r = arow + 32 * p;
            float4 v = make_float4(0.f, 0.f, 0.f, 0.f);
            if (m0 + r < M)
                v = *(const float4*)&A[(size_t)(m0 + r) * K + k0 + acol];
            As[r][acol + 0] = f2tf32(v.x);
            As[r][acol + 1] = f2tf32(v.y);
            As[r][acol + 2] = f2tf32(v.z);
            As[r][acol + 3] = f2tf32(v.w);
        }
#pragma unroll
        for (int p = 0; p < 4; p++) {
            int r = brow + 8 * p;
            float4 v = *(const float4*)&Bm[(size_t)(k0 + r) * N + n0 + bcol];
            Bs[r][bcol + 0] = f2tf32(v.x);
            Bs[r][bcol + 1] = f2tf32(v.y);
            Bs[r][bcol + 2] = f2tf32(v.z);
            Bs[r][bcol + 3] = f2tf32(v.w);
        }
        __syncthreads();

#pragma unroll
        for (int ks = 0; ks < 4; ks++) {
            unsigned af[4][4], bf[4][2];
#pragma unroll
            for (int mt = 0; mt < 4; mt++) {
                int row = wm + mt * 16 + g;
                int kc = ks * 8 + t;
                af[mt][0] = As[row][kc];
                af[mt][1] = As[row + 8][kc];
                af[mt][2] = As[row][kc + 4];
                af[mt][3] = As[row + 8][kc + 4];
            }
#pragma unroll
            for (int nt = 0; nt < 4; nt++) {
                int col = wn + nt * 8 + g;
                bf[nt][0] = Bs[ks * 8 + t][col];
                bf[nt][1] = Bs[ks * 8 + t + 4][col];
            }
#pragma unroll
            for (int mt = 0; mt < 4; mt++)
#pragma unroll
                for (int nt = 0; nt < 4; nt++)
                    mma_tf32(acc[mt][nt], af[mt], bf[nt]);
        }
        __syncthreads();
    }

#pragma unroll
    for (int mt = 0; mt < 4; mt++) {
        int row = m0 + wm + mt * 16 + g;
#pragma unroll
        for (int nt = 0; nt < 4; nt++) {
            int col = n0 + wn + nt * 8 + t * 2;
            float b0 = bias[col], b1 = bias[col + 1];
            if (row < M) {
                *(float2*)&Cm[(size_t)row * N + col] =
                    make_float2(acc[mt][nt][0] + b0, acc[mt][nt][1] + b1);
            }
            if (row + 8 < M) {
                *(float2*)&Cm[(size_t)(row + 8) * N + col] =
                    make_float2(acc[mt][nt][2] + b0, acc[mt][nt][3] + b1);
            }
        }
    }
}

// ---------------------------------------------------------------------------
// RoPE + transpose (unchanged)
// ---------------------------------------------------------------------------
__global__ void rope_kernel(const float* __restrict__ qkv,
                            const float* __restrict__ rope,
                            float* __restrict__ Q, float* __restrict__ K,
                            float* __restrict__ V) {
    int idx = blockIdx.x * blockDim.x + threadIdx.x;
    int total = Bb * Hh * Lq * Dd;
    if (idx >= total) return;
    int d = idx & 63;
    int l = (idx >> 6) % Lq;
    int h = (idx / (Dd * Lq)) % Hh;
    int b = idx / (Dd * Lq * Hh);

    size_t base = ((size_t)b * Lq + l) * (3 * Cc);
    int col = h * Dd + d;
    float q = qkv[base + col];
    float k = qkv[base + Cc + col];
    float v = qkv[base + 2 * Cc + col];
    if (l >= NREG) {
        int dp = d ^ 32;
        float sgn = (d < 32) ? -1.f : 1.f;
        float qp = qkv[base + h * Dd + dp];
        float kp = qkv[base + Cc + h * Dd + dp];
        float cv = rope[(size_t)(l - NREG) * Dd + d];
        float sv = rope[(size_t)ROPE_PLANE + (size_t)(l - NREG) * Dd + d];
        q = q * cv + sgn * qp * sv;
        k = k * cv + sgn * kp * sv;
    }
    size_t oidx = ((size_t)(b * Hh + h) * Lq + l) * Dd + d;
    Q[oidx] = q;
    K[oidx] = k;
    V[oidx] = v;
}

// ---------------------------------------------------------------------------
// Flash attention, bf16x3 tensor-core version.
// Block: 128 q-rows x (full kv stream in tiles of 64). 8 warps, each 16 rows.
// QK^T and PV via mma.m16n8k16.bf16 with hi/lo error compensation.
// S fragments feed PV A-fragments register-only.
// ---------------------------------------------------------------------------
__global__ __launch_bounds__(256) void flash_mma_kernel(
    const float* __restrict__ Q, const float* __restrict__ K,
    const float* __restrict__ V, float* __restrict__ O) {
    // K tile natural [kv][d], V tile transposed [d][kv]; bf16, row stride 72
    __shared__ __nv_bfloat16 Khi[64][72], Klo[64][72];
    __shared__ __nv_bfloat16 Vthi[64][72], Vtlo[64][72];

    int tid = threadIdx.x;
    int warp = tid >> 5, lane = tid & 31;
    int g = lane >> 2, t = lane & 3;
    int q0 = blockIdx.x * 128;
    int h = blockIdx.y, b = blockIdx.z;
    const float* Qb = Q + ((size_t)(b * Hh + h) * Lq) * Dd;
    const float* Kb = K + ((size_t)(b * Hh + h) * Lq) * Dd;
    const float* Vb = V + ((size_t)(b * Hh + h) * Lq) * Dd;

    int r0 = q0 + warp * 16 + g;   // this thread's q rows
    int r1 = r0 + 8;

    // --- Q fragments (pre-scaled by 1/sqrt(D)), hi/lo split, resident ------
    const float scale = 0.125f;
    unsigned qhi[4][4], qlo[4][4];
#pragma unroll
    for (int ks = 0; ks < 4; ks++) {
        int c = ks * 16 + 2 * t;
        float2 v00 = make_float2(0.f, 0.f), v10 = v00, v01 = v00, v11 = v00;
        if (r0 < Lq) {
            v00 = *(const float2*)&Qb[(size_t)r0 * Dd + c];
            v01 = *(const float2*)&Qb[(size_t)r0 * Dd + c + 8];
        }
        if (r1 < Lq) {
            v10 = *(const float2*)&Qb[(size_t)r1 * Dd + c];
            v11 = *(const float2*)&Qb[(size_t)r1 * Dd + c + 8];
        }
        split2(v00.x * scale, v00.y * scale, qhi[ks][0], qlo[ks][0]);
        split2(v10.x * scale, v10.y * scale, qhi[ks][1], qlo[ks][1]);
        split2(v01.x * scale, v01.y * scale, qhi[ks][2], qlo[ks][2]);
        split2(v11.x * scale, v11.y * scale, qhi[ks][3], qlo[ks][3]);
    }

    float m0 = -1e30f, m1 = -1e30f, l0 = 0.f, l1 = 0.f;
    float o[8][4];
#pragma unroll
    for (int nf = 0; nf < 8; nf++)
#pragma unroll
        for (int r = 0; r < 4; r++) o[nf][r] = 0.f;

    const unsigned* KhiW = (const unsigned*)Khi;
    const unsigned* KloW = (const unsigned*)Klo;
    const unsigned* VhiW = (const unsigned*)Vthi;
    const unsigned* VloW = (const unsigned*)Vtlo;

    int nkt = (Lq + 63) / 64;  // 33
    for (int kt = 0; kt < nkt; kt++) {
        int k0 = kt * 64;
        // ---- stage K (natural) and V (transposed) tiles, hi/lo bf16 -------
        for (int it = tid; it < 64 * 16; it += 256) {
            int r = it >> 4, c4 = (it & 15) * 4;
            float4 kv = make_float4(0.f, 0.f, 0.f, 0.f), vv = kv;
            if (k0 + r < Lq) {
                kv = *(const float4*)&Kb[(size_t)(k0 + r) * Dd + c4];
                vv = *(const float4*)&Vb[(size_t)(k0 + r) * Dd + c4];
            }
            unsigned h0, l0w, h1, l1w;
            split2(kv.x, kv.y, h0, l0w);
            split2(kv.z, kv.w, h1, l1w);
            *(uint2*)&Khi[r][c4] = make_uint2(h0, h1);
            *(uint2*)&Klo[r][c4] = make_uint2(l0w, l1w);
            float vf[4] = {vv.x, vv.y, vv.z, vv.w};
#pragma unroll
            for (int j = 0; j < 4; j++) {
                __nv_bfloat16 vh = __float2bfloat16_rn(vf[j]);
                float rem = vf[j] - __bfloat162float(vh);
                Vthi[c4 + j][r] = vh;
                Vtlo[c4 + j][r] = __float2bfloat16_rn(rem);
            }
        }
        __syncthreads();

        // ---- S = Q K^T (bf16x3) -------------------------------------------
        float s[8][4];
#pragma unroll
        for (int nf = 0; nf < 8; nf++)
#pragma unroll
            for (int r = 0; r < 4; r++) s[nf][r] = 0.f;

#pragma unroll
        for (int nf = 0; nf < 8; nf++) {
            int n = nf * 8 + g;
#pragma unroll
            for (int ks = 0; ks < 4; ks++) {
                unsigned bh[2], bl[2];
                int w = n * 36 + ks * 8 + t;
                bh[0] = KhiW[w];
                bh[1] = KhiW[w + 4];
                bl[0] = KloW[w];
                bl[1] = KloW[w + 4];
                mma_bf16(s[nf], qhi[ks], bh);
                mma_bf16(s[nf], qhi[ks], bl);
                mma_bf16(s[nf], qlo[ks], bh);
            }
        }

        // ---- mask + online softmax ----------------------------------------
#pragma unroll
        for (int nf = 0; nf < 8; nf++) {
            int c = k0 + nf * 8 + 2 * t;
            if (c >= Lq) s[nf][0] = s[nf][2] = -1e30f;
            if (c + 1 >= Lq) s[nf][1] = s[nf][3] = -1e30f;
        }
        float mx0 = -1e30f, mx1 = -1e30f;
#pragma unroll
        for (int nf = 0; nf < 8; nf++) {
            mx0 = fmaxf(mx0, fmaxf(s[nf][0], s[nf][1]));
            mx1 = fmaxf(mx1, fmaxf(s[nf][2], s[nf][3]));
        }
        mx0 = fmaxf(mx0, __shfl_xor_sync(0xffffffffu, mx0, 1));
        mx0 = fmaxf(mx0, __shfl_xor_sync(0xffffffffu, mx0, 2));
        mx1 = fmaxf(mx1, __shfl_xor_sync(0xffffffffu, mx1, 1));
        mx1 = fmaxf(mx1, __shfl_xor_sync(0xffffffffu, mx1, 2));
        float mn0 = fmaxf(m0, mx0), mn1 = fmaxf(m1, mx1);
        float a0 = __expf(m0 - mn0), a1 = __expf(m1 - mn1);
        m0 = mn0;
        m1 = mn1;
        float rs0 = 0.f, rs1 = 0.f;
#pragma unroll
        for (int nf = 0; nf < 8; nf++) {
            s[nf][0] = __expf(s[nf][0] - mn0);
            s[nf][1] = __expf(s[nf][1] - mn0);
            s[nf][2] = __expf(s[nf][2] - mn1);
            s[nf][3] = __expf(s[nf][3] - mn1);
            rs0 += s[nf][0] + s[nf][1];
            rs1 += s[nf][2] + s[nf][3];
        }
        rs0 += __shfl_xor_sync(0xffffffffu, rs0, 1);
        rs0 += __shfl_xor_sync(0xffffffffu, rs0, 2);
        rs1 += __shfl_xor_sync(0xffffffffu, rs1, 1);
        rs1 += __shfl_xor_sync(0xffffffffu, rs1, 2);
        l0 = l0 * a0 + rs0;
        l1 = l1 * a1 + rs1;
#pragma unroll
        for (int nf = 0; nf < 8; nf++) {
            o[nf][0] *= a0;
            o[nf][1] *= a0;
            o[nf][2] *= a1;
            o[nf][3] *= a1;
        }

        // ---- O += P V (bf16x3); P fragments directly from S layout --------
#pragma unroll
        for (int ks = 0; ks < 4; ks++) {
            unsigned ph[4], pl[4];
            split2(s[2 * ks][0], s[2 * ks][1], ph[0], pl[0]);
            split2(s[2 * ks][2], s[2 * ks][3], ph[1], pl[1]);
            split2(s[2 * ks + 1][0], s[2 * ks + 1][1], ph[2], pl[2]);
            split2(s[2 * ks + 1][2], s[2 * ks + 1][3], ph[3], pl[3]);
#pragma unroll
            for (int nf = 0; nf < 8; nf++) {
                int d = nf * 8 + g;
                int w = d * 36 + ks * 8 + t;
                unsigned vh[2], vl[2];
                vh[0] = VhiW[w];
                vh[1] = VhiW[w + 4];
                vl[0] = VloW[w];
                vl[1] = VloW[w + 4];
                mma_bf16(o[nf], ph, vh);
                mma_bf16(o[nf], ph, vl);
                mma_bf16(o[nf], pl, vh);
            }
        }
        __syncthreads();
    }

    // ---- store O / l into [B,L,C] layout ----------------------------------
    float inv0 = 1.f / l0, inv1 = 1.f / l1;
#pragma unroll
    for (int nf = 0; nf < 8; nf++) {
        int col = h * Dd + nf * 8 + 2 * t;
        if (r0 < Lq)
            *(float2*)&O[((size_t)b * Lq + r0) * Cc + col] =
                make_float2(o[nf][0] * inv0, o[nf][1] * inv0);
        if (r1 < Lq)
            *(float2*)&O[((size_t)b * Lq + r1) * Cc + col] =
                make_float2(o[nf][2] * inv1, o[nf][3] * inv1);
    }
}

// ---------------------------------------------------------------------------
// LayerNorm (unchanged)
// ---------------------------------------------------------------------------
__global__ void ln_kernel(const float* __restrict__ in,
                          const float* __restrict__ gamma,
                          const float* __restrict__ beta,
                          float* __restrict__ out) {
    int row = blockIdx.x;
    int tid = threadIdx.x;
    const float* r = in + (size_t)row * Cc;
    float4 v = *(const float4*)&r[tid * 4];
    float s = v.x + v.y + v.z + v.w;
    float s2 = v.x * v.x + v.y * v.y + v.z * v.z + v.w * v.w;
#pragma unroll
    for (int off = 16; off >= 1; off >>= 1) {
        s += __shfl_xor_sync(0xffffffffu, s, off);
        s2 += __shfl_xor_sync(0xffffffffu, s2, off);
    }
    __shared__ float ws[8], ws2[8];
    __shared__ float mean_s, rstd_s;
    int wid = tid >> 5, lane = tid & 31;
    if (lane == 0) {
        ws[wid] = s;
        ws2[wid] = s2;
    }
    __syncthreads();
    if (tid == 0) {
        float S = 0.f, S2 = 0.f;
#pragma unroll
        for (int i = 0; i < 8; i++) {
            S += ws[i];
            S2 += ws2[i];
        }
        float mean = S * (1.f / Cc);
        float var = S2 * (1.f / Cc) - mean * mean;
        mean_s = mean;
        rstd_s = rsqrtf(var + 1e-5f);
    }
    __syncthreads();
    float mean = mean_s, rstd = rstd_s;
    float4 g = *(const float4*)&gamma[tid * 4];
    float4 bt = *(const float4*)&beta[tid * 4];
    float4 o;
    o.x = (v.x - mean) * rstd * g.x + bt.x;
    o.y = (v.y - mean) * rstd * g.y + bt.y;
    o.z = (v.z - mean) * rstd * g.z + bt.z;
    o.w = (v.w - mean) * rstd * g.w + bt.w;
    *(float4*)&out[(size_t)row * Cc + tid * 4] = o;
}

// ---------------------------------------------------------------------------
extern "C" void kernel_launch(void* const* d_in, const int* in_sizes, int n_in,
                              void* d_out, int out_size) {
    const float* x = (const float*)d_in[0];
    const float* rope = (const float*)d_in[1];
    const float* Wqkv = (const float*)d_in[2];
    const float* bqkv = (const float*)d_in[3];
    const float* Wproj = (const float*)d_in[4];
    const float* bproj = (const float*)d_in[5];
    const float* gamma = (const float*)d_in[6];
    const float* beta = (const float*)d_in[7];
    float* out = (float*)d_out;

    float *qkv, *q, *k, *v, *attn, *ln;
    cudaGetSymbolAddress((void**)&qkv, g_qkv);
    cudaGetSymbolAddress((void**)&q, g_q);
    cudaGetSymbolAddress((void**)&k, g_k);
    cudaGetSymbolAddress((void**)&v, g_v);
    cudaGetSymbolAddress((void**)&attn, g_attn);
    cudaGetSymbolAddress((void**)&ln, g_ln);

    const int M = ROWS;  // 8208

    // 1) QKV GEMM (tf32): [8208,1024] @ [1024,3072] + bqkv
    gemm_tf32_kernel<<<dim3(3 * Cc / 128, (M + 127) / 128), 256>>>(
        x, Wqkv, bqkv, qkv, M, 3 * Cc, Cc);

    // 2) RoPE + transpose to [B,H,L,D]
    int total = Bb * Hh * Lq * Dd;
    rope_kernel<<<(total + 255) / 256, 256>>>(qkv, rope, q, k, v);

    // 3) Flash attention (bf16x3 tensor cores) -> [B,L,C]
    flash_mma_kernel<<<dim3((Lq + 127) / 128, Hh, Bb), 256>>>(q, k, v, attn);

    // 4) LayerNorm
    ln_kernel<<<M, 256>>>(attn, gamma, beta, ln);

    // 5) Projection GEMM (tf32): [8208,1024] @ [1024,1024] + bproj
    gemm_tf32_kernel<<<dim3(Cc / 128, (M + 127) / 128), 256>>>(
        ln, Wproj, bproj, out, M, Cc, Cc);
}

// round 4
// speedup vs baseline: 3.0592x; 1.5387x over previous
#include <cuda_runtime.h>
#include <cuda_bf16.h>

// Problem constants
#define Bb 4
#define Lq 2052
#define Cc 1024
#define Hh 16
#define Dd 64
#define NREG 4
#define ROWS (Bb * Lq)                  // 8208
#define ROPE_PLANE ((Lq - NREG) * Dd)   // 2048*64
#define LPAD 2064                       // padded L for transposed V rows

// -------- scratch (device globals; no allocation allowed) ------------------
__device__ float g_qkv[(size_t)ROWS * 3 * Cc];       // QKV GEMM output
__device__ float g_q[(size_t)Bb * Hh * Lq * Dd];     // Q fp32 [B,H,L,D]
__device__ __nv_bfloat16 g_khi[(size_t)Bb * Hh * Lq * Dd];
__device__ __nv_bfloat16 g_klo[(size_t)Bb * Hh * Lq * Dd];
__device__ __nv_bfloat16 g_vthi[(size_t)Bb * Hh * Dd * LPAD];  // V^T [B,H,D,Lpad]
__device__ __nv_bfloat16 g_vtlo[(size_t)Bb * Hh * Dd * LPAD];
__device__ float g_attn[(size_t)ROWS * Cc];          // attention out [B,L,C]
__device__ float g_ln[(size_t)ROWS * Cc];            // LN out (tf32-rounded)
__device__ float g_xr[(size_t)ROWS * Cc];            // x rounded to tf32
__device__ float g_wqkvr[(size_t)Cc * 3 * Cc];       // Wqkv rounded
__device__ float g_wprojr[(size_t)Cc * Cc];          // Wproj rounded

// ---------------------------------------------------------------------------
// helpers
// ---------------------------------------------------------------------------
__device__ __forceinline__ unsigned f2tf32(float f) {
    unsigned u;
    asm("cvt.rna.tf32.f32 %0, %1;" : "=r"(u) : "f"(f));
    return u;
}

__device__ __forceinline__ void mma_tf32(float* c, const unsigned* a,
                                         const unsigned* b) {
    asm volatile(
        "mma.sync.aligned.m16n8k8.row.col.f32.tf32.tf32.f32 "
        "{%0,%1,%2,%3}, {%4,%5,%6,%7}, {%8,%9}, {%0,%1,%2,%3};"
        : "+f"(c[0]), "+f"(c[1]), "+f"(c[2]), "+f"(c[3])
        : "r"(a[0]), "r"(a[1]), "r"(a[2]), "r"(a[3]), "r"(b[0]), "r"(b[1]));
}

__device__ __forceinline__ void mma_bf16(float* c, const unsigned* a,
                                         const unsigned* b) {
    asm volatile(
        "mma.sync.aligned.m16n8k16.row.col.f32.bf16.bf16.f32 "
        "{%0,%1,%2,%3}, {%4,%5,%6,%7}, {%8,%9}, {%0,%1,%2,%3};"
        : "+f"(c[0]), "+f"(c[1]), "+f"(c[2]), "+f"(c[3])
        : "r"(a[0]), "r"(a[1]), "r"(a[2]), "r"(a[3]), "r"(b[0]), "r"(b[1]));
}

__device__ __forceinline__ unsigned pack_bf16(float x, float y) {
    __nv_bfloat162 t = __floats2bfloat162_rn(x, y);
    return *(unsigned*)&t;
}

__device__ __forceinline__ void split2(float x, float y, unsigned& hi,
                                       unsigned& lo) {
    __nv_bfloat16 hx = __float2bfloat16_rn(x);
    __nv_bfloat16 hy = __float2bfloat16_rn(y);
    float rx = x - __bfloat162float(hx);
    float ry = y - __bfloat162float(hy);
    __nv_bfloat162 h;
    h.x = hx;
    h.y = hy;
    hi = *(unsigned*)&h;
    lo = pack_bf16(rx, ry);
}

__device__ __forceinline__ unsigned smaddr(const void* p) {
    return (unsigned)__cvta_generic_to_shared(p);
}
__device__ __forceinline__ void cpa16(unsigned dst, const void* src, int sz) {
    asm volatile("cp.async.cg.shared.global [%0], [%1], 16, %2;" ::"r"(dst),
                 "l"(src), "r"(sz));
}
#define CPA_COMMIT asm volatile("cp.async.commit_group;")
#define CPA_WAIT0 asm volatile("cp.async.wait_group 0;" ::: "memory")

// ---------------------------------------------------------------------------
// pre-round fp32 -> tf32 (rna), stored as fp32 container
// ---------------------------------------------------------------------------
__global__ void round_tf32_kernel(const float* __restrict__ src,
                                  float* __restrict__ dst, int n4) {
    int i = blockIdx.x * blockDim.x + threadIdx.x;
    if (i >= n4) return;
    float4 v = ((const float4*)src)[i];
    v.x = __uint_as_float(f2tf32(v.x));
    v.y = __uint_as_float(f2tf32(v.y));
    v.z = __uint_as_float(f2tf32(v.z));
    v.w = __uint_as_float(f2tf32(v.w));
    ((float4*)dst)[i] = v;
}

// ---------------------------------------------------------------------------
// tf32 GEMM, cp.async double-buffered. Inputs pre-rounded to tf32.
// C[M,N] = A[M,K] @ B[K,N] + bias[N]. 128x128 tile, BK=32, 256 threads.
// dyn smem: As[2][128][36] + Bs[2][32][132] floats = 70656 B.
// ---------------------------------------------------------------------------
#define GEMM_SMEM ((2 * 128 * 36 + 2 * 32 * 132) * 4)

__global__ __launch_bounds__(256) void gemm_tf32_db(
    const float* __restrict__ A, const float* __restrict__ Bm,
    const float* __restrict__ bias, float* __restrict__ Cm,
    int M, int N, int K) {
    extern __shared__ float gsm[];
    float(*As)[128][36] = (float(*)[128][36])gsm;
    float(*Bs)[32][132] = (float(*)[32][132])(gsm + 2 * 128 * 36);

    int tid = threadIdx.x;
    int warp = tid >> 5, lane = tid & 31;
    int g = lane >> 2, t = lane & 3;
    int wm = (warp >> 2) * 64, wn = (warp & 3) * 32;
    int m0 = blockIdx.y * 128, n0 = blockIdx.x * 128;

    float acc[4][4][4];
#pragma unroll
    for (int mt = 0; mt < 4; mt++)
#pragma unroll
        for (int nt = 0; nt < 4; nt++)
#pragma unroll
            for (int r = 0; r < 4; r++) acc[mt][nt][r] = 0.f;

    auto stage = [&](int buf, int k0) {
#pragma unroll
        for (int p = 0; p < 4; p++) {
            int it = tid + p * 256;
            int row = it >> 3, c4 = (it & 7) * 4;
            int ar = m0 + row;
            int arc = ar < M ? ar : 0;
            cpa16(smaddr(&As[buf][row][c4]),
                  &A[(size_t)arc * K + k0 + c4], ar < M ? 16 : 0);
        }
#pragma unroll
        for (int p = 0; p < 4; p++) {
            int it = tid + p * 256;
            int row = it >> 5, c4 = (it & 31) * 4;
            cpa16(smaddr(&Bs[buf][row][c4]),
                  &Bm[(size_t)(k0 + row) * N + n0 + c4], 16);
        }
    };

    int nk = K / 32;
    stage(0, 0);
    CPA_COMMIT;

    for (int kt = 0; kt < nk; kt++) {
        CPA_WAIT0;
        __syncthreads();
        if (kt + 1 < nk) {
            stage((kt + 1) & 1, (kt + 1) * 32);
            CPA_COMMIT;
        }
        int buf = kt & 1;
        const unsigned* AsU = (const unsigned*)As[buf];
        const unsigned* BsU = (const unsigned*)Bs[buf];
#pragma unroll
        for (int ks = 0; ks < 4; ks++) {
            unsigned af[4][4], bf[4][2];
#pragma unroll
            for (int mt = 0; mt < 4; mt++) {
                int row = wm + mt * 16 + g;
                int kc = ks * 8 + t;
                af[mt][0] = AsU[row * 36 + kc];
                af[mt][1] = AsU[(row + 8) * 36 + kc];
                af[mt][2] = AsU[row * 36 + kc + 4];
                af[mt][3] = AsU[(row + 8) * 36 + kc + 4];
            }
#pragma unroll
            for (int nt = 0; nt < 4; nt++) {
                int col = wn + nt * 8 + g;
                bf[nt][0] = BsU[(ks * 8 + t) * 132 + col];
                bf[nt][1] = BsU[(ks * 8 + t + 4) * 132 + col];
            }
#pragma unroll
            for (int mt = 0; mt < 4; mt++)
#pragma unroll
                for (int nt = 0; nt < 4; nt++)
                    mma_tf32(acc[mt][nt], af[mt], bf[nt]);
        }
    }

#pragma unroll
    for (int mt = 0; mt < 4; mt++) {
        int row = m0 + wm + mt * 16 + g;
#pragma unroll
        for (int nt = 0; nt < 4; nt++) {
            int col = n0 + wn + nt * 8 + t * 2;
            float b0 = bias[col], b1 = bias[col + 1];
            if (row < M) {
                *(float2*)&Cm[(size_t)row * N + col] =
                    make_float2(acc[mt][nt][0] + b0, acc[mt][nt][1] + b1);
            }
            if (row + 8 < M) {
                *(float2*)&Cm[(size_t)(row + 8) * N + col] =
                    make_float2(acc[mt][nt][2] + b0, acc[mt][nt][3] + b1);
            }
        }
    }
}

// ---------------------------------------------------------------------------
// RoPE + split + transpose: qkv -> Q fp32 [B,H,L,D]; K hi/lo bf16 [B,H,L,D];
// V^T hi/lo bf16 [B,H,D,LPAD] (zero-padded beyond Lq).
// Block per (ltile64, h, b); 256 threads.
// ---------------------------------------------------------------------------
__global__ __launch_bounds__(256) void rope_split_kernel(
    const float* __restrict__ qkv, const float* __restrict__ rope,
    float* __restrict__ Q, __nv_bfloat16* __restrict__ KHI,
    __nv_bfloat16* __restrict__ KLO, __nv_bfloat16* __restrict__ VTH,
    __nv_bfloat16* __restrict__ VTL) {
    __shared__ __nv_bfloat16 vh[64][72], vl[64][72];  // [d][l_local]
    int lt0 = blockIdx.x * 64, h = blockIdx.y, b = blockIdx.z;
    int tid = threadIdx.x;
    size_t bh = (size_t)(b * Hh + h);

    for (int it = tid; it < 64 * 16; it += 256) {
        int ll = it >> 4, d4 = (it & 15) * 4;
        int l = lt0 + ll;
        if (l < Lq) {
            size_t base = ((size_t)b * Lq + l) * (3 * Cc) + h * Dd;
            float4 qv = *(const float4*)&qkv[base + d4];
            float4 kv = *(const float4*)&qkv[base + Cc + d4];
            float4 vv = *(const float4*)&qkv[base + 2 * Cc + d4];
            if (l >= NREG) {
                int dp = d4 ^ 32;
                float4 qp = *(const float4*)&qkv[base + dp];
                float4 kp = *(const float4*)&qkv[base + Cc + dp];
                float4 cs = *(const float4*)&rope[(size_t)(l - NREG) * Dd + d4];
                float4 sn = *(const float4*)&rope[(size_t)ROPE_PLANE +
                                                  (size_t)(l - NREG) * Dd + d4];
                float sgn = (d4 < 32) ? -1.f : 1.f;
                qv.x = qv.x * cs.x + sgn * qp.x * sn.x;
                qv.y = qv.y * cs.y + sgn * qp.y * sn.y;
                qv.z = qv.z * cs.z + sgn * qp.z * sn.z;
                qv.w = qv.w * cs.w + sgn * qp.w * sn.w;
                kv.x = kv.x * cs.x + sgn * kp.x * sn.x;
                kv.y = kv.y * cs.y + sgn * kp.y * sn.y;
                kv.z = kv.z * cs.z + sgn * kp.z * sn.z;
                kv.w = kv.w * cs.w + sgn * kp.w * sn.w;
            }
            size_t oidx = (bh * Lq + l) * Dd + d4;
            *(float4*)&Q[oidx] = qv;
            unsigned h0, l0w, h1, l1w;
            split2(kv.x, kv.y, h0, l0w);
            split2(kv.z, kv.w, h1, l1w);
            *(uint2*)&KHI[oidx] = make_uint2(h0, h1);
            *(uint2*)&KLO[oidx] = make_uint2(l0w, l1w);
            float vf[4] = {vv.x, vv.y, vv.z, vv.w};
#pragma unroll
            for (int j = 0; j < 4; j++) {
                __nv_bfloat16 vhi = __float2bfloat16_rn(vf[j]);
                float rem = vf[j] - __bfloat162float(vhi);
                vh[d4 + j][ll] = vhi;
                vl[d4 + j][ll] = __float2bfloat16_rn(rem);
            }
        } else {
            __nv_bfloat16 z = __float2bfloat16_rn(0.f);
#pragma unroll
            for (int j = 0; j < 4; j++) {
                vh[d4 + j][ll] = z;
                vl[d4 + j][ll] = z;
            }
        }
    }
    __syncthreads();
    for (int it = tid; it < 64 * 8; it += 256) {
        int d = it >> 3, c8 = (it & 7) * 8;
        int l = lt0 + c8;
        if (l < LPAD) {
            *(uint4*)&VTH[(bh * Dd + d) * LPAD + l] = *(uint4*)&vh[d][c8];
            *(uint4*)&VTL[(bh * Dd + d) * LPAD + l] = *(uint4*)&vl[d][c8];
        }
    }
}

// ---------------------------------------------------------------------------
// Flash attention, bf16x3, cp.async double-buffered pre-split operands.
// dyn smem: 2 buffers x 4 arrays x [64][72] bf16 = 73728 B.
// ---------------------------------------------------------------------------
#define FARR (64 * 72)              // bf16 elements per array
#define FBUF (4 * FARR)             // per buffer
#define FLASH_SMEM (2 * FBUF * 2)   // bytes

__global__ __launch_bounds__(256) void flash_mma_db(
    const float* __restrict__ Q, const __nv_bfloat16* __restrict__ KHI,
    const __nv_bfloat16* __restrict__ KLO,
    const __nv_bfloat16* __restrict__ VTH,
    const __nv_bfloat16* __restrict__ VTL, float* __restrict__ O) {
    extern __shared__ __nv_bfloat16 fsm[];

    int tid = threadIdx.x;
    int warp = tid >> 5, lane = tid & 31;
    int g = lane >> 2, t = lane & 3;
    int q0 = blockIdx.x * 128;
    int h = blockIdx.y, b = blockIdx.z;
    size_t bh = (size_t)(b * Hh + h);
    const float* Qb = Q + bh * Lq * Dd;
    const __nv_bfloat16* KHIb = KHI + bh * Lq * Dd;
    const __nv_bfloat16* KLOb = KLO + bh * Lq * Dd;
    const __nv_bfloat16* VTHb = VTH + bh * Dd * LPAD;
    const __nv_bfloat16* VTLb = VTL + bh * Dd * LPAD;

    int r0 = q0 + warp * 16 + g;
    int r1 = r0 + 8;

    // Q fragments (pre-scaled), hi/lo split, resident
    const float scale = 0.125f;
    unsigned qhi[4][4], qlo[4][4];
#pragma unroll
    for (int ks = 0; ks < 4; ks++) {
        int c = ks * 16 + 2 * t;
        float2 v00 = make_float2(0.f, 0.f), v10 = v00, v01 = v00, v11 = v00;
        if (r0 < Lq) {
            v00 = *(const float2*)&Qb[(size_t)r0 * Dd + c];
            v01 = *(const float2*)&Qb[(size_t)r0 * Dd + c + 8];
        }
        if (r1 < Lq) {
            v10 = *(const float2*)&Qb[(size_t)r1 * Dd + c];
            v11 = *(const float2*)&Qb[(size_t)r1 * Dd + c + 8];
        }
        split2(v00.x * scale, v00.y * scale, qhi[ks][0], qlo[ks][0]);
        split2(v10.x * scale, v10.y * scale, qhi[ks][1], qlo[ks][1]);
        split2(v01.x * scale, v01.y * scale, qhi[ks][2], qlo[ks][2]);
        split2(v11.x * scale, v11.y * scale, qhi[ks][3], qlo[ks][3]);
    }

    float m0 = -1e30f, m1 = -1e30f, l0 = 0.f, l1 = 0.f;
    float o[8][4];
#pragma unroll
    for (int nf = 0; nf < 8; nf++)
#pragma unroll
        for (int r = 0; r < 4; r++) o[nf][r] = 0.f;

    auto stage = [&](int buf, int kt) {
        int k0 = kt * 64;
        __nv_bfloat16* B = fsm + buf * FBUF;
#pragma unroll
        for (int p = 0; p < 8; p++) {
            int it = tid + p * 256;          // 0..2047
            int arr = it >> 9;               // 0:khi 1:klo 2:vhi 3:vlo
            int idx = it & 511;
            int row = idx >> 3, c8 = (idx & 7) * 8;
            __nv_bfloat16* dst = B + arr * FARR + row * 72 + c8;
            if (arr < 2) {
                int kr = k0 + row;
                int krc = kr < Lq ? kr : 0;
                const __nv_bfloat16* src =
                    (arr == 0 ? KHIb : KLOb) + (size_t)krc * Dd + c8;
                cpa16(smaddr(dst), src, kr < Lq ? 16 : 0);
            } else {
                int col = k0 + c8;
                int colc = col < LPAD ? col : 0;
                const __nv_bfloat16* src =
                    (arr == 2 ? VTHb : VTLb) + (size_t)row * LPAD + colc;
                cpa16(smaddr(dst), src, col < LPAD ? 16 : 0);
            }
        }
    };

    int nkt = (Lq + 63) / 64;  // 33
    stage(0, 0);
    CPA_COMMIT;

    for (int kt = 0; kt < nkt; kt++) {
        CPA_WAIT0;
        __syncthreads();
        if (kt + 1 < nkt) {
            stage((kt + 1) & 1, kt + 1);
            CPA_COMMIT;
        }
        int k0 = kt * 64;
        const __nv_bfloat16* B = fsm + (kt & 1) * FBUF;
        const unsigned* KhiW = (const unsigned*)(B);
        const unsigned* KloW = (const unsigned*)(B + FARR);
        const unsigned* VhiW = (const unsigned*)(B + 2 * FARR);
        const unsigned* VloW = (const unsigned*)(B + 3 * FARR);

        // S = Q K^T (bf16x3)
        float s[8][4];
#pragma unroll
        for (int nf = 0; nf < 8; nf++)
#pragma unroll
            for (int r = 0; r < 4; r++) s[nf][r] = 0.f;

#pragma unroll
        for (int nf = 0; nf < 8; nf++) {
            int n = nf * 8 + g;
#pragma unroll
            for (int ks = 0; ks < 4; ks++) {
                unsigned bhf[2], blf[2];
                int w = n * 36 + ks * 8 + t;
                bhf[0] = KhiW[w];
                bhf[1] = KhiW[w + 4];
                blf[0] = KloW[w];
                blf[1] = KloW[w + 4];
                mma_bf16(s[nf], qhi[ks], bhf);
                mma_bf16(s[nf], qhi[ks], blf);
                mma_bf16(s[nf], qlo[ks], bhf);
            }
        }

        // mask + online softmax
#pragma unroll
        for (int nf = 0; nf < 8; nf++) {
            int c = k0 + nf * 8 + 2 * t;
            if (c >= Lq) s[nf][0] = s[nf][2] = -1e30f;
            if (c + 1 >= Lq) s[nf][1] = s[nf][3] = -1e30f;
        }
        float mx0 = -1e30f, mx1 = -1e30f;
#pragma unroll
        for (int nf = 0; nf < 8; nf++) {
            mx0 = fmaxf(mx0, fmaxf(s[nf][0], s[nf][1]));
            mx1 = fmaxf(mx1, fmaxf(s[nf][2], s[nf][3]));
        }
        mx0 = fmaxf(mx0, __shfl_xor_sync(0xffffffffu, mx0, 1));
        mx0 = fmaxf(mx0, __shfl_xor_sync(0xffffffffu, mx0, 2));
        mx1 = fmaxf(mx1, __shfl_xor_sync(0xffffffffu, mx1, 1));
        mx1 = fmaxf(mx1, __shfl_xor_sync(0xffffffffu, mx1, 2));
        float mn0 = fmaxf(m0, mx0), mn1 = fmaxf(m1, mx1);
        float a0 = __expf(m0 - mn0), a1 = __expf(m1 - mn1);
        m0 = mn0;
        m1 = mn1;
        float rs0 = 0.f, rs1 = 0.f;
#pragma unroll
        for (int nf = 0; nf < 8; nf++) {
            s[nf][0] = __expf(s[nf][0] - mn0);
            s[nf][1] = __expf(s[nf][1] - mn0);
            s[nf][2] = __expf(s[nf][2] - mn1);
            s[nf][3] = __expf(s[nf][3] - mn1);
            rs0 += s[nf][0] + s[nf][1];
            rs1 += s[nf][2] + s[nf][3];
        }
        rs0 += __shfl_xor_sync(0xffffffffu, rs0, 1);
        rs0 += __shfl_xor_sync(0xffffffffu, rs0, 2);
        rs1 += __shfl_xor_sync(0xffffffffu, rs1, 1);
        rs1 += __shfl_xor_sync(0xffffffffu, rs1, 2);
        l0 = l0 * a0 + rs0;
        l1 = l1 * a1 + rs1;
#pragma unroll
        for (int nf = 0; nf < 8; nf++) {
            o[nf][0] *= a0;
            o[nf][1] *= a0;
            o[nf][2] *= a1;
            o[nf][3] *= a1;
        }

        // O += P V (bf16x3)
#pragma unroll
        for (int ks = 0; ks < 4; ks++) {
            unsigned ph[4], pl[4];
            split2(s[2 * ks][0], s[2 * ks][1], ph[0], pl[0]);
            split2(s[2 * ks][2], s[2 * ks][3], ph[1], pl[1]);
            split2(s[2 * ks + 1][0], s[2 * ks + 1][1], ph[2], pl[2]);
            split2(s[2 * ks + 1][2], s[2 * ks + 1][3], ph[3], pl[3]);
#pragma unroll
            for (int nf = 0; nf < 8; nf++) {
                int d = nf * 8 + g;
                int w = d * 36 + ks * 8 + t;
                unsigned vhf[2], vlf[2];
                vhf[0] = VhiW[w];
                vhf[1] = VhiW[w + 4];
                vlf[0] = VloW[w];
                vlf[1] = VloW[w + 4];
                mma_bf16(o[nf], ph, vhf);
                mma_bf16(o[nf], ph, vlf);
                mma_bf16(o[nf], pl, vhf);
            }
        }
    }

    float inv0 = 1.f / l0, inv1 = 1.f / l1;
#pragma unroll
    for (int nf = 0; nf < 8; nf++) {
        int col = h * Dd + nf * 8 + 2 * t;
        if (r0 < Lq)
            *(float2*)&O[((size_t)b * Lq + r0) * Cc + col] =
                make_float2(o[nf][0] * inv0, o[nf][1] * inv0);
        if (r1 < Lq)
            *(float2*)&O[((size_t)b * Lq + r1) * Cc + col] =
                make_float2(o[nf][2] * inv1, o[nf][3] * inv1);
    }
}

// ---------------------------------------------------------------------------
// LayerNorm; output rounded to tf32 (feeds proj GEMM only).
// ---------------------------------------------------------------------------
__global__ void ln_kernel(const float* __restrict__ in,
                          const float* __restrict__ gamma,
                          const float* __restrict__ beta,
                          float* __restrict__ out) {
    int row = blockIdx.x;
    int tid = threadIdx.x;
    const float* r = in + (size_t)row * Cc;
    float4 v = *(const float4*)&r[tid * 4];
    float s = v.x + v.y + v.z + v.w;
    float s2 = v.x * v.x + v.y * v.y + v.z * v.z + v.w * v.w;
#pragma unroll
    for (int off = 16; off >= 1; off >>= 1) {
        s += __shfl_xor_sync(0xffffffffu, s, off);
        s2 += __shfl_xor_sync(0xffffffffu, s2, off);
    }
    __shared__ float ws[8], ws2[8];
    __shared__ float mean_s, rstd_s;
    int wid = tid >> 5, lane = tid & 31;
    if (lane == 0) {
        ws[wid] = s;
        ws2[wid] = s2;
    }
    __syncthreads();
    if (tid == 0) {
        float S = 0.f, S2 = 0.f;
#pragma unroll
        for (int i = 0; i < 8; i++) {
            S += ws[i];
            S2 += ws2[i];
        }
        float mean = S * (1.f / Cc);
        float var = S2 * (1.f / Cc) - mean * mean;
        mean_s = mean;
        rstd_s = rsqrtf(var + 1e-5f);
    }
    __syncthreads();
    float mean = mean_s, rstd = rstd_s;
    float4 g = *(const float4*)&gamma[tid * 4];
    float4 bt = *(const float4*)&beta[tid * 4];
    float4 o;
    o.x = __uint_as_float(f2tf32((v.x - mean) * rstd * g.x + bt.x));
    o.y = __uint_as_float(f2tf32((v.y - mean) * rstd * g.y + bt.y));
    o.z = __uint_as_float(f2tf32((v.z - mean) * rstd * g.z + bt.z));
    o.w = __uint_as_float(f2tf32((v.w - mean) * rstd * g.w + bt.w));
    *(float4*)&out[(size_t)row * Cc + tid * 4] = o;
}

// ---------------------------------------------------------------------------
extern "C" void kernel_launch(void* const* d_in, const int* in_sizes, int n_in,
                              void* d_out, int out_size) {
    const float* x = (const float*)d_in[0];
    const float* rope = (const float*)d_in[1];
    const float* Wqkv = (const float*)d_in[2];
    const float* bqkv = (const float*)d_in[3];
    const float* Wproj = (const float*)d_in[4];
    const float* bproj = (const float*)d_in[5];
    const float* gamma = (const float*)d_in[6];
    const float* beta = (const float*)d_in[7];
    float* out = (float*)d_out;

    float *qkv, *q, *attn, *ln, *xr, *wqkvr, *wprojr;
    __nv_bfloat16 *khi, *klo, *vthi, *vtlo;
    cudaGetSymbolAddress((void**)&qkv, g_qkv);
    cudaGetSymbolAddress((void**)&q, g_q);
    cudaGetSymbolAddress((void**)&khi, g_khi);
    cudaGetSymbolAddress((void**)&klo, g_klo);
    cudaGetSymbolAddress((void**)&vthi, g_vthi);
    cudaGetSymbolAddress((void**)&vtlo, g_vtlo);
    cudaGetSymbolAddress((void**)&attn, g_attn);
    cudaGetSymbolAddress((void**)&ln, g_ln);
    cudaGetSymbolAddress((void**)&xr, g_xr);
    cudaGetSymbolAddress((void**)&wqkvr, g_wqkvr);
    cudaGetSymbolAddress((void**)&wprojr, g_wprojr);

    const int M = ROWS;  // 8208

    // 0) pre-round operands to tf32
    int nx4 = ROWS * Cc / 4, nw4 = Cc * 3 * Cc / 4, np4 = Cc * Cc / 4;
    round_tf32_kernel<<<(nx4 + 255) / 256, 256>>>(x, xr, nx4);
    round_tf32_kernel<<<(nw4 + 255) / 256, 256>>>(Wqkv, wqkvr, nw4);
    round_tf32_kernel<<<(np4 + 255) / 256, 256>>>(Wproj, wprojr, np4);

    // 1) QKV GEMM
    cudaFuncSetAttribute(gemm_tf32_db, cudaFuncAttributeMaxDynamicSharedMemorySize,
                         GEMM_SMEM);
    gemm_tf32_db<<<dim3(3 * Cc / 128, (M + 127) / 128), 256, GEMM_SMEM>>>(
        xr, wqkvr, bqkv, qkv, M, 3 * Cc, Cc);

    // 2) RoPE + split + transpose
    rope_split_kernel<<<dim3((Lq + 63) / 64, Hh, Bb), 256>>>(
        qkv, rope, q, khi, klo, vthi, vtlo);

    // 3) Flash attention
    cudaFuncSetAttribute(flash_mma_db, cudaFuncAttributeMaxDynamicSharedMemorySize,
                         FLASH_SMEM);
    flash_mma_db<<<dim3((Lq + 127) / 128, Hh, Bb), 256, FLASH_SMEM>>>(
        q, khi, klo, vthi, vtlo, attn);

    // 4) LayerNorm (emits tf32-rounded)
    ln_kernel<<<M, 256>>>(attn, gamma, beta, ln);

    // 5) Projection GEMM
    gemm_tf32_db<<<dim3(Cc / 128, (M + 127) / 128), 256, GEMM_SMEM>>>(
        ln, wprojr, bproj, out, M, Cc, Cc);
}

// round 7
// speedup vs baseline: 3.0684x; 1.0030x over previous
#include <cuda_runtime.h>
#include <cuda_bf16.h>

// Problem constants
#define Bb 4
#define Lq 2052
#define Cc 1024
#define Hh 16
#define Dd 64
#define NREG 4
#define ROWS (Bb * Lq)                  // 8208
#define ROPE_PLANE ((Lq - NREG) * Dd)   // 2048*64
#define LPAD 2064                       // padded L for transposed V rows

// -------- scratch (device globals; no allocation allowed) ------------------
__device__ float g_qkv[(size_t)ROWS * 3 * Cc];       // QKV GEMM output
__device__ float g_q[(size_t)Bb * Hh * Lq * Dd];     // Q fp32 [B,H,L,D]
__device__ __nv_bfloat16 g_khi[(size_t)Bb * Hh * Lq * Dd];
__device__ __nv_bfloat16 g_klo[(size_t)Bb * Hh * Lq * Dd];
__device__ __nv_bfloat16 g_vthi[(size_t)Bb * Hh * Dd * LPAD];  // V^T [B,H,D,Lpad]
__device__ __nv_bfloat16 g_vtlo[(size_t)Bb * Hh * Dd * LPAD];
__device__ float g_attn[(size_t)ROWS * Cc];          // attention out [B,L,C]
__device__ float g_ln[(size_t)ROWS * Cc];            // LN out (tf32-rounded)
__device__ float g_xr[(size_t)ROWS * Cc];            // x rounded to tf32
__device__ float g_wqkvr[(size_t)Cc * 3 * Cc];       // Wqkv rounded
__device__ float g_wprojr[(size_t)Cc * Cc];          // Wproj rounded

// ---------------------------------------------------------------------------
// helpers
// ---------------------------------------------------------------------------
__device__ __forceinline__ unsigned f2tf32(float f) {
    unsigned u;
    asm("cvt.rna.tf32.f32 %0, %1;" : "=r"(u) : "f"(f));
    return u;
}

__device__ __forceinline__ void mma_tf32(float* c, const unsigned* a,
                                         const unsigned* b) {
    asm volatile(
        "mma.sync.aligned.m16n8k8.row.col.f32.tf32.tf32.f32 "
        "{%0,%1,%2,%3}, {%4,%5,%6,%7}, {%8,%9}, {%0,%1,%2,%3};"
        : "+f"(c[0]), "+f"(c[1]), "+f"(c[2]), "+f"(c[3])
        : "r"(a[0]), "r"(a[1]), "r"(a[2]), "r"(a[3]), "r"(b[0]), "r"(b[1]));
}

__device__ __forceinline__ void mma_bf16(float* c, const unsigned* a,
                                         const unsigned* b) {
    asm volatile(
        "mma.sync.aligned.m16n8k16.row.col.f32.bf16.bf16.f32 "
        "{%0,%1,%2,%3}, {%4,%5,%6,%7}, {%8,%9}, {%0,%1,%2,%3};"
        : "+f"(c[0]), "+f"(c[1]), "+f"(c[2]), "+f"(c[3])
        : "r"(a[0]), "r"(a[1]), "r"(a[2]), "r"(a[3]), "r"(b[0]), "r"(b[1]));
}

__device__ __forceinline__ void ldsm_x4(unsigned& r0, unsigned& r1,
                                        unsigned& r2, unsigned& r3,
                                        unsigned addr) {
    asm volatile(
        "ldmatrix.sync.aligned.m8n8.x4.shared.b16 {%0,%1,%2,%3}, [%4];"
        : "=r"(r0), "=r"(r1), "=r"(r2), "=r"(r3)
        : "r"(addr));
}

__device__ __forceinline__ unsigned pack_bf16(float x, float y) {
    __nv_bfloat162 t = __floats2bfloat162_rn(x, y);
    return *(unsigned*)&t;
}

__device__ __forceinline__ void split2(float x, float y, unsigned& hi,
                                       unsigned& lo) {
    __nv_bfloat16 hx = __float2bfloat16_rn(x);
    __nv_bfloat16 hy = __float2bfloat16_rn(y);
    float rx = x - __bfloat162float(hx);
    float ry = y - __bfloat162float(hy);
    __nv_bfloat162 h;
    h.x = hx;
    h.y = hy;
    hi = *(unsigned*)&h;
    lo = pack_bf16(rx, ry);
}

__device__ __forceinline__ unsigned smaddr(const void* p) {
    return (unsigned)__cvta_generic_to_shared(p);
}
__device__ __forceinline__ void cpa16(unsigned dst, const void* src, int sz) {
    asm volatile("cp.async.cg.shared.global [%0], [%1], 16, %2;" ::"r"(dst),
                 "l"(src), "r"(sz));
}
#define CPA_COMMIT asm volatile("cp.async.commit_group;")
#define CPA_WAIT0 asm volatile("cp.async.wait_group 0;" ::: "memory")

// ---------------------------------------------------------------------------
// pre-round fp32 -> tf32 (rna)
// ---------------------------------------------------------------------------
__global__ void round_tf32_kernel(const float* __restrict__ src,
                                  float* __restrict__ dst, int n4) {
    int i = blockIdx.x * blockDim.x + threadIdx.x;
    if (i >= n4) return;
    float4 v = ((const float4*)src)[i];
    v.x = __uint_as_float(f2tf32(v.x));
    v.y = __uint_as_float(f2tf32(v.y));
    v.z = __uint_as_float(f2tf32(v.z));
    v.w = __uint_as_float(f2tf32(v.w));
    ((float4*)dst)[i] = v;
}

// ---------------------------------------------------------------------------
// tf32 GEMM, cp.async double-buffered (unchanged from round 4)
// ---------------------------------------------------------------------------
#define GEMM_SMEM ((2 * 128 * 36 + 2 * 32 * 132) * 4)

__global__ __launch_bounds__(256) void gemm_tf32_db(
    const float* __restrict__ A, const float* __restrict__ Bm,
    const float* __restrict__ bias, float* __restrict__ Cm,
    int M, int N, int K) {
    extern __shared__ float gsm[];
    float(*As)[128][36] = (float(*)[128][36])gsm;
    float(*Bs)[32][132] = (float(*)[32][132])(gsm + 2 * 128 * 36);

    int tid = threadIdx.x;
    int warp = tid >> 5, lane = tid & 31;
    int g = lane >> 2, t = lane & 3;
    int wm = (warp >> 2) * 64, wn = (warp & 3) * 32;
    int m0 = blockIdx.y * 128, n0 = blockIdx.x * 128;

    float acc[4][4][4];
#pragma unroll
    for (int mt = 0; mt < 4; mt++)
#pragma unroll
        for (int nt = 0; nt < 4; nt++)
#pragma unroll
            for (int r = 0; r < 4; r++) acc[mt][nt][r] = 0.f;

    auto stage = [&](int buf, int k0) {
#pragma unroll
        for (int p = 0; p < 4; p++) {
            int it = tid + p * 256;
            int row = it >> 3, c4 = (it & 7) * 4;
            int ar = m0 + row;
            int arc = ar < M ? ar : 0;
            cpa16(smaddr(&As[buf][row][c4]),
                  &A[(size_t)arc * K + k0 + c4], ar < M ? 16 : 0);
        }
#pragma unroll
        for (int p = 0; p < 4; p++) {
            int it = tid + p * 256;
            int row = it >> 5, c4 = (it & 31) * 4;
            cpa16(smaddr(&Bs[buf][row][c4]),
                  &Bm[(size_t)(k0 + row) * N + n0 + c4], 16);
        }
    };

    int nk = K / 32;
    stage(0, 0);
    CPA_COMMIT;

    for (int kt = 0; kt < nk; kt++) {
        CPA_WAIT0;
        __syncthreads();
        if (kt + 1 < nk) {
            stage((kt + 1) & 1, (kt + 1) * 32);
            CPA_COMMIT;
        }
        int buf = kt & 1;
        const unsigned* AsU = (const unsigned*)As[buf];
        const unsigned* BsU = (const unsigned*)Bs[buf];
#pragma unroll
        for (int ks = 0; ks < 4; ks++) {
            unsigned af[4][4], bf[4][2];
#pragma unroll
            for (int mt = 0; mt < 4; mt++) {
                int row = wm + mt * 16 + g;
                int kc = ks * 8 + t;
                af[mt][0] = AsU[row * 36 + kc];
                af[mt][1] = AsU[(row + 8) * 36 + kc];
                af[mt][2] = AsU[row * 36 + kc + 4];
                af[mt][3] = AsU[(row + 8) * 36 + kc + 4];
            }
#pragma unroll
            for (int nt = 0; nt < 4; nt++) {
                int col = wn + nt * 8 + g;
                bf[nt][0] = BsU[(ks * 8 + t) * 132 + col];
                bf[nt][1] = BsU[(ks * 8 + t + 4) * 132 + col];
            }
#pragma unroll
            for (int mt = 0; mt < 4; mt++)
#pragma unroll
                for (int nt = 0; nt < 4; nt++)
                    mma_tf32(acc[mt][nt], af[mt], bf[nt]);
        }
    }

#pragma unroll
    for (int mt = 0; mt < 4; mt++) {
        int row = m0 + wm + mt * 16 + g;
#pragma unroll
        for (int nt = 0; nt < 4; nt++) {
            int col = n0 + wn + nt * 8 + t * 2;
            float b0 = bias[col], b1 = bias[col + 1];
            if (row < M) {
                *(float2*)&Cm[(size_t)row * N + col] =
                    make_float2(acc[mt][nt][0] + b0, acc[mt][nt][1] + b1);
            }
            if (row + 8 < M) {
                *(float2*)&Cm[(size_t)(row + 8) * N + col] =
                    make_float2(acc[mt][nt][2] + b0, acc[mt][nt][3] + b1);
            }
        }
    }
}

// ---------------------------------------------------------------------------
// RoPE + split + transpose (unchanged)
// ---------------------------------------------------------------------------
__global__ __launch_bounds__(256) void rope_split_kernel(
    const float* __restrict__ qkv, const float* __restrict__ rope,
    float* __restrict__ Q, __nv_bfloat16* __restrict__ KHI,
    __nv_bfloat16* __restrict__ KLO, __nv_bfloat16* __restrict__ VTH,
    __nv_bfloat16* __restrict__ VTL) {
    __shared__ __nv_bfloat16 vh[64][72], vl[64][72];  // [d][l_local]
    int lt0 = blockIdx.x * 64, h = blockIdx.y, b = blockIdx.z;
    int tid = threadIdx.x;
    size_t bh = (size_t)(b * Hh + h);

    for (int it = tid; it < 64 * 16; it += 256) {
        int ll = it >> 4, d4 = (it & 15) * 4;
        int l = lt0 + ll;
        if (l < Lq) {
            size_t base = ((size_t)b * Lq + l) * (3 * Cc) + h * Dd;
            float4 qv = *(const float4*)&qkv[base + d4];
            float4 kv = *(const float4*)&qkv[base + Cc + d4];
            float4 vv = *(const float4*)&qkv[base + 2 * Cc + d4];
            if (l >= NREG) {
                int dp = d4 ^ 32;
                float4 qp = *(const float4*)&qkv[base + dp];
                float4 kp = *(const float4*)&qkv[base + Cc + dp];
                float4 cs = *(const float4*)&rope[(size_t)(l - NREG) * Dd + d4];
                float4 sn = *(const float4*)&rope[(size_t)ROPE_PLANE +
                                                  (size_t)(l - NREG) * Dd + d4];
                float sgn = (d4 < 32) ? -1.f : 1.f;
                qv.x = qv.x * cs.x + sgn * qp.x * sn.x;
                qv.y = qv.y * cs.y + sgn * qp.y * sn.y;
                qv.z = qv.z * cs.z + sgn * qp.z * sn.z;
                qv.w = qv.w * cs.w + sgn * qp.w * sn.w;
                kv.x = kv.x * cs.x + sgn * kp.x * sn.x;
                kv.y = kv.y * cs.y + sgn * kp.y * sn.y;
                kv.z = kv.z * cs.z + sgn * kp.z * sn.z;
                kv.w = kv.w * cs.w + sgn * kp.w * sn.w;
            }
            size_t oidx = (bh * Lq + l) * Dd + d4;
            *(float4*)&Q[oidx] = qv;
            unsigned h0, l0w, h1, l1w;
            split2(kv.x, kv.y, h0, l0w);
            split2(kv.z, kv.w, h1, l1w);
            *(uint2*)&KHI[oidx] = make_uint2(h0, h1);
            *(uint2*)&KLO[oidx] = make_uint2(l0w, l1w);
            float vf[4] = {vv.x, vv.y, vv.z, vv.w};
#pragma unroll
            for (int j = 0; j < 4; j++) {
                __nv_bfloat16 vhi = __float2bfloat16_rn(vf[j]);
                float rem = vf[j] - __bfloat162float(vhi);
                vh[d4 + j][ll] = vhi;
                vl[d4 + j][ll] = __float2bfloat16_rn(rem);
            }
        } else {
            __nv_bfloat16 z = __float2bfloat16_rn(0.f);
#pragma unroll
            for (int j = 0; j < 4; j++) {
                vh[d4 + j][ll] = z;
                vl[d4 + j][ll] = z;
            }
        }
    }
    __syncthreads();
    for (int it = tid; it < 64 * 8; it += 256) {
        int d = it >> 3, c8 = (it & 7) * 8;
        int l = lt0 + c8;
        if (l < LPAD) {
            *(uint4*)&VTH[(bh * Dd + d) * LPAD + l] = *(uint4*)&vh[d][c8];
            *(uint4*)&VTL[(bh * Dd + d) * LPAD + l] = *(uint4*)&vl[d][c8];
        }
    }
}

// ---------------------------------------------------------------------------
// Flash attention, bf16x3, cp.async double-buffered + ldmatrix fragments.
// ---------------------------------------------------------------------------
#define FARR (64 * 72)              // bf16 elements per array
#define FBUF (4 * FARR)             // per buffer
#define FLASH_SMEM (2 * FBUF * 2)   // bytes

__global__ __launch_bounds__(256) void flash_mma_db(
    const float* __restrict__ Q, const __nv_bfloat16* __restrict__ KHI,
    const __nv_bfloat16* __restrict__ KLO,
    const __nv_bfloat16* __restrict__ VTH,
    const __nv_bfloat16* __restrict__ VTL, float* __restrict__ O) {
    extern __shared__ __nv_bfloat16 fsm[];

    int tid = threadIdx.x;
    int warp = tid >> 5, lane = tid & 31;
    int g = lane >> 2, t = lane & 3;
    int q0 = blockIdx.x * 128;
    int h = blockIdx.y, b = blockIdx.z;
    size_t bh = (size_t)(b * Hh + h);
    const float* Qb = Q + bh * Lq * Dd;
    const __nv_bfloat16* KHIb = KHI + bh * Lq * Dd;
    const __nv_bfloat16* KLOb = KLO + bh * Lq * Dd;
    const __nv_bfloat16* VTHb = VTH + bh * Dd * LPAD;
    const __nv_bfloat16* VTLb = VTL + bh * Dd * LPAD;

    int r0 = q0 + warp * 16 + g;
    int r1 = r0 + 8;

    // ldmatrix per-lane address pattern: matrix mi = lane>>3, row rr = lane&7.
    // quad covers nf = 2q + (mi>>1), k-half = mi&1.
    int mi = lane >> 3, rr = lane & 7;
    unsigned ldsm_off = (((mi >> 1) * 8 + rr) * 72 + (mi & 1) * 8) * 2;  // bytes

    // Q fragments (pre-scaled), hi/lo split, resident
    const float scale = 0.125f;
    unsigned qhi[4][4], qlo[4][4];
#pragma unroll
    for (int ks = 0; ks < 4; ks++) {
        int c = ks * 16 + 2 * t;
        float2 v00 = make_float2(0.f, 0.f), v10 = v00, v01 = v00, v11 = v00;
        if (r0 < Lq) {
            v00 = *(const float2*)&Qb[(size_t)r0 * Dd + c];
            v01 = *(const float2*)&Qb[(size_t)r0 * Dd + c + 8];
        }
        if (r1 < Lq) {
            v10 = *(const float2*)&Qb[(size_t)r1 * Dd + c];
            v11 = *(const float2*)&Qb[(size_t)r1 * Dd + c + 8];
        }
        split2(v00.x * scale, v00.y * scale, qhi[ks][0], qlo[ks][0]);
        split2(v10.x * scale, v10.y * scale, qhi[ks][1], qlo[ks][1]);
        split2(v01.x * scale, v01.y * scale, qhi[ks][2], qlo[ks][2]);
        split2(v11.x * scale, v11.y * scale, qhi[ks][3], qlo[ks][3]);
    }

    float m0 = -1e30f, m1 = -1e30f, l0 = 0.f, l1 = 0.f;
    float o[8][4];
#pragma unroll
    for (int nf = 0; nf < 8; nf++)
#pragma unroll
        for (int r = 0; r < 4; r++) o[nf][r] = 0.f;

    auto stage = [&](int buf, int kt) {
        int k0 = kt * 64;
        __nv_bfloat16* B = fsm + buf * FBUF;
#pragma unroll
        for (int p = 0; p < 8; p++) {
            int it = tid + p * 256;          // 0..2047
            int arr = it >> 9;               // 0:khi 1:klo 2:vhi 3:vlo
            int idx = it & 511;
            int row = idx >> 3, c8 = (idx & 7) * 8;
            __nv_bfloat16* dst = B + arr * FARR + row * 72 + c8;
            if (arr < 2) {
                int kr = k0 + row;
                int krc = kr < Lq ? kr : 0;
                const __nv_bfloat16* src =
                    (arr == 0 ? KHIb : KLOb) + (size_t)krc * Dd + c8;
                cpa16(smaddr(dst), src, kr < Lq ? 16 : 0);
            } else {
                int col = k0 + c8;
                int colc = col < LPAD ? col : 0;
                const __nv_bfloat16* src =
                    (arr == 2 ? VTHb : VTLb) + (size_t)row * LPAD + colc;
                cpa16(smaddr(dst), src, col < LPAD ? 16 : 0);
            }
        }
    };

    int nkt = (Lq + 63) / 64;  // 33
    stage(0, 0);
    CPA_COMMIT;

    for (int kt = 0; kt < nkt; kt++) {
        CPA_WAIT0;
        __syncthreads();
        if (kt + 1 < nkt) {
            stage((kt + 1) & 1, kt + 1);
            CPA_COMMIT;
        }
        int k0 = kt * 64;
        unsigned khiB = smaddr(fsm + (kt & 1) * FBUF) + ldsm_off;
        unsigned kloB = khiB + FARR * 2;
        unsigned vhiB = khiB + 2 * FARR * 2;
        unsigned vloB = khiB + 3 * FARR * 2;

        // S = Q K^T (bf16x3), B-fragments via ldmatrix
        float s[8][4];
#pragma unroll
        for (int nf = 0; nf < 8; nf++)
#pragma unroll
            for (int r = 0; r < 4; r++) s[nf][r] = 0.f;

#pragma unroll
        for (int ks = 0; ks < 4; ks++) {
#pragma unroll
            for (int q = 0; q < 4; q++) {
                unsigned off = (q * 16 * 72 + ks * 16) * 2;
                unsigned bh0[2], bh1[2], bl0[2], bl1[2];
                ldsm_x4(bh0[0], bh0[1], bh1[0], bh1[1], khiB + off);
                ldsm_x4(bl0[0], bl0[1], bl1[0], bl1[1], kloB + off);
                mma_bf16(s[2 * q], qhi[ks], bh0);
                mma_bf16(s[2 * q], qhi[ks], bl0);
                mma_bf16(s[2 * q], qlo[ks], bh0);
                mma_bf16(s[2 * q + 1], qhi[ks], bh1);
                mma_bf16(s[2 * q + 1], qhi[ks], bl1);
                mma_bf16(s[2 * q + 1], qlo[ks], bh1);
            }
        }

        // mask + online softmax
#pragma unroll
        for (int nf = 0; nf < 8; nf++) {
            int c = k0 + nf * 8 + 2 * t;
            if (c >= Lq) s[nf][0] = s[nf][2] = -1e30f;
            if (c + 1 >= Lq) s[nf][1] = s[nf][3] = -1e30f;
        }
        float mx0 = -1e30f, mx1 = -1e30f;
#pragma unroll
        for (int nf = 0; nf < 8; nf++) {
            mx0 = fmaxf(mx0, fmaxf(s[nf][0], s[nf][1]));
            mx1 = fmaxf(mx1, fmaxf(s[nf][2], s[nf][3]));
        }
        mx0 = fmaxf(mx0, __shfl_xor_sync(0xffffffffu, mx0, 1));
        mx0 = fmaxf(mx0, __shfl_xor_sync(0xffffffffu, mx0, 2));
        mx1 = fmaxf(mx1, __shfl_xor_sync(0xffffffffu, mx1, 1));
        mx1 = fmaxf(mx1, __shfl_xor_sync(0xffffffffu, mx1, 2));
        float mn0 = fmaxf(m0, mx0), mn1 = fmaxf(m1, mx1);
        float a0 = __expf(m0 - mn0), a1 = __expf(m1 - mn1);
        m0 = mn0;
        m1 = mn1;
        float rs0 = 0.f, rs1 = 0.f;
#pragma unroll
        for (int nf = 0; nf < 8; nf++) {
            s[nf][0] = __expf(s[nf][0] - mn0);
            s[nf][1] = __expf(s[nf][1] - mn0);
            s[nf][2] = __expf(s[nf][2] - mn1);
            s[nf][3] = __expf(s[nf][3] - mn1);
            rs0 += s[nf][0] + s[nf][1];
            rs1 += s[nf][2] + s[nf][3];
        }
        rs0 += __shfl_xor_sync(0xffffffffu, rs0, 1);
        rs0 += __shfl_xor_sync(0xffffffffu, rs0, 2);
        rs1 += __shfl_xor_sync(0xffffffffu, rs1, 1);
        rs1 += __shfl_xor_sync(0xffffffffu, rs1, 2);
        l0 = l0 * a0 + rs0;
        l1 = l1 * a1 + rs1;
#pragma unroll
        for (int nf = 0; nf < 8; nf++) {
            o[nf][0] *= a0;
            o[nf][1] *= a0;
            o[nf][2] *= a1;
            o[nf][3] *= a1;
        }

        // O += P V (bf16x3), V-fragments via ldmatrix
#pragma unroll
        for (int ks = 0; ks < 4; ks++) {
            unsigned ph[4], pl[4];
            split2(s[2 * ks][0], s[2 * ks][1], ph[0], pl[0]);
            split2(s[2 * ks][2], s[2 * ks][3], ph[1], pl[1]);
            split2(s[2 * ks + 1][0], s[2 * ks + 1][1], ph[2], pl[2]);
            split2(s[2 * ks + 1][2], s[2 * ks + 1][3], ph[3], pl[3]);
#pragma unroll
            for (int q = 0; q < 4; q++) {
                unsigned off = (q * 16 * 72 + ks * 16) * 2;
                unsigned vh0[2], vh1[2], vl0[2], vl1[2];
                ldsm_x4(vh0[0], vh0[1], vh1[0], vh1[1], vhiB + off);
                ldsm_x4(vl0[0], vl0[1], vl1[0], vl1[1], vloB + off);
                mma_bf16(o[2 * q], ph, vh0);
                mma_bf16(o[2 * q], ph, vl0);
                mma_bf16(o[2 * q], pl, vh0);
                mma_bf16(o[2 * q + 1], ph, vh1);
                mma_bf16(o[2 * q + 1], ph, vl1);
                mma_bf16(o[2 * q + 1], pl, vh1);
            }
        }
    }

    float inv0 = 1.f / l0, inv1 = 1.f / l1;
#pragma unroll
    for (int nf = 0; nf < 8; nf++) {
        int col = h * Dd + nf * 8 + 2 * t;
        if (r0 < Lq)
            *(float2*)&O[((size_t)b * Lq + r0) * Cc + col] =
                make_float2(o[nf][0] * inv0, o[nf][1] * inv0);
        if (r1 < Lq)
            *(float2*)&O[((size_t)b * Lq + r1) * Cc + col] =
                make_float2(o[nf][2] * inv1, o[nf][3] * inv1);
    }
}

// ---------------------------------------------------------------------------
// LayerNorm; output rounded to tf32 (unchanged)
// ---------------------------------------------------------------------------
__global__ void ln_kernel(const float* __restrict__ in,
                          const float* __restrict__ gamma,
                          const float* __restrict__ beta,
                          float* __restrict__ out) {
    int row = blockIdx.x;
    int tid = threadIdx.x;
    const float* r = in + (size_t)row * Cc;
    float4 v = *(const float4*)&r[tid * 4];
    float s = v.x + v.y + v.z + v.w;
    float s2 = v.x * v.x + v.y * v.y + v.z * v.z + v.w * v.w;
#pragma unroll
    for (int off = 16; off >= 1; off >>= 1) {
        s += __shfl_xor_sync(0xffffffffu, s, off);
        s2 += __shfl_xor_sync(0xffffffffu, s2, off);
    }
    __shared__ float ws[8], ws2[8];
    __shared__ float mean_s, rstd_s;
    int wid = tid >> 5, lane = tid & 31;
    if (lane == 0) {
        ws[wid] = s;
        ws2[wid] = s2;
    }
    __syncthreads();
    if (tid == 0) {
        float S = 0.f, S2 = 0.f;
#pragma unroll
        for (int i = 0; i < 8; i++) {
            S += ws[i];
            S2 += ws2[i];
        }
        float mean = S * (1.f / Cc);
        float var = S2 * (1.f / Cc) - mean * mean;
        mean_s = mean;
        rstd_s = rsqrtf(var + 1e-5f);
    }
    __syncthreads();
    float mean = mean_s, rstd = rstd_s;
    float4 g = *(const float4*)&gamma[tid * 4];
    float4 bt = *(const float4*)&beta[tid * 4];
    float4 o;
    o.x = __uint_as_float(f2tf32((v.x - mean) * rstd * g.x + bt.x));
    o.y = __uint_as_float(f2tf32((v.y - mean) * rstd * g.y + bt.y));
    o.z = __uint_as_float(f2tf32((v.z - mean) * rstd * g.z + bt.z));
    o.w = __uint_as_float(f2tf32((v.w - mean) * rstd * g.w + bt.w));
    *(float4*)&out[(size_t)row * Cc + tid * 4] = o;
}

// ---------------------------------------------------------------------------
extern "C" void kernel_launch(void* const* d_in, const int* in_sizes, int n_in,
                              void* d_out, int out_size) {
    const float* x = (const float*)d_in[0];
    const float* rope = (const float*)d_in[1];
    const float* Wqkv = (const float*)d_in[2];
    const float* bqkv = (const float*)d_in[3];
    const float* Wproj = (const float*)d_in[4];
    const float* bproj = (const float*)d_in[5];
    const float* gamma = (const float*)d_in[6];
    const float* beta = (const float*)d_in[7];
    float* out = (float*)d_out;

    float *qkv, *q, *attn, *ln, *xr, *wqkvr, *wprojr;
    __nv_bfloat16 *khi, *klo, *vthi, *vtlo;
    cudaGetSymbolAddress((void**)&qkv, g_qkv);
    cudaGetSymbolAddress((void**)&q, g_q);
    cudaGetSymbolAddress((void**)&khi, g_khi);
    cudaGetSymbolAddress((void**)&klo, g_klo);
    cudaGetSymbolAddress((void**)&vthi, g_vthi);
    cudaGetSymbolAddress((void**)&vtlo, g_vtlo);
    cudaGetSymbolAddress((void**)&attn, g_attn);
    cudaGetSymbolAddress((void**)&ln, g_ln);
    cudaGetSymbolAddress((void**)&xr, g_xr);
    cudaGetSymbolAddress((void**)&wqkvr, g_wqkvr);
    cudaGetSymbolAddress((void**)&wprojr, g_wprojr);

    const int M = ROWS;  // 8208

    // 0) pre-round operands to tf32
    int nx4 = ROWS * Cc / 4, nw4 = Cc * 3 * Cc / 4, np4 = Cc * Cc / 4;
    round_tf32_kernel<<<(nx4 + 255) / 256, 256>>>(x, xr, nx4);
    round_tf32_kernel<<<(nw4 + 255) / 256, 256>>>(Wqkv, wqkvr, nw4);
    round_tf32_kernel<<<(np4 + 255) / 256, 256>>>(Wproj, wprojr, np4);

    // 1) QKV GEMM
    cudaFuncSetAttribute(gemm_tf32_db, cudaFuncAttributeMaxDynamicSharedMemorySize,
                         GEMM_SMEM);
    gemm_tf32_db<<<dim3(3 * Cc / 128, (M + 127) / 128), 256, GEMM_SMEM>>>(
        xr, wqkvr, bqkv, qkv, M, 3 * Cc, Cc);

    // 2) RoPE + split + transpose
    rope_split_kernel<<<dim3((Lq + 63) / 64, Hh, Bb), 256>>>(
        qkv, rope, q, khi, klo, vthi, vtlo);

    // 3) Flash attention
    cudaFuncSetAttribute(flash_mma_db, cudaFuncAttributeMaxDynamicSharedMemorySize,
                         FLASH_SMEM);
    flash_mma_db<<<dim3((Lq + 127) / 128, Hh, Bb), 256, FLASH_SMEM>>>(
        q, khi, klo, vthi, vtlo, attn);

    // 4) LayerNorm (emits tf32-rounded)
    ln_kernel<<<M, 256>>>(attn, gamma, beta, ln);

    // 5) Projection GEMM
    gemm_tf32_db<<<dim3(Cc / 128, (M + 127) / 128), 256, GEMM_SMEM>>>(
        ln, wprojr, bproj, out, M, Cc, Cc);
}

// round 9
// speedup vs baseline: 3.2497x; 1.0591x over previous
#include <cuda_runtime.h>
#include <cuda_bf16.h>
#include <cstdint>

// Problem constants
#define Bb 4
#define Lq 2052
#define Cc 1024
#define Hh 16
#define Dd 64
#define NREG 4
#define ROWS (Bb * Lq)                  // 8208
#define ROPE_PLANE ((Lq - NREG) * Dd)   // 2048*64
#define LPAD 2064                       // padded L for transposed V rows

// -------- scratch (device globals; no allocation allowed) ------------------
__device__ float g_qkv[(size_t)ROWS * 3 * Cc];       // QKV GEMM output
__device__ float g_q[(size_t)Bb * Hh * Lq * Dd];     // Q fp32 [B,H,L,D]
__device__ __nv_bfloat16 g_khi[(size_t)Bb * Hh * Lq * Dd];
__device__ __nv_bfloat16 g_klo[(size_t)Bb * Hh * Lq * Dd];
__device__ __nv_bfloat16 g_vthi[(size_t)Bb * Hh * Dd * LPAD];  // V^T [B,H,D,Lpad]
__device__ __nv_bfloat16 g_vtlo[(size_t)Bb * Hh * Dd * LPAD];
__device__ float g_attn[(size_t)ROWS * Cc];          // attention out [B,L,C]
__device__ float g_ln[(size_t)ROWS * Cc];            // LN out (tf32-rounded)
__device__ float g_xr[(size_t)ROWS * Cc];            // x rounded to tf32
__device__ float g_wqkvT[(size_t)3 * Cc * Cc];       // Wqkv^T [3C][C] tf32
__device__ float g_wprojT[(size_t)Cc * Cc];          // Wproj^T [C][C] tf32

// ---------------------------------------------------------------------------
// helpers
// ---------------------------------------------------------------------------
__device__ __forceinline__ unsigned f2tf32(float f) {
    unsigned u;
    asm("cvt.rna.tf32.f32 %0, %1;" : "=r"(u) : "f"(f));
    return u;
}

__device__ __forceinline__ void mma_tf32(float* c, const unsigned* a,
                                         const unsigned* b) {
    asm volatile(
        "mma.sync.aligned.m16n8k8.row.col.f32.tf32.tf32.f32 "
        "{%0,%1,%2,%3}, {%4,%5,%6,%7}, {%8,%9}, {%0,%1,%2,%3};"
        : "+f"(c[0]), "+f"(c[1]), "+f"(c[2]), "+f"(c[3])
        : "r"(a[0]), "r"(a[1]), "r"(a[2]), "r"(a[3]), "r"(b[0]), "r"(b[1]));
}

__device__ __forceinline__ void mma_bf16(float* c, const unsigned* a,
                                         const unsigned* b) {
    asm volatile(
        "mma.sync.aligned.m16n8k16.row.col.f32.bf16.bf16.f32 "
        "{%0,%1,%2,%3}, {%4,%5,%6,%7}, {%8,%9}, {%0,%1,%2,%3};"
        : "+f"(c[0]), "+f"(c[1]), "+f"(c[2]), "+f"(c[3])
        : "r"(a[0]), "r"(a[1]), "r"(a[2]), "r"(a[3]), "r"(b[0]), "r"(b[1]));
}

__device__ __forceinline__ void ldsm_x4(unsigned& r0, unsigned& r1,
                                        unsigned& r2, unsigned& r3,
                                        unsigned addr) {
    asm volatile(
        "ldmatrix.sync.aligned.m8n8.x4.shared.b16 {%0,%1,%2,%3}, [%4];"
        : "=r"(r0), "=r"(r1), "=r"(r2), "=r"(r3)
        : "r"(addr));
}

__device__ __forceinline__ unsigned pack_bf16(float x, float y) {
    __nv_bfloat162 t = __floats2bfloat162_rn(x, y);
    return *(unsigned*)&t;
}

__device__ __forceinline__ void split2(float x, float y, unsigned& hi,
                                       unsigned& lo) {
    __nv_bfloat16 hx = __float2bfloat16_rn(x);
    __nv_bfloat16 hy = __float2bfloat16_rn(y);
    float rx = x - __bfloat162float(hx);
    float ry = y - __bfloat162float(hy);
    __nv_bfloat162 h;
    h.x = hx;
    h.y = hy;
    hi = *(unsigned*)&h;
    lo = pack_bf16(rx, ry);
}

__device__ __forceinline__ unsigned smaddr(const void* p) {
    return (unsigned)__cvta_generic_to_shared(p);
}
__device__ __forceinline__ void cpa16(unsigned dst, const void* src, int sz) {
    asm volatile("cp.async.cg.shared.global [%0], [%1], 16, %2;" ::"r"(dst),
                 "l"(src), "r"(sz));
}
#define CPA_COMMIT asm volatile("cp.async.commit_group;")
#define CPA_WAIT0 asm volatile("cp.async.wait_group 0;" ::: "memory")

// ---------------------------------------------------------------------------
// prep: round x to tf32; transpose+round W -> WT [N][K]
// ---------------------------------------------------------------------------
__global__ void round_tf32_kernel(const float* __restrict__ src,
                                  float* __restrict__ dst, int n4) {
    int i = blockIdx.x * blockDim.x + threadIdx.x;
    if (i >= n4) return;
    float4 v = ((const float4*)src)[i];
    v.x = __uint_as_float(f2tf32(v.x));
    v.y = __uint_as_float(f2tf32(v.y));
    v.z = __uint_as_float(f2tf32(v.z));
    v.w = __uint_as_float(f2tf32(v.w));
    ((float4*)dst)[i] = v;
}

__global__ void transpose_round_kernel(const float* __restrict__ W,
                                       float* __restrict__ WT, int K, int N) {
    __shared__ float tile[32][33];
    int k0 = blockIdx.y * 32, n0 = blockIdx.x * 32;
    int tx = threadIdx.x, ty = threadIdx.y;
#pragma unroll
    for (int j = 0; j < 4; j++)
        tile[ty + j * 8][tx] = W[(size_t)(k0 + ty + j * 8) * N + n0 + tx];
    __syncthreads();
#pragma unroll
    for (int j = 0; j < 4; j++)
        WT[(size_t)(n0 + ty + j * 8) * K + k0 + tx] =
            __uint_as_float(f2tf32(tile[tx][ty + j * 8]));
}

// ---------------------------------------------------------------------------
// tf32 GEMM, cp.async double-buffered, both operands k-major + ldmatrix.
// C[M,N] = A[M,K] @ BT[N,K]^T + bias. Tile 128x128, BK=32, 256 threads.
// smem: As[2][128][36] + Bs[2][128][36] floats = 73728 B.
// ---------------------------------------------------------------------------
#define GEMM_SMEM (4 * 128 * 36 * 4)

__global__ __launch_bounds__(256) void gemm_tf32_db(
    const float* __restrict__ A, const float* __restrict__ BT,
    const float* __restrict__ bias, float* __restrict__ Cm,
    int M, int N, int K) {
    extern __shared__ float gsm[];
    float(*As)[128][36] = (float(*)[128][36])gsm;
    float(*Bs)[128][36] = (float(*)[128][36])(gsm + 2 * 128 * 36);

    int tid = threadIdx.x;
    int warp = tid >> 5, lane = tid & 31;
    int g = lane >> 2, t = lane & 3;
    int wm = (warp >> 2) * 64, wn = (warp & 3) * 32;
    int m0 = blockIdx.y * 128, n0 = blockIdx.x * 128;

    // ldmatrix lane offsets (fp32 8x4 matrices, row stride 36 words):
    int j = lane >> 3, r = lane & 7;
    int aoff = ((j & 1) * 8 + r) * 36 + (j >> 1) * 4;   // A: m-pair, k-half
    int boff = ((j >> 1) * 8 + r) * 36 + (j & 1) * 4;   // B: n-pair, k-half

    float acc[4][4][4];
#pragma unroll
    for (int mt = 0; mt < 4; mt++)
#pragma unroll
        for (int nt = 0; nt < 4; nt++)
#pragma unroll
            for (int q = 0; q < 4; q++) acc[mt][nt][q] = 0.f;

    auto stage = [&](int buf, int k0) {
#pragma unroll
        for (int p = 0; p < 4; p++) {
            int it = tid + p * 256;
            int row = it >> 3, c4 = (it & 7) * 4;
            int ar = m0 + row;
            int arc = ar < M ? ar : 0;
            cpa16(smaddr(&As[buf][row][c4]),
                  &A[(size_t)arc * K + k0 + c4], ar < M ? 16 : 0);
        }
#pragma unroll
        for (int p = 0; p < 4; p++) {
            int it = tid + p * 256;
            int row = it >> 3, c4 = (it & 7) * 4;
            cpa16(smaddr(&Bs[buf][row][c4]),
                  &BT[(size_t)(n0 + row) * K + k0 + c4], 16);
        }
    };

    int nk = K / 32;
    stage(0, 0);
    CPA_COMMIT;

    for (int kt = 0; kt < nk; kt++) {
        CPA_WAIT0;
        __syncthreads();
        if (kt + 1 < nk) {
            stage((kt + 1) & 1, (kt + 1) * 32);
            CPA_COMMIT;
        }
        int buf = kt & 1;
        unsigned Abase = smaddr(&As[buf][0][0]);
        unsigned Bbase = smaddr(&Bs[buf][0][0]);
#pragma unroll
        for (int ks = 0; ks < 4; ks++) {
            unsigned af[4][4], bf[4][2];
#pragma unroll
            for (int mt = 0; mt < 4; mt++) {
                unsigned ad =
                    Abase + ((wm + mt * 16) * 36 + ks * 8 + aoff) * 4;
                ldsm_x4(af[mt][0], af[mt][1], af[mt][2], af[mt][3], ad);
            }
#pragma unroll
            for (int pr = 0; pr < 2; pr++) {
                unsigned bd =
                    Bbase + ((wn + pr * 16) * 36 + ks * 8 + boff) * 4;
                ldsm_x4(bf[2 * pr][0], bf[2 * pr][1], bf[2 * pr + 1][0],
                        bf[2 * pr + 1][1], bd);
            }
#pragma unroll
            for (int mt = 0; mt < 4; mt++)
#pragma unroll
                for (int nt = 0; nt < 4; nt++)
                    mma_tf32(acc[mt][nt], af[mt], bf[nt]);
        }
    }

#pragma unroll
    for (int mt = 0; mt < 4; mt++) {
        int row = m0 + wm + mt * 16 + g;
#pragma unroll
        for (int nt = 0; nt < 4; nt++) {
            int col = n0 + wn + nt * 8 + t * 2;
            float b0 = bias[col], b1 = bias[col + 1];
            if (row < M) {
                *(float2*)&Cm[(size_t)row * N + col] =
                    make_float2(acc[mt][nt][0] + b0, acc[mt][nt][1] + b1);
            }
            if (row + 8 < M) {
                *(float2*)&Cm[(size_t)(row + 8) * N + col] =
                    make_float2(acc[mt][nt][2] + b0, acc[mt][nt][3] + b1);
            }
        }
    }
}

// ---------------------------------------------------------------------------
// RoPE + split + transpose (unchanged from round 7)
// ---------------------------------------------------------------------------
__global__ __launch_bounds__(256) void rope_split_kernel(
    const float* __restrict__ qkv, const float* __restrict__ rope,
    float* __restrict__ Q, __nv_bfloat16* __restrict__ KHI,
    __nv_bfloat16* __restrict__ KLO, __nv_bfloat16* __restrict__ VTH,
    __nv_bfloat16* __restrict__ VTL) {
    __shared__ __nv_bfloat16 vh[64][72], vl[64][72];  // [d][l_local]
    int lt0 = blockIdx.x * 64, h = blockIdx.y, b = blockIdx.z;
    int tid = threadIdx.x;
    size_t bh = (size_t)(b * Hh + h);

    for (int it = tid; it < 64 * 16; it += 256) {
        int ll = it >> 4, d4 = (it & 15) * 4;
        int l = lt0 + ll;
        if (l < Lq) {
            size_t base = ((size_t)b * Lq + l) * (3 * Cc) + h * Dd;
            float4 qv = *(const float4*)&qkv[base + d4];
            float4 kv = *(const float4*)&qkv[base + Cc + d4];
            float4 vv = *(const float4*)&qkv[base + 2 * Cc + d4];
            if (l >= NREG) {
                int dp = d4 ^ 32;
                float4 qp = *(const float4*)&qkv[base + dp];
                float4 kp = *(const float4*)&qkv[base + Cc + dp];
                float4 cs = *(const float4*)&rope[(size_t)(l - NREG) * Dd + d4];
                float4 sn = *(const float4*)&rope[(size_t)ROPE_PLANE +
                                                  (size_t)(l - NREG) * Dd + d4];
                float sgn = (d4 < 32) ? -1.f : 1.f;
                qv.x = qv.x * cs.x + sgn * qp.x * sn.x;
                qv.y = qv.y * cs.y + sgn * qp.y * sn.y;
                qv.z = qv.z * cs.z + sgn * qp.z * sn.z;
                qv.w = qv.w * cs.w + sgn * qp.w * sn.w;
                kv.x = kv.x * cs.x + sgn * kp.x * sn.x;
                kv.y = kv.y * cs.y + sgn * kp.y * sn.y;
                kv.z = kv.z * cs.z + sgn * kp.z * sn.z;
                kv.w = kv.w * cs.w + sgn * kp.w * sn.w;
            }
            size_t oidx = (bh * Lq + l) * Dd + d4;
            *(float4*)&Q[oidx] = qv;
            unsigned h0, l0w, h1, l1w;
            split2(kv.x, kv.y, h0, l0w);
            split2(kv.z, kv.w, h1, l1w);
            *(uint2*)&KHI[oidx] = make_uint2(h0, h1);
            *(uint2*)&KLO[oidx] = make_uint2(l0w, l1w);
            float vf[4] = {vv.x, vv.y, vv.z, vv.w};
#pragma unroll
            for (int jj = 0; jj < 4; jj++) {
                __nv_bfloat16 vhi = __float2bfloat16_rn(vf[jj]);
                float rem = vf[jj] - __bfloat162float(vhi);
                vh[d4 + jj][ll] = vhi;
                vl[d4 + jj][ll] = __float2bfloat16_rn(rem);
            }
        } else {
            __nv_bfloat16 z = __float2bfloat16_rn(0.f);
#pragma unroll
            for (int jj = 0; jj < 4; jj++) {
                vh[d4 + jj][ll] = z;
                vl[d4 + jj][ll] = z;
            }
        }
    }
    __syncthreads();
    for (int it = tid; it < 64 * 8; it += 256) {
        int d = it >> 3, c8 = (it & 7) * 8;
        int l = lt0 + c8;
        if (l < LPAD) {
            *(uint4*)&VTH[(bh * Dd + d) * LPAD + l] = *(uint4*)&vh[d][c8];
            *(uint4*)&VTL[(bh * Dd + d) * LPAD + l] = *(uint4*)&vl[d][c8];
        }
    }
}

// ---------------------------------------------------------------------------
// Flash attention, bf16x3, cp.async double-buffered; Q in smem (hi/lo) and
// re-fetched via ldmatrix each tile -> lower regs, 2 CTAs/SM.
// smem: Qhi/Qlo [128][72] + 2 x 4 arrays [64][72], bf16 = 110592 B.
// ---------------------------------------------------------------------------
#define QARR (128 * 72)
#define FARR (64 * 72)
#define FBUF (4 * FARR)
#define FLASH_SMEM ((2 * QARR + 2 * FBUF) * 2)

__global__ __launch_bounds__(256, 2) void flash_mma_db(
    const float* __restrict__ Q, const __nv_bfloat16* __restrict__ KHI,
    const __nv_bfloat16* __restrict__ KLO,
    const __nv_bfloat16* __restrict__ VTH,
    const __nv_bfloat16* __restrict__ VTL, float* __restrict__ O) {
    extern __shared__ __nv_bfloat16 fsm[];
    __nv_bfloat16* Qh = fsm;
    __nv_bfloat16* Ql = fsm + QARR;
    __nv_bfloat16* KV = fsm + 2 * QARR;

    int tid = threadIdx.x;
    int warp = tid >> 5, lane = tid & 31;
    int g = lane >> 2, t = lane & 3;
    int q0 = blockIdx.x * 128;
    int h = blockIdx.y, b = blockIdx.z;
    size_t bh = (size_t)(b * Hh + h);
    const float* Qb = Q + bh * Lq * Dd;
    const __nv_bfloat16* KHIb = KHI + bh * Lq * Dd;
    const __nv_bfloat16* KLOb = KLO + bh * Lq * Dd;
    const __nv_bfloat16* VTHb = VTH + bh * Dd * LPAD;
    const __nv_bfloat16* VTLb = VTL + bh * Dd * LPAD;

    int r0 = q0 + warp * 16 + g;
    int r1 = r0 + 8;

    // B-side ldmatrix lane offset (K/V), as round 7
    int mi = lane >> 3, rr = lane & 7;
    unsigned ldsm_off = (((mi >> 1) * 8 + rr) * 72 + (mi & 1) * 8) * 2;
    // A-side (Q) ldmatrix lane offset: m-pair (j&1), k-half (j>>1)
    unsigned q_off = (((mi & 1) * 8 + rr) * 72 + (mi >> 1) * 8) * 2;

    // ---- stage Q (scaled, hi/lo split) into smem once ----------------------
    const float scale = 0.125f;
    for (int it = tid; it < 128 * 16; it += 256) {
        int row = it >> 4, c4 = (it & 15) * 4;
        int l = q0 + row;
        float4 v = make_float4(0.f, 0.f, 0.f, 0.f);
        if (l < Lq) v = *(const float4*)&Qb[(size_t)l * Dd + c4];
        unsigned h0, l0w, h1, l1w;
        split2(v.x * scale, v.y * scale, h0, l0w);
        split2(v.z * scale, v.w * scale, h1, l1w);
        *(uint2*)&Qh[row * 72 + c4] = make_uint2(h0, h1);
        *(uint2*)&Ql[row * 72 + c4] = make_uint2(l0w, l1w);
    }

    float m0 = -1e30f, m1 = -1e30f, l0 = 0.f, l1 = 0.f;
    float o[8][4];
#pragma unroll
    for (int nf = 0; nf < 8; nf++)
#pragma unroll
        for (int q = 0; q < 4; q++) o[nf][q] = 0.f;

    auto stage = [&](int buf, int kt) {
        int k0 = kt * 64;
        __nv_bfloat16* B = KV + buf * FBUF;
#pragma unroll
        for (int p = 0; p < 8; p++) {
            int it = tid + p * 256;
            int arr = it >> 9;
            int idx = it & 511;
            int row = idx >> 3, c8 = (idx & 7) * 8;
            __nv_bfloat16* dst = B + arr * FARR + row * 72 + c8;
            if (arr < 2) {
                int kr = k0 + row;
                int krc = kr < Lq ? kr : 0;
                const __nv_bfloat16* src =
                    (arr == 0 ? KHIb : KLOb) + (size_t)krc * Dd + c8;
                cpa16(smaddr(dst), src, kr < Lq ? 16 : 0);
            } else {
                int col = k0 + c8;
                int colc = col < LPAD ? col : 0;
                const __nv_bfloat16* src =
                    (arr == 2 ? VTHb : VTLb) + (size_t)row * LPAD + colc;
                cpa16(smaddr(dst), src, col < LPAD ? 16 : 0);
            }
        }
    };

    int nkt = (Lq + 63) / 64;  // 33
    stage(0, 0);
    CPA_COMMIT;

    unsigned qhB = smaddr(Qh) + warp * 16 * 72 * 2 + q_off;
    unsigned qlB = qhB + QARR * 2;

    for (int kt = 0; kt < nkt; kt++) {
        CPA_WAIT0;
        __syncthreads();
        if (kt + 1 < nkt) {
            stage((kt + 1) & 1, kt + 1);
            CPA_COMMIT;
        }
        int k0 = kt * 64;
        unsigned khiB = smaddr(KV + (kt & 1) * FBUF) + ldsm_off;
        unsigned kloB = khiB + FARR * 2;
        unsigned vhiB = khiB + 2 * FARR * 2;
        unsigned vloB = khiB + 3 * FARR * 2;

        float s[8][4];
#pragma unroll
        for (int nf = 0; nf < 8; nf++)
#pragma unroll
            for (int q = 0; q < 4; q++) s[nf][q] = 0.f;

#pragma unroll
        for (int ks = 0; ks < 4; ks++) {
            unsigned qh4[4], ql4[4];
            ldsm_x4(qh4[0], qh4[1], qh4[2], qh4[3], qhB + ks * 32);
            ldsm_x4(ql4[0], ql4[1], ql4[2], ql4[3], qlB + ks * 32);
#pragma unroll
            for (int q = 0; q < 4; q++) {
                unsigned off = (q * 16 * 72 + ks * 16) * 2;
                unsigned bh0[2], bh1[2], bl0[2], bl1[2];
                ldsm_x4(bh0[0], bh0[1], bh1[0], bh1[1], khiB + off);
                ldsm_x4(bl0[0], bl0[1], bl1[0], bl1[1], kloB + off);
                mma_bf16(s[2 * q], qh4, bh0);
                mma_bf16(s[2 * q], qh4, bl0);
                mma_bf16(s[2 * q], ql4, bh0);
                mma_bf16(s[2 * q + 1], qh4, bh1);
                mma_bf16(s[2 * q + 1], qh4, bl1);
                mma_bf16(s[2 * q + 1], ql4, bh1);
            }
        }

#pragma unroll
        for (int nf = 0; nf < 8; nf++) {
            int c = k0 + nf * 8 + 2 * t;
            if (c >= Lq) s[nf][0] = s[nf][2] = -1e30f;
            if (c + 1 >= Lq) s[nf][1] = s[nf][3] = -1e30f;
        }
        float mx0 = -1e30f, mx1 = -1e30f;
#pragma unroll
        for (int nf = 0; nf < 8; nf++) {
            mx0 = fmaxf(mx0, fmaxf(s[nf][0], s[nf][1]));
            mx1 = fmaxf(mx1, fmaxf(s[nf][2], s[nf][3]));
        }
        mx0 = fmaxf(mx0, __shfl_xor_sync(0xffffffffu, mx0, 1));
        mx0 = fmaxf(mx0, __shfl_xor_sync(0xffffffffu, mx0, 2));
        mx1 = fmaxf(mx1, __shfl_xor_sync(0xffffffffu, mx1, 1));
        mx1 = fmaxf(mx1, __shfl_xor_sync(0xffffffffu, mx1, 2));
        float mn0 = fmaxf(m0, mx0), mn1 = fmaxf(m1, mx1);
        float a0 = __expf(m0 - mn0), a1 = __expf(m1 - mn1);
        m0 = mn0;
        m1 = mn1;
        float rs0 = 0.f, rs1 = 0.f;
#pragma unroll
        for (int nf = 0; nf < 8; nf++) {
            s[nf][0] = __expf(s[nf][0] - mn0);
            s[nf][1] = __expf(s[nf][1] - mn0);
            s[nf][2] = __expf(s[nf][2] - mn1);
            s[nf][3] = __expf(s[nf][3] - mn1);
            rs0 += s[nf][0] + s[nf][1];
            rs1 += s[nf][2] + s[nf][3];
        }
        rs0 += __shfl_xor_sync(0xffffffffu, rs0, 1);
        rs0 += __shfl_xor_sync(0xffffffffu, rs0, 2);
        rs1 += __shfl_xor_sync(0xffffffffu, rs1, 1);
        rs1 += __shfl_xor_sync(0xffffffffu, rs1, 2);
        l0 = l0 * a0 + rs0;
        l1 = l1 * a1 + rs1;
#pragma unroll
        for (int nf = 0; nf < 8; nf++) {
            o[nf][0] *= a0;
            o[nf][1] *= a0;
            o[nf][2] *= a1;
            o[nf][3] *= a1;
        }

#pragma unroll
        for (int ks = 0; ks < 4; ks++) {
            unsigned ph[4], pl[4];
            split2(s[2 * ks][0], s[2 * ks][1], ph[0], pl[0]);
            split2(s[2 * ks][2], s[2 * ks][3], ph[1], pl[1]);
            split2(s[2 * ks + 1][0], s[2 * ks + 1][1], ph[2], pl[2]);
            split2(s[2 * ks + 1][2], s[2 * ks + 1][3], ph[3], pl[3]);
#pragma unroll
            for (int q = 0; q < 4; q++) {
                unsigned off = (q * 16 * 72 + ks * 16) * 2;
                unsigned vh0[2], vh1[2], vl0[2], vl1[2];
                ldsm_x4(vh0[0], vh0[1], vh1[0], vh1[1], vhiB + off);
                ldsm_x4(vl0[0], vl0[1], vl1[0], vl1[1], vloB + off);
                mma_bf16(o[2 * q], ph, vh0);
                mma_bf16(o[2 * q], ph, vl0);
                mma_bf16(o[2 * q], pl, vh0);
                mma_bf16(o[2 * q + 1], ph, vh1);
                mma_bf16(o[2 * q + 1], ph, vl1);
                mma_bf16(o[2 * q + 1], pl, vh1);
            }
        }
    }

    float inv0 = 1.f / l0, inv1 = 1.f / l1;
#pragma unroll
    for (int nf = 0; nf < 8; nf++) {
        int col = h * Dd + nf * 8 + 2 * t;
        if (r0 < Lq)
            *(float2*)&O[((size_t)b * Lq + r0) * Cc + col] =
                make_float2(o[nf][0] * inv0, o[nf][1] * inv0);
        if (r1 < Lq)
            *(float2*)&O[((size_t)b * Lq + r1) * Cc + col] =
                make_float2(o[nf][2] * inv1, o[nf][3] * inv1);
    }
}

// ---------------------------------------------------------------------------
// LayerNorm; output rounded to tf32 (unchanged)
// ---------------------------------------------------------------------------
__global__ void ln_kernel(const float* __restrict__ in,
                          const float* __restrict__ gamma,
                          const float* __restrict__ beta,
                          float* __restrict__ out) {
    int row = blockIdx.x;
    int tid = threadIdx.x;
    const float* r = in + (size_t)row * Cc;
    float4 v = *(const float4*)&r[tid * 4];
    float s = v.x + v.y + v.z + v.w;
    float s2 = v.x * v.x + v.y * v.y + v.z * v.z + v.w * v.w;
#pragma unroll
    for (int off = 16; off >= 1; off >>= 1) {
        s += __shfl_xor_sync(0xffffffffu, s, off);
        s2 += __shfl_xor_sync(0xffffffffu, s2, off);
    }
    __shared__ float ws[8], ws2[8];
    __shared__ float mean_s, rstd_s;
    int wid = tid >> 5, lane = tid & 31;
    if (lane == 0) {
        ws[wid] = s;
        ws2[wid] = s2;
    }
    __syncthreads();
    if (tid == 0) {
        float S = 0.f, S2 = 0.f;
#pragma unroll
        for (int i = 0; i < 8; i++) {
            S += ws[i];
            S2 += ws2[i];
        }
        float mean = S * (1.f / Cc);
        float var = S2 * (1.f / Cc) - mean * mean;
        mean_s = mean;
        rstd_s = rsqrtf(var + 1e-5f);
    }
    __syncthreads();
    float mean = mean_s, rstd = rstd_s;
    float4 g = *(const float4*)&gamma[tid * 4];
    float4 bt = *(const float4*)&beta[tid * 4];
    float4 o;
    o.x = __uint_as_float(f2tf32((v.x - mean) * rstd * g.x + bt.x));
    o.y = __uint_as_float(f2tf32((v.y - mean) * rstd * g.y + bt.y));
    o.z = __uint_as_float(f2tf32((v.z - mean) * rstd * g.z + bt.z));
    o.w = __uint_as_float(f2tf32((v.w - mean) * rstd * g.w + bt.w));
    *(float4*)&out[(size_t)row * Cc + tid * 4] = o;
}

// ---------------------------------------------------------------------------
extern "C" void kernel_launch(void* const* d_in, const int* in_sizes, int n_in,
                              void* d_out, int out_size) {
    const float* x = (const float*)d_in[0];
    const float* rope = (const float*)d_in[1];
    const float* Wqkv = (const float*)d_in[2];
    const float* bqkv = (const float*)d_in[3];
    const float* Wproj = (const float*)d_in[4];
    const float* bproj = (const float*)d_in[5];
    const float* gamma = (const float*)d_in[6];
    const float* beta = (const float*)d_in[7];
    float* out = (float*)d_out;

    float *qkv, *q, *attn, *ln, *xr, *wqkvT, *wprojT;
    __nv_bfloat16 *khi, *klo, *vthi, *vtlo;
    cudaGetSymbolAddress((void**)&qkv, g_qkv);
    cudaGetSymbolAddress((void**)&q, g_q);
    cudaGetSymbolAddress((void**)&khi, g_khi);
    cudaGetSymbolAddress((void**)&klo, g_klo);
    cudaGetSymbolAddress((void**)&vthi, g_vthi);
    cudaGetSymbolAddress((void**)&vtlo, g_vtlo);
    cudaGetSymbolAddress((void**)&attn, g_attn);
    cudaGetSymbolAddress((void**)&ln, g_ln);
    cudaGetSymbolAddress((void**)&xr, g_xr);
    cudaGetSymbolAddress((void**)&wqkvT, g_wqkvT);
    cudaGetSymbolAddress((void**)&wprojT, g_wprojT);

    const int M = ROWS;  // 8208

    // 0) pre-round x; transpose+round weights to [N][K]
    int nx4 = ROWS * Cc / 4;
    round_tf32_kernel<<<(nx4 + 255) / 256, 256>>>(x, xr, nx4);
    transpose_round_kernel<<<dim3(3 * Cc / 32, Cc / 32), dim3(32, 8)>>>(
        Wqkv, wqkvT, Cc, 3 * Cc);
    transpose_round_kernel<<<dim3(Cc / 32, Cc / 32), dim3(32, 8)>>>(
        Wproj, wprojT, Cc, Cc);

    // 1) QKV GEMM
    cudaFuncSetAttribute(gemm_tf32_db, cudaFuncAttributeMaxDynamicSharedMemorySize,
                         GEMM_SMEM);
    gemm_tf32_db<<<dim3(3 * Cc / 128, (M + 127) / 128), 256, GEMM_SMEM>>>(
        xr, wqkvT, bqkv, qkv, M, 3 * Cc, Cc);

    // 2) RoPE + split + transpose
    rope_split_kernel<<<dim3((Lq + 63) / 64, Hh, Bb), 256>>>(
        qkv, rope, q, khi, klo, vthi, vtlo);

    // 3) Flash attention
    cudaFuncSetAttribute(flash_mma_db, cudaFuncAttributeMaxDynamicSharedMemorySize,
                         FLASH_SMEM);
    flash_mma_db<<<dim3((Lq + 127) / 128, Hh, Bb), 256, FLASH_SMEM>>>(
        q, khi, klo, vthi, vtlo, attn);

    // 4) LayerNorm (emits tf32-rounded)
    ln_kernel<<<M, 256>>>(attn, gamma, beta, ln);

    // 5) Projection GEMM
    gemm_tf32_db<<<dim3(Cc / 128, (M + 127) / 128), 256, GEMM_SMEM>>>(
        ln, wprojT, bproj, out, M, Cc, Cc);
}

// round 10
// speedup vs baseline: 3.6782x; 1.1319x over previous
#include <cuda_runtime.h>
#include <cuda_bf16.h>
#include <cuda_fp16.h>
#include <cstdint>

// Problem constants
#define Bb 4
#define Lq 2052
#define Cc 1024
#define Hh 16
#define Dd 64
#define NREG 4
#define ROWS (Bb * Lq)                  // 8208
#define ROPE_PLANE ((Lq - NREG) * Dd)   // 2048*64
#define LPAD 2064                       // padded L for transposed V rows

// -------- scratch (device globals; no allocation allowed) ------------------
__device__ float g_qkv[(size_t)ROWS * 3 * Cc];       // QKV GEMM output
__device__ float g_q[(size_t)Bb * Hh * Lq * Dd];     // Q fp32 [B,H,L,D]
__device__ __nv_bfloat16 g_khi[(size_t)Bb * Hh * Lq * Dd];
__device__ __nv_bfloat16 g_klo[(size_t)Bb * Hh * Lq * Dd];
__device__ __half g_vt[(size_t)Bb * Hh * Dd * LPAD];  // V^T fp16 [B,H,D,Lpad]
__device__ float g_attn[(size_t)ROWS * Cc];          // attention out [B,L,C]
__device__ float g_ln[(size_t)ROWS * Cc];            // LN out (tf32-rounded)
__device__ float g_xr[(size_t)ROWS * Cc];            // x rounded to tf32
__device__ float g_wqkvT[(size_t)3 * Cc * Cc];       // Wqkv^T [3C][C] tf32
__device__ float g_wprojT[(size_t)Cc * Cc];          // Wproj^T [C][C] tf32

// ---------------------------------------------------------------------------
// helpers
// ---------------------------------------------------------------------------
__device__ __forceinline__ unsigned f2tf32(float f) {
    unsigned u;
    asm("cvt.rna.tf32.f32 %0, %1;" : "=r"(u) : "f"(f));
    return u;
}

__device__ __forceinline__ float ex2f(float x) {
    float r;
    asm("ex2.approx.ftz.f32 %0, %1;" : "=f"(r) : "f"(x));
    return r;
}

__device__ __forceinline__ void mma_tf32(float* c, const unsigned* a,
                                         const unsigned* b) {
    asm volatile(
        "mma.sync.aligned.m16n8k8.row.col.f32.tf32.tf32.f32 "
        "{%0,%1,%2,%3}, {%4,%5,%6,%7}, {%8,%9}, {%0,%1,%2,%3};"
        : "+f"(c[0]), "+f"(c[1]), "+f"(c[2]), "+f"(c[3])
        : "r"(a[0]), "r"(a[1]), "r"(a[2]), "r"(a[3]), "r"(b[0]), "r"(b[1]));
}

__device__ __forceinline__ void mma_bf16(float* c, const unsigned* a,
                                         const unsigned* b) {
    asm volatile(
        "mma.sync.aligned.m16n8k16.row.col.f32.bf16.bf16.f32 "
        "{%0,%1,%2,%3}, {%4,%5,%6,%7}, {%8,%9}, {%0,%1,%2,%3};"
        : "+f"(c[0]), "+f"(c[1]), "+f"(c[2]), "+f"(c[3])
        : "r"(a[0]), "r"(a[1]), "r"(a[2]), "r"(a[3]), "r"(b[0]), "r"(b[1]));
}

__device__ __forceinline__ void mma_f16(float* c, const unsigned* a,
                                        const unsigned* b) {
    asm volatile(
        "mma.sync.aligned.m16n8k16.row.col.f32.f16.f16.f32 "
        "{%0,%1,%2,%3}, {%4,%5,%6,%7}, {%8,%9}, {%0,%1,%2,%3};"
        : "+f"(c[0]), "+f"(c[1]), "+f"(c[2]), "+f"(c[3])
        : "r"(a[0]), "r"(a[1]), "r"(a[2]), "r"(a[3]), "r"(b[0]), "r"(b[1]));
}

__device__ __forceinline__ void ldsm_x4(unsigned& r0, unsigned& r1,
                                        unsigned& r2, unsigned& r3,
                                        unsigned addr) {
    asm volatile(
        "ldmatrix.sync.aligned.m8n8.x4.shared.b16 {%0,%1,%2,%3}, [%4];"
        : "=r"(r0), "=r"(r1), "=r"(r2), "=r"(r3)
        : "r"(addr));
}

__device__ __forceinline__ unsigned pack_bf16(float x, float y) {
    __nv_bfloat162 t = __floats2bfloat162_rn(x, y);
    return *(unsigned*)&t;
}

__device__ __forceinline__ void split2(float x, float y, unsigned& hi,
                                       unsigned& lo) {
    __nv_bfloat16 hx = __float2bfloat16_rn(x);
    __nv_bfloat16 hy = __float2bfloat16_rn(y);
    float rx = x - __bfloat162float(hx);
    float ry = y - __bfloat162float(hy);
    __nv_bfloat162 h;
    h.x = hx;
    h.y = hy;
    hi = *(unsigned*)&h;
    lo = pack_bf16(rx, ry);
}

// split pair into fp16 hi + fp16 residual, packed
__device__ __forceinline__ void split2h(float x, float y, unsigned& hi,
                                        unsigned& lo) {
    __half hx = __float2half_rn(x);
    __half hy = __float2half_rn(y);
    float rx = x - __half2float(hx);
    float ry = y - __half2float(hy);
    __half2 h;
    h.x = hx;
    h.y = hy;
    hi = *(unsigned*)&h;
    __half2 l;
    l.x = __float2half_rn(rx);
    l.y = __float2half_rn(ry);
    lo = *(unsigned*)&l;
}

__device__ __forceinline__ unsigned smaddr(const void* p) {
    return (unsigned)__cvta_generic_to_shared(p);
}
__device__ __forceinline__ void cpa16(unsigned dst, const void* src, int sz) {
    asm volatile("cp.async.cg.shared.global [%0], [%1], 16, %2;" ::"r"(dst),
                 "l"(src), "r"(sz));
}
#define CPA_COMMIT asm volatile("cp.async.commit_group;")
#define CPA_WAIT0 asm volatile("cp.async.wait_group 0;" ::: "memory")

// ---------------------------------------------------------------------------
// prep: round x to tf32; transpose+round W -> WT [N][K]
// ---------------------------------------------------------------------------
__global__ void round_tf32_kernel(const float* __restrict__ src,
                                  float* __restrict__ dst, int n4) {
    int i = blockIdx.x * blockDim.x + threadIdx.x;
    if (i >= n4) return;
    float4 v = ((const float4*)src)[i];
    v.x = __uint_as_float(f2tf32(v.x));
    v.y = __uint_as_float(f2tf32(v.y));
    v.z = __uint_as_float(f2tf32(v.z));
    v.w = __uint_as_float(f2tf32(v.w));
    ((float4*)dst)[i] = v;
}

__global__ void transpose_round_kernel(const float* __restrict__ W,
                                       float* __restrict__ WT, int K, int N) {
    __shared__ float tile[32][33];
    int k0 = blockIdx.y * 32, n0 = blockIdx.x * 32;
    int tx = threadIdx.x, ty = threadIdx.y;
#pragma unroll
    for (int j = 0; j < 4; j++)
        tile[ty + j * 8][tx] = W[(size_t)(k0 + ty + j * 8) * N + n0 + tx];
    __syncthreads();
#pragma unroll
    for (int j = 0; j < 4; j++)
        WT[(size_t)(n0 + ty + j * 8) * K + k0 + tx] =
            __uint_as_float(f2tf32(tile[tx][ty + j * 8]));
}

// ---------------------------------------------------------------------------
// tf32 GEMM, cp.async double-buffered, both operands k-major + ldmatrix.
// (unchanged from round 9)
// ---------------------------------------------------------------------------
#define GEMM_SMEM (4 * 128 * 36 * 4)

__global__ __launch_bounds__(256) void gemm_tf32_db(
    const float* __restrict__ A, const float* __restrict__ BT,
    const float* __restrict__ bias, float* __restrict__ Cm,
    int M, int N, int K) {
    extern __shared__ float gsm[];
    float(*As)[128][36] = (float(*)[128][36])gsm;
    float(*Bs)[128][36] = (float(*)[128][36])(gsm + 2 * 128 * 36);

    int tid = threadIdx.x;
    int warp = tid >> 5, lane = tid & 31;
    int g = lane >> 2, t = lane & 3;
    int wm = (warp >> 2) * 64, wn = (warp & 3) * 32;
    int m0 = blockIdx.y * 128, n0 = blockIdx.x * 128;

    int j = lane >> 3, r = lane & 7;
    int aoff = ((j & 1) * 8 + r) * 36 + (j >> 1) * 4;
    int boff = ((j >> 1) * 8 + r) * 36 + (j & 1) * 4;

    float acc[4][4][4];
#pragma unroll
    for (int mt = 0; mt < 4; mt++)
#pragma unroll
        for (int nt = 0; nt < 4; nt++)
#pragma unroll
            for (int q = 0; q < 4; q++) acc[mt][nt][q] = 0.f;

    auto stage = [&](int buf, int k0) {
#pragma unroll
        for (int p = 0; p < 4; p++) {
            int it = tid + p * 256;
            int row = it >> 3, c4 = (it & 7) * 4;
            int ar = m0 + row;
            int arc = ar < M ? ar : 0;
            cpa16(smaddr(&As[buf][row][c4]),
                  &A[(size_t)arc * K + k0 + c4], ar < M ? 16 : 0);
        }
#pragma unroll
        for (int p = 0; p < 4; p++) {
            int it = tid + p * 256;
            int row = it >> 3, c4 = (it & 7) * 4;
            cpa16(smaddr(&Bs[buf][row][c4]),
                  &BT[(size_t)(n0 + row) * K + k0 + c4], 16);
        }
    };

    int nk = K / 32;
    stage(0, 0);
    CPA_COMMIT;

    for (int kt = 0; kt < nk; kt++) {
        CPA_WAIT0;
        __syncthreads();
        if (kt + 1 < nk) {
            stage((kt + 1) & 1, (kt + 1) * 32);
            CPA_COMMIT;
        }
        int buf = kt & 1;
        unsigned Abase = smaddr(&As[buf][0][0]);
        unsigned Bbase = smaddr(&Bs[buf][0][0]);
#pragma unroll
        for (int ks = 0; ks < 4; ks++) {
            unsigned af[4][4], bf[4][2];
#pragma unroll
            for (int mt = 0; mt < 4; mt++) {
                unsigned ad =
                    Abase + ((wm + mt * 16) * 36 + ks * 8 + aoff) * 4;
                ldsm_x4(af[mt][0], af[mt][1], af[mt][2], af[mt][3], ad);
            }
#pragma unroll
            for (int pr = 0; pr < 2; pr++) {
                unsigned bd =
                    Bbase + ((wn + pr * 16) * 36 + ks * 8 + boff) * 4;
                ldsm_x4(bf[2 * pr][0], bf[2 * pr][1], bf[2 * pr + 1][0],
                        bf[2 * pr + 1][1], bd);
            }
#pragma unroll
            for (int mt = 0; mt < 4; mt++)
#pragma unroll
                for (int nt = 0; nt < 4; nt++)
                    mma_tf32(acc[mt][nt], af[mt], bf[nt]);
        }
    }

#pragma unroll
    for (int mt = 0; mt < 4; mt++) {
        int row = m0 + wm + mt * 16 + g;
#pragma unroll
        for (int nt = 0; nt < 4; nt++) {
            int col = n0 + wn + nt * 8 + t * 2;
            float b0 = bias[col], b1 = bias[col + 1];
            if (row < M) {
                *(float2*)&Cm[(size_t)row * N + col] =
                    make_float2(acc[mt][nt][0] + b0, acc[mt][nt][1] + b1);
            }
            if (row + 8 < M) {
                *(float2*)&Cm[(size_t)(row + 8) * N + col] =
                    make_float2(acc[mt][nt][2] + b0, acc[mt][nt][3] + b1);
            }
        }
    }
}

// ---------------------------------------------------------------------------
// RoPE + split + transpose: Q fp32; K hi/lo bf16 [B,H,L,D]; V^T fp16 [B,H,D,LPAD]
// ---------------------------------------------------------------------------
__global__ __launch_bounds__(256) void rope_split_kernel(
    const float* __restrict__ qkv, const float* __restrict__ rope,
    float* __restrict__ Q, __nv_bfloat16* __restrict__ KHI,
    __nv_bfloat16* __restrict__ KLO, __half* __restrict__ VT) {
    __shared__ __half vh[64][72];  // [d][l_local]
    int lt0 = blockIdx.x * 64, h = blockIdx.y, b = blockIdx.z;
    int tid = threadIdx.x;
    size_t bh = (size_t)(b * Hh + h);

    for (int it = tid; it < 64 * 16; it += 256) {
        int ll = it >> 4, d4 = (it & 15) * 4;
        int l = lt0 + ll;
        if (l < Lq) {
            size_t base = ((size_t)b * Lq + l) * (3 * Cc) + h * Dd;
            float4 qv = *(const float4*)&qkv[base + d4];
            float4 kv = *(const float4*)&qkv[base + Cc + d4];
            float4 vv = *(const float4*)&qkv[base + 2 * Cc + d4];
            if (l >= NREG) {
                int dp = d4 ^ 32;
                float4 qp = *(const float4*)&qkv[base + dp];
                float4 kp = *(const float4*)&qkv[base + Cc + dp];
                float4 cs = *(const float4*)&rope[(size_t)(l - NREG) * Dd + d4];
                float4 sn = *(const float4*)&rope[(size_t)ROPE_PLANE +
                                                  (size_t)(l - NREG) * Dd + d4];
                float sgn = (d4 < 32) ? -1.f : 1.f;
                qv.x = qv.x * cs.x + sgn * qp.x * sn.x;
                qv.y = qv.y * cs.y + sgn * qp.y * sn.y;
                qv.z = qv.z * cs.z + sgn * qp.z * sn.z;
                qv.w = qv.w * cs.w + sgn * qp.w * sn.w;
                kv.x = kv.x * cs.x + sgn * kp.x * sn.x;
                kv.y = kv.y * cs.y + sgn * kp.y * sn.y;
                kv.z = kv.z * cs.z + sgn * kp.z * sn.z;
                kv.w = kv.w * cs.w + sgn * kp.w * sn.w;
            }
            size_t oidx = (bh * Lq + l) * Dd + d4;
            *(float4*)&Q[oidx] = qv;
            unsigned h0, l0w, h1, l1w;
            split2(kv.x, kv.y, h0, l0w);
            split2(kv.z, kv.w, h1, l1w);
            *(uint2*)&KHI[oidx] = make_uint2(h0, h1);
            *(uint2*)&KLO[oidx] = make_uint2(l0w, l1w);
            vh[d4 + 0][ll] = __float2half_rn(vv.x);
            vh[d4 + 1][ll] = __float2half_rn(vv.y);
            vh[d4 + 2][ll] = __float2half_rn(vv.z);
            vh[d4 + 3][ll] = __float2half_rn(vv.w);
        } else {
            __half z = __float2half_rn(0.f);
#pragma unroll
            for (int jj = 0; jj < 4; jj++) vh[d4 + jj][ll] = z;
        }
    }
    __syncthreads();
    for (int it = tid; it < 64 * 8; it += 256) {
        int d = it >> 3, c8 = (it & 7) * 8;
        int l = lt0 + c8;
        if (l < LPAD)
            *(uint4*)&VT[(bh * Dd + d) * LPAD + l] = *(uint4*)&vh[d][c8];
    }
}

// ---------------------------------------------------------------------------
// Flash attention: QK bf16x3, softmax in exp2 domain, PV = P(fp16 hi/lo) x
// V(fp16). Q in smem, cp.async double-buffered KV, 2 CTAs/SM.
// smem: Qhi/Qlo [128][72] + 2 x {khi,klo,v} [64][72] = 92160 B.
// ---------------------------------------------------------------------------
#define QARR (128 * 72)
#define FARR (64 * 72)
#define FBUF (3 * FARR)
#define FLASH_SMEM ((2 * QARR + 2 * FBUF) * 2)

__global__ __launch_bounds__(256, 2) void flash_mma_db(
    const float* __restrict__ Q, const __nv_bfloat16* __restrict__ KHI,
    const __nv_bfloat16* __restrict__ KLO, const __half* __restrict__ VT,
    float* __restrict__ O) {
    extern __shared__ __nv_bfloat16 fsm[];
    __nv_bfloat16* Qh = fsm;
    __nv_bfloat16* Ql = fsm + QARR;
    __nv_bfloat16* KV = fsm + 2 * QARR;

    int tid = threadIdx.x;
    int warp = tid >> 5, lane = tid & 31;
    int g = lane >> 2, t = lane & 3;
    int q0 = blockIdx.x * 128;
    int h = blockIdx.y, b = blockIdx.z;
    size_t bh = (size_t)(b * Hh + h);
    const float* Qb = Q + bh * Lq * Dd;
    const __nv_bfloat16* KHIb = KHI + bh * Lq * Dd;
    const __nv_bfloat16* KLOb = KLO + bh * Lq * Dd;
    const __half* VTb = VT + bh * Dd * LPAD;

    int r0 = q0 + warp * 16 + g;
    int r1 = r0 + 8;

    int mi = lane >> 3, rr = lane & 7;
    unsigned ldsm_off = (((mi >> 1) * 8 + rr) * 72 + (mi & 1) * 8) * 2;
    unsigned q_off = (((mi & 1) * 8 + rr) * 72 + (mi >> 1) * 8) * 2;

    // stage Q once: scaled by (1/sqrt(D)) * log2(e) -> softmax in exp2 domain
    const float scale = 0.125f * 1.4426950408889634f;
    for (int it = tid; it < 128 * 16; it += 256) {
        int row = it >> 4, c4 = (it & 15) * 4;
        int l = q0 + row;
        float4 v = make_float4(0.f, 0.f, 0.f, 0.f);
        if (l < Lq) v = *(const float4*)&Qb[(size_t)l * Dd + c4];
        unsigned h0, l0w, h1, l1w;
        split2(v.x * scale, v.y * scale, h0, l0w);
        split2(v.z * scale, v.w * scale, h1, l1w);
        *(uint2*)&Qh[row * 72 + c4] = make_uint2(h0, h1);
        *(uint2*)&Ql[row * 72 + c4] = make_uint2(l0w, l1w);
    }

    float m0 = -1e30f, m1 = -1e30f, l0 = 0.f, l1 = 0.f;
    float o[8][4];
#pragma unroll
    for (int nf = 0; nf < 8; nf++)
#pragma unroll
        for (int q = 0; q < 4; q++) o[nf][q] = 0.f;

    auto stage = [&](int buf, int kt) {
        int k0 = kt * 64;
        __nv_bfloat16* B = KV + buf * FBUF;
#pragma unroll
        for (int p = 0; p < 6; p++) {
            int it = tid + p * 256;          // 0..1535
            int arr = it >> 9;               // 0:khi 1:klo 2:v
            int idx = it & 511;
            int row = idx >> 3, c8 = (idx & 7) * 8;
            __nv_bfloat16* dst = B + arr * FARR + row * 72 + c8;
            if (arr < 2) {
                int kr = k0 + row;
                int krc = kr < Lq ? kr : 0;
                const __nv_bfloat16* src =
                    (arr == 0 ? KHIb : KLOb) + (size_t)krc * Dd + c8;
                cpa16(smaddr(dst), src, kr < Lq ? 16 : 0);
            } else {
                int col = k0 + c8;
                int colc = col < LPAD ? col : 0;
                const __half* src = VTb + (size_t)row * LPAD + colc;
                cpa16(smaddr(dst), src, col < LPAD ? 16 : 0);
            }
        }
    };

    int nkt = (Lq + 63) / 64;  // 33
    stage(0, 0);
    CPA_COMMIT;

    unsigned qhB = smaddr(Qh) + warp * 16 * 72 * 2 + q_off;
    unsigned qlB = qhB + QARR * 2;

    for (int kt = 0; kt < nkt; kt++) {
        CPA_WAIT0;
        __syncthreads();
        if (kt + 1 < nkt) {
            stage((kt + 1) & 1, kt + 1);
            CPA_COMMIT;
        }
        int k0 = kt * 64;
        unsigned khiB = smaddr(KV + (kt & 1) * FBUF) + ldsm_off;
        unsigned kloB = khiB + FARR * 2;
        unsigned vB = khiB + 2 * FARR * 2;

        // S = Q K^T (bf16x3), log2-domain logits
        float s[8][4];
#pragma unroll
        for (int nf = 0; nf < 8; nf++)
#pragma unroll
            for (int q = 0; q < 4; q++) s[nf][q] = 0.f;

#pragma unroll
        for (int ks = 0; ks < 4; ks++) {
            unsigned qh4[4], ql4[4];
            ldsm_x4(qh4[0], qh4[1], qh4[2], qh4[3], qhB + ks * 32);
            ldsm_x4(ql4[0], ql4[1], ql4[2], ql4[3], qlB + ks * 32);
#pragma unroll
            for (int q = 0; q < 4; q++) {
                unsigned off = (q * 16 * 72 + ks * 16) * 2;
                unsigned bh0[2], bh1[2], bl0[2], bl1[2];
                ldsm_x4(bh0[0], bh0[1], bh1[0], bh1[1], khiB + off);
                ldsm_x4(bl0[0], bl0[1], bl1[0], bl1[1], kloB + off);
                mma_bf16(s[2 * q], qh4, bh0);
                mma_bf16(s[2 * q], qh4, bl0);
                mma_bf16(s[2 * q], ql4, bh0);
                mma_bf16(s[2 * q + 1], qh4, bh1);
                mma_bf16(s[2 * q + 1], qh4, bl1);
                mma_bf16(s[2 * q + 1], ql4, bh1);
            }
        }

        // mask + online softmax (exp2 domain)
#pragma unroll
        for (int nf = 0; nf < 8; nf++) {
            int c = k0 + nf * 8 + 2 * t;
            if (c >= Lq) s[nf][0] = s[nf][2] = -1e30f;
            if (c + 1 >= Lq) s[nf][1] = s[nf][3] = -1e30f;
        }
        float mx0 = -1e30f, mx1 = -1e30f;
#pragma unroll
        for (int nf = 0; nf < 8; nf++) {
            mx0 = fmaxf(mx0, fmaxf(s[nf][0], s[nf][1]));
            mx1 = fmaxf(mx1, fmaxf(s[nf][2], s[nf][3]));
        }
        mx0 = fmaxf(mx0, __shfl_xor_sync(0xffffffffu, mx0, 1));
        mx0 = fmaxf(mx0, __shfl_xor_sync(0xffffffffu, mx0, 2));
        mx1 = fmaxf(mx1, __shfl_xor_sync(0xffffffffu, mx1, 1));
        mx1 = fmaxf(mx1, __shfl_xor_sync(0xffffffffu, mx1, 2));
        float mn0 = fmaxf(m0, mx0), mn1 = fmaxf(m1, mx1);
        float a0 = ex2f(m0 - mn0), a1 = ex2f(m1 - mn1);
        m0 = mn0;
        m1 = mn1;
        float rs0 = 0.f, rs1 = 0.f;
#pragma unroll
        for (int nf = 0; nf < 8; nf++) {
            s[nf][0] = ex2f(s[nf][0] - mn0);
            s[nf][1] = ex2f(s[nf][1] - mn0);
            s[nf][2] = ex2f(s[nf][2] - mn1);
            s[nf][3] = ex2f(s[nf][3] - mn1);
            rs0 += s[nf][0] + s[nf][1];
            rs1 += s[nf][2] + s[nf][3];
        }
        rs0 += __shfl_xor_sync(0xffffffffu, rs0, 1);
        rs0 += __shfl_xor_sync(0xffffffffu, rs0, 2);
        rs1 += __shfl_xor_sync(0xffffffffu, rs1, 1);
        rs1 += __shfl_xor_sync(0xffffffffu, rs1, 2);
        l0 = l0 * a0 + rs0;
        l1 = l1 * a1 + rs1;
#pragma unroll
        for (int nf = 0; nf < 8; nf++) {
            o[nf][0] *= a0;
            o[nf][1] *= a0;
            o[nf][2] *= a1;
            o[nf][3] *= a1;
        }

        // O += P V : P fp16 hi/lo x V fp16 (64 mma)
#pragma unroll
        for (int ks = 0; ks < 4; ks++) {
            unsigned ph[4], pl[4];
            split2h(s[2 * ks][0], s[2 * ks][1], ph[0], pl[0]);
            split2h(s[2 * ks][2], s[2 * ks][3], ph[1], pl[1]);
            split2h(s[2 * ks + 1][0], s[2 * ks + 1][1], ph[2], pl[2]);
            split2h(s[2 * ks + 1][2], s[2 * ks + 1][3], ph[3], pl[3]);
#pragma unroll
            for (int q = 0; q < 4; q++) {
                unsigned off = (q * 16 * 72 + ks * 16) * 2;
                unsigned vh0[2], vh1[2];
                ldsm_x4(vh0[0], vh0[1], vh1[0], vh1[1], vB + off);
                mma_f16(o[2 * q], ph, vh0);
                mma_f16(o[2 * q], pl, vh0);
                mma_f16(o[2 * q + 1], ph, vh1);
                mma_f16(o[2 * q + 1], pl, vh1);
            }
        }
    }

    float inv0 = 1.f / l0, inv1 = 1.f / l1;
#pragma unroll
    for (int nf = 0; nf < 8; nf++) {
        int col = h * Dd + nf * 8 + 2 * t;
        if (r0 < Lq)
            *(float2*)&O[((size_t)b * Lq + r0) * Cc + col] =
                make_float2(o[nf][0] * inv0, o[nf][1] * inv0);
        if (r1 < Lq)
            *(float2*)&O[((size_t)b * Lq + r1) * Cc + col] =
                make_float2(o[nf][2] * inv1, o[nf][3] * inv1);
    }
}

// ---------------------------------------------------------------------------
// LayerNorm; output rounded to tf32 (unchanged)
// ---------------------------------------------------------------------------
__global__ void ln_kernel(const float* __restrict__ in,
                          const float* __restrict__ gamma,
                          const float* __restrict__ beta,
                          float* __restrict__ out) {
    int row = blockIdx.x;
    int tid = threadIdx.x;
    const float* r = in + (size_t)row * Cc;
    float4 v = *(const float4*)&r[tid * 4];
    float s = v.x + v.y + v.z + v.w;
    float s2 = v.x * v.x + v.y * v.y + v.z * v.z + v.w * v.w;
#pragma unroll
    for (int off = 16; off >= 1; off >>= 1) {
        s += __shfl_xor_sync(0xffffffffu, s, off);
        s2 += __shfl_xor_sync(0xffffffffu, s2, off);
    }
    __shared__ float ws[8], ws2[8];
    __shared__ float mean_s, rstd_s;
    int wid = tid >> 5, lane = tid & 31;
    if (lane == 0) {
        ws[wid] = s;
        ws2[wid] = s2;
    }
    __syncthreads();
    if (tid == 0) {
        float S = 0.f, S2 = 0.f;
#pragma unroll
        for (int i = 0; i < 8; i++) {
            S += ws[i];
            S2 += ws2[i];
        }
        float mean = S * (1.f / Cc);
        float var = S2 * (1.f / Cc) - mean * mean;
        mean_s = mean;
        rstd_s = rsqrtf(var + 1e-5f);
    }
    __syncthreads();
    float mean = mean_s, rstd = rstd_s;
    float4 g = *(const float4*)&gamma[tid * 4];
    float4 bt = *(const float4*)&beta[tid * 4];
    float4 o;
    o.x = __uint_as_float(f2tf32((v.x - mean) * rstd * g.x + bt.x));
    o.y = __uint_as_float(f2tf32((v.y - mean) * rstd * g.y + bt.y));
    o.z = __uint_as_float(f2tf32((v.z - mean) * rstd * g.z + bt.z));
    o.w = __uint_as_float(f2tf32((v.w - mean) * rstd * g.w + bt.w));
    *(float4*)&out[(size_t)row * Cc + tid * 4] = o;
}

// ---------------------------------------------------------------------------
extern "C" void kernel_launch(void* const* d_in, const int* in_sizes, int n_in,
                              void* d_out, int out_size) {
    const float* x = (const float*)d_in[0];
    const float* rope = (const float*)d_in[1];
    const float* Wqkv = (const float*)d_in[2];
    const float* bqkv = (const float*)d_in[3];
    const float* Wproj = (const float*)d_in[4];
    const float* bproj = (const float*)d_in[5];
    const float* gamma = (const float*)d_in[6];
    const float* beta = (const float*)d_in[7];
    float* out = (float*)d_out;

    float *qkv, *q, *attn, *ln, *xr, *wqkvT, *wprojT;
    __nv_bfloat16 *khi, *klo;
    __half* vt;
    cudaGetSymbolAddress((void**)&qkv, g_qkv);
    cudaGetSymbolAddress((void**)&q, g_q);
    cudaGetSymbolAddress((void**)&khi, g_khi);
    cudaGetSymbolAddress((void**)&klo, g_klo);
    cudaGetSymbolAddress((void**)&vt, g_vt);
    cudaGetSymbolAddress((void**)&attn, g_attn);
    cudaGetSymbolAddress((void**)&ln, g_ln);
    cudaGetSymbolAddress((void**)&xr, g_xr);
    cudaGetSymbolAddress((void**)&wqkvT, g_wqkvT);
    cudaGetSymbolAddress((void**)&wprojT, g_wprojT);

    const int M = ROWS;  // 8208

    // 0) pre-round x; transpose+round weights to [N][K]
    int nx4 = ROWS * Cc / 4;
    round_tf32_kernel<<<(nx4 + 255) / 256, 256>>>(x, xr, nx4);
    transpose_round_kernel<<<dim3(3 * Cc / 32, Cc / 32), dim3(32, 8)>>>(
        Wqkv, wqkvT, Cc, 3 * Cc);
    transpose_round_kernel<<<dim3(Cc / 32, Cc / 32), dim3(32, 8)>>>(
        Wproj, wprojT, Cc, Cc);

    // 1) QKV GEMM
    cudaFuncSetAttribute(gemm_tf32_db, cudaFuncAttributeMaxDynamicSharedMemorySize,
                         GEMM_SMEM);
    gemm_tf32_db<<<dim3(3 * Cc / 128, (M + 127) / 128), 256, GEMM_SMEM>>>(
        xr, wqkvT, bqkv, qkv, M, 3 * Cc, Cc);

    // 2) RoPE + split + transpose
    rope_split_kernel<<<dim3((Lq + 63) / 64, Hh, Bb), 256>>>(
        qkv, rope, q, khi, klo, vt);

    // 3) Flash attention
    cudaFuncSetAttribute(flash_mma_db, cudaFuncAttributeMaxDynamicSharedMemorySize,
                         FLASH_SMEM);
    flash_mma_db<<<dim3((Lq + 127) / 128, Hh, Bb), 256, FLASH_SMEM>>>(
        q, khi, klo, vt, attn);

    // 4) LayerNorm (emits tf32-rounded)
    ln_kernel<<<M, 256>>>(attn, gamma, beta, ln);

    // 5) Projection GEMM
    gemm_tf32_db<<<dim3(Cc / 128, (M + 127) / 128), 256, GEMM_SMEM>>>(
        ln, wprojT, bproj, out, M, Cc, Cc);
}

// round 11
// speedup vs baseline: 3.7770x; 1.0269x over previous
#include <cuda_runtime.h>
#include <cuda_bf16.h>
#include <cuda_fp16.h>
#include <cstdint>

// Problem constants
#define Bb 4
#define Lq 2052
#define Cc 1024
#define Hh 16
#define Dd 64
#define NREG 4
#define ROWS (Bb * Lq)                  // 8208
#define ROPE_PLANE ((Lq - NREG) * Dd)   // 2048*64
#define LPAD 2064                       // padded L for transposed V rows

// -------- scratch (device globals; no allocation allowed) ------------------
__device__ float g_qkv[(size_t)ROWS * 3 * Cc];       // QKV GEMM output
__device__ float g_q[(size_t)Bb * Hh * Lq * Dd];     // Q fp32 [B,H,L,D]
__device__ __nv_bfloat16 g_khi[(size_t)Bb * Hh * Lq * Dd];
__device__ __nv_bfloat16 g_klo[(size_t)Bb * Hh * Lq * Dd];
__device__ __half g_vt[(size_t)Bb * Hh * Dd * LPAD];  // V^T fp16 [B,H,D,Lpad]
__device__ float g_attn[(size_t)ROWS * Cc];          // attention out [B,L,C]
__device__ float g_ln[(size_t)ROWS * Cc];            // LN out (tf32-rounded)
__device__ float g_xr[(size_t)ROWS * Cc];            // x rounded to tf32
__device__ float g_wqkvT[(size_t)3 * Cc * Cc];       // Wqkv^T [3C][C] tf32
__device__ float g_wprojT[(size_t)Cc * Cc];          // Wproj^T [C][C] tf32

// ---------------------------------------------------------------------------
// helpers
// ---------------------------------------------------------------------------
__device__ __forceinline__ unsigned f2tf32(float f) {
    unsigned u;
    asm("cvt.rna.tf32.f32 %0, %1;" : "=r"(u) : "f"(f));
    return u;
}

__device__ __forceinline__ float ex2f(float x) {
    float r;
    asm("ex2.approx.ftz.f32 %0, %1;" : "=f"(r) : "f"(x));
    return r;
}

__device__ __forceinline__ void mma_tf32(float* c, const unsigned* a,
                                         const unsigned* b) {
    asm volatile(
        "mma.sync.aligned.m16n8k8.row.col.f32.tf32.tf32.f32 "
        "{%0,%1,%2,%3}, {%4,%5,%6,%7}, {%8,%9}, {%0,%1,%2,%3};"
        : "+f"(c[0]), "+f"(c[1]), "+f"(c[2]), "+f"(c[3])
        : "r"(a[0]), "r"(a[1]), "r"(a[2]), "r"(a[3]), "r"(b[0]), "r"(b[1]));
}

__device__ __forceinline__ void mma_bf16(float* c, const unsigned* a,
                                         const unsigned* b) {
    asm volatile(
        "mma.sync.aligned.m16n8k16.row.col.f32.bf16.bf16.f32 "
        "{%0,%1,%2,%3}, {%4,%5,%6,%7}, {%8,%9}, {%0,%1,%2,%3};"
        : "+f"(c[0]), "+f"(c[1]), "+f"(c[2]), "+f"(c[3])
        : "r"(a[0]), "r"(a[1]), "r"(a[2]), "r"(a[3]), "r"(b[0]), "r"(b[1]));
}

__device__ __forceinline__ void mma_f16(float* c, const unsigned* a,
                                        const unsigned* b) {
    asm volatile(
        "mma.sync.aligned.m16n8k16.row.col.f32.f16.f16.f32 "
        "{%0,%1,%2,%3}, {%4,%5,%6,%7}, {%8,%9}, {%0,%1,%2,%3};"
        : "+f"(c[0]), "+f"(c[1]), "+f"(c[2]), "+f"(c[3])
        : "r"(a[0]), "r"(a[1]), "r"(a[2]), "r"(a[3]), "r"(b[0]), "r"(b[1]));
}

__device__ __forceinline__ void ldsm_x4(unsigned& r0, unsigned& r1,
                                        unsigned& r2, unsigned& r3,
                                        unsigned addr) {
    asm volatile(
        "ldmatrix.sync.aligned.m8n8.x4.shared.b16 {%0,%1,%2,%3}, [%4];"
        : "=r"(r0), "=r"(r1), "=r"(r2), "=r"(r3)
        : "r"(addr));
}

__device__ __forceinline__ unsigned pack_bf16(float x, float y) {
    __nv_bfloat162 t = __floats2bfloat162_rn(x, y);
    return *(unsigned*)&t;
}

__device__ __forceinline__ void split2(float x, float y, unsigned& hi,
                                       unsigned& lo) {
    __nv_bfloat16 hx = __float2bfloat16_rn(x);
    __nv_bfloat16 hy = __float2bfloat16_rn(y);
    float rx = x - __bfloat162float(hx);
    float ry = y - __bfloat162float(hy);
    __nv_bfloat162 h;
    h.x = hx;
    h.y = hy;
    hi = *(unsigned*)&h;
    lo = pack_bf16(rx, ry);
}

__device__ __forceinline__ void split2h(float x, float y, unsigned& hi,
                                        unsigned& lo) {
    __half hx = __float2half_rn(x);
    __half hy = __float2half_rn(y);
    float rx = x - __half2float(hx);
    float ry = y - __half2float(hy);
    __half2 h;
    h.x = hx;
    h.y = hy;
    hi = *(unsigned*)&h;
    __half2 l;
    l.x = __float2half_rn(rx);
    l.y = __float2half_rn(ry);
    lo = *(unsigned*)&l;
}

__device__ __forceinline__ unsigned smaddr(const void* p) {
    return (unsigned)__cvta_generic_to_shared(p);
}
__device__ __forceinline__ void cpa16(unsigned dst, const void* src, int sz) {
    asm volatile("cp.async.cg.shared.global [%0], [%1], 16, %2;" ::"r"(dst),
                 "l"(src), "r"(sz));
}
#define CPA_COMMIT asm volatile("cp.async.commit_group;")
#define CPA_WAIT0 asm volatile("cp.async.wait_group 0;" ::: "memory")

// ---------------------------------------------------------------------------
// prep: round x to tf32; transpose+round W -> WT [N][K]
// ---------------------------------------------------------------------------
__global__ void round_tf32_kernel(const float* __restrict__ src,
                                  float* __restrict__ dst, int n4) {
    int i = blockIdx.x * blockDim.x + threadIdx.x;
    if (i >= n4) return;
    float4 v = ((const float4*)src)[i];
    v.x = __uint_as_float(f2tf32(v.x));
    v.y = __uint_as_float(f2tf32(v.y));
    v.z = __uint_as_float(f2tf32(v.z));
    v.w = __uint_as_float(f2tf32(v.w));
    ((float4*)dst)[i] = v;
}

__global__ void transpose_round_kernel(const float* __restrict__ W,
                                       float* __restrict__ WT, int K, int N) {
    __shared__ float tile[32][33];
    int k0 = blockIdx.y * 32, n0 = blockIdx.x * 32;
    int tx = threadIdx.x, ty = threadIdx.y;
#pragma unroll
    for (int j = 0; j < 4; j++)
        tile[ty + j * 8][tx] = W[(size_t)(k0 + ty + j * 8) * N + n0 + tx];
    __syncthreads();
#pragma unroll
    for (int j = 0; j < 4; j++)
        WT[(size_t)(n0 + ty + j * 8) * K + k0 + tx] =
            __uint_as_float(f2tf32(tile[tx][ty + j * 8]));
}

// ---------------------------------------------------------------------------
// tf32 GEMM: block tile 128x256, BK=64, warp tile 64x64, double-buffered
// cp.async, both operands k-major + ldmatrix.
// smem: As[2][128][68] + Bs[2][256][68] floats = 208896 B.
// ---------------------------------------------------------------------------
#define GEMM_SMEM ((2 * 128 * 68 + 2 * 256 * 68) * 4)

__global__ __launch_bounds__(256) void gemm_tf32_db(
    const float* __restrict__ A, const float* __restrict__ BT,
    const float* __restrict__ bias, float* __restrict__ Cm,
    int M, int N, int K) {
    extern __shared__ float gsm[];
    float(*As)[128][68] = (float(*)[128][68])gsm;
    float(*Bs)[256][68] = (float(*)[256][68])(gsm + 2 * 128 * 68);

    int tid = threadIdx.x;
    int warp = tid >> 5, lane = tid & 31;
    int g = lane >> 2, t = lane & 3;
    int wm = (warp >> 2) * 64, wn = (warp & 3) * 64;
    int m0 = blockIdx.y * 128, n0 = blockIdx.x * 256;

    // ldmatrix lane offsets (fp32 8x4 matrices, row stride 68 words)
    int j = lane >> 3, r = lane & 7;
    int aoff = ((j & 1) * 8 + r) * 68 + (j >> 1) * 4;   // A: m-pair, k-half
    int boff = ((j >> 1) * 8 + r) * 68 + (j & 1) * 4;   // B: n-pair, k-half

    float acc[4][8][4];
#pragma unroll
    for (int mt = 0; mt < 4; mt++)
#pragma unroll
        for (int nt = 0; nt < 8; nt++)
#pragma unroll
            for (int q = 0; q < 4; q++) acc[mt][nt][q] = 0.f;

    auto stage = [&](int buf, int k0) {
        // A: 128 rows x 16 float4
#pragma unroll
        for (int p = 0; p < 8; p++) {
            int it = tid + p * 256;
            int row = it >> 4, c4 = (it & 15) * 4;
            int ar = m0 + row;
            int arc = ar < M ? ar : 0;
            cpa16(smaddr(&As[buf][row][c4]),
                  &A[(size_t)arc * K + k0 + c4], ar < M ? 16 : 0);
        }
        // B: 256 rows x 16 float4
#pragma unroll
        for (int p = 0; p < 16; p++) {
            int it = tid + p * 256;
            int row = it >> 4, c4 = (it & 15) * 4;
            cpa16(smaddr(&Bs[buf][row][c4]),
                  &BT[(size_t)(n0 + row) * K + k0 + c4], 16);
        }
    };

    int nk = K / 64;  // 16
    stage(0, 0);
    CPA_COMMIT;

    for (int kt = 0; kt < nk; kt++) {
        CPA_WAIT0;
        __syncthreads();
        if (kt + 1 < nk) {
            stage((kt + 1) & 1, (kt + 1) * 64);
            CPA_COMMIT;
        }
        int buf = kt & 1;
        unsigned Abase = smaddr(&As[buf][0][0]);
        unsigned Bbase = smaddr(&Bs[buf][0][0]);
#pragma unroll
        for (int ks = 0; ks < 8; ks++) {
            unsigned af[4][4], bf[8][2];
#pragma unroll
            for (int mt = 0; mt < 4; mt++) {
                unsigned ad =
                    Abase + ((wm + mt * 16) * 68 + ks * 8 + aoff) * 4;
                ldsm_x4(af[mt][0], af[mt][1], af[mt][2], af[mt][3], ad);
            }
#pragma unroll
            for (int pr = 0; pr < 4; pr++) {
                unsigned bd =
                    Bbase + ((wn + pr * 16) * 68 + ks * 8 + boff) * 4;
                ldsm_x4(bf[2 * pr][0], bf[2 * pr][1], bf[2 * pr + 1][0],
                        bf[2 * pr + 1][1], bd);
            }
#pragma unroll
            for (int mt = 0; mt < 4; mt++)
#pragma unroll
                for (int nt = 0; nt < 8; nt++)
                    mma_tf32(acc[mt][nt], af[mt], bf[nt]);
        }
    }

#pragma unroll
    for (int mt = 0; mt < 4; mt++) {
        int row = m0 + wm + mt * 16 + g;
#pragma unroll
        for (int nt = 0; nt < 8; nt++) {
            int col = n0 + wn + nt * 8 + t * 2;
            float b0 = bias[col], b1 = bias[col + 1];
            if (row < M) {
                *(float2*)&Cm[(size_t)row * N + col] =
                    make_float2(acc[mt][nt][0] + b0, acc[mt][nt][1] + b1);
            }
            if (row + 8 < M) {
                *(float2*)&Cm[(size_t)(row + 8) * N + col] =
                    make_float2(acc[mt][nt][2] + b0, acc[mt][nt][3] + b1);
            }
        }
    }
}

// ---------------------------------------------------------------------------
// RoPE + split + transpose: Q fp32; K hi/lo bf16 [B,H,L,D]; V^T fp16 [B,H,D,LPAD]
// ---------------------------------------------------------------------------
__global__ __launch_bounds__(256) void rope_split_kernel(
    const float* __restrict__ qkv, const float* __restrict__ rope,
    float* __restrict__ Q, __nv_bfloat16* __restrict__ KHI,
    __nv_bfloat16* __restrict__ KLO, __half* __restrict__ VT) {
    __shared__ __half vh[64][72];  // [d][l_local]
    int lt0 = blockIdx.x * 64, h = blockIdx.y, b = blockIdx.z;
    int tid = threadIdx.x;
    size_t bh = (size_t)(b * Hh + h);

    for (int it = tid; it < 64 * 16; it += 256) {
        int ll = it >> 4, d4 = (it & 15) * 4;
        int l = lt0 + ll;
        if (l < Lq) {
            size_t base = ((size_t)b * Lq + l) * (3 * Cc) + h * Dd;
            float4 qv = *(const float4*)&qkv[base + d4];
            float4 kv = *(const float4*)&qkv[base + Cc + d4];
            float4 vv = *(const float4*)&qkv[base + 2 * Cc + d4];
            if (l >= NREG) {
                int dp = d4 ^ 32;
                float4 qp = *(const float4*)&qkv[base + dp];
                float4 kp = *(const float4*)&qkv[base + Cc + dp];
                float4 cs = *(const float4*)&rope[(size_t)(l - NREG) * Dd + d4];
                float4 sn = *(const float4*)&rope[(size_t)ROPE_PLANE +
                                                  (size_t)(l - NREG) * Dd + d4];
                float sgn = (d4 < 32) ? -1.f : 1.f;
                qv.x = qv.x * cs.x + sgn * qp.x * sn.x;
                qv.y = qv.y * cs.y + sgn * qp.y * sn.y;
                qv.z = qv.z * cs.z + sgn * qp.z * sn.z;
                qv.w = qv.w * cs.w + sgn * qp.w * sn.w;
                kv.x = kv.x * cs.x + sgn * kp.x * sn.x;
                kv.y = kv.y * cs.y + sgn * kp.y * sn.y;
                kv.z = kv.z * cs.z + sgn * kp.z * sn.z;
                kv.w = kv.w * cs.w + sgn * kp.w * sn.w;
            }
            size_t oidx = (bh * Lq + l) * Dd + d4;
            *(float4*)&Q[oidx] = qv;
            unsigned h0, l0w, h1, l1w;
            split2(kv.x, kv.y, h0, l0w);
            split2(kv.z, kv.w, h1, l1w);
            *(uint2*)&KHI[oidx] = make_uint2(h0, h1);
            *(uint2*)&KLO[oidx] = make_uint2(l0w, l1w);
            vh[d4 + 0][ll] = __float2half_rn(vv.x);
            vh[d4 + 1][ll] = __float2half_rn(vv.y);
            vh[d4 + 2][ll] = __float2half_rn(vv.z);
            vh[d4 + 3][ll] = __float2half_rn(vv.w);
        } else {
            __half z = __float2half_rn(0.f);
#pragma unroll
            for (int jj = 0; jj < 4; jj++) vh[d4 + jj][ll] = z;
        }
    }
    __syncthreads();
    for (int it = tid; it < 64 * 8; it += 256) {
        int d = it >> 3, c8 = (it & 7) * 8;
        int l = lt0 + c8;
        if (l < LPAD)
            *(uint4*)&VT[(bh * Dd + d) * LPAD + l] = *(uint4*)&vh[d][c8];
    }
}

// ---------------------------------------------------------------------------
// Flash attention (round-10 passing version, unchanged): QK bf16x3, exp2
// softmax, PV = P(fp16 hi/lo) x V(fp16), Q in smem, 2 CTAs/SM.
// ---------------------------------------------------------------------------
#define QARR (128 * 72)
#define FARR (64 * 72)
#define FBUF (3 * FARR)
#define FLASH_SMEM ((2 * QARR + 2 * FBUF) * 2)

__global__ __launch_bounds__(256, 2) void flash_mma_db(
    const float* __restrict__ Q, const __nv_bfloat16* __restrict__ KHI,
    const __nv_bfloat16* __restrict__ KLO, const __half* __restrict__ VT,
    float* __restrict__ O) {
    extern __shared__ __nv_bfloat16 fsm[];
    __nv_bfloat16* Qh = fsm;
    __nv_bfloat16* Ql = fsm + QARR;
    __nv_bfloat16* KV = fsm + 2 * QARR;

    int tid = threadIdx.x;
    int warp = tid >> 5, lane = tid & 31;
    int g = lane >> 2, t = lane & 3;
    int q0 = blockIdx.x * 128;
    int h = blockIdx.y, b = blockIdx.z;
    size_t bh = (size_t)(b * Hh + h);
    const float* Qb = Q + bh * Lq * Dd;
    const __nv_bfloat16* KHIb = KHI + bh * Lq * Dd;
    const __nv_bfloat16* KLOb = KLO + bh * Lq * Dd;
    const __half* VTb = VT + bh * Dd * LPAD;

    int r0 = q0 + warp * 16 + g;
    int r1 = r0 + 8;

    int mi = lane >> 3, rr = lane & 7;
    unsigned ldsm_off = (((mi >> 1) * 8 + rr) * 72 + (mi & 1) * 8) * 2;
    unsigned q_off = (((mi & 1) * 8 + rr) * 72 + (mi >> 1) * 8) * 2;

    const float scale = 0.125f * 1.4426950408889634f;
    for (int it = tid; it < 128 * 16; it += 256) {
        int row = it >> 4, c4 = (it & 15) * 4;
        int l = q0 + row;
        float4 v = make_float4(0.f, 0.f, 0.f, 0.f);
        if (l < Lq) v = *(const float4*)&Qb[(size_t)l * Dd + c4];
        unsigned h0, l0w, h1, l1w;
        split2(v.x * scale, v.y * scale, h0, l0w);
        split2(v.z * scale, v.w * scale, h1, l1w);
        *(uint2*)&Qh[row * 72 + c4] = make_uint2(h0, h1);
        *(uint2*)&Ql[row * 72 + c4] = make_uint2(l0w, l1w);
    }

    float m0 = -1e30f, m1 = -1e30f, l0 = 0.f, l1 = 0.f;
    float o[8][4];
#pragma unroll
    for (int nf = 0; nf < 8; nf++)
#pragma unroll
        for (int q = 0; q < 4; q++) o[nf][q] = 0.f;

    auto stage = [&](int buf, int kt) {
        int k0 = kt * 64;
        __nv_bfloat16* B = KV + buf * FBUF;
#pragma unroll
        for (int p = 0; p < 6; p++) {
            int it = tid + p * 256;
            int arr = it >> 9;
            int idx = it & 511;
            int row = idx >> 3, c8 = (idx & 7) * 8;
            __nv_bfloat16* dst = B + arr * FARR + row * 72 + c8;
            if (arr < 2) {
                int kr = k0 + row;
                int krc = kr < Lq ? kr : 0;
                const __nv_bfloat16* src =
                    (arr == 0 ? KHIb : KLOb) + (size_t)krc * Dd + c8;
                cpa16(smaddr(dst), src, kr < Lq ? 16 : 0);
            } else {
                int col = k0 + c8;
                int colc = col < LPAD ? col : 0;
                const __half* src = VTb + (size_t)row * LPAD + colc;
                cpa16(smaddr(dst), src, col < LPAD ? 16 : 0);
            }
        }
    };

    int nkt = (Lq + 63) / 64;  // 33
    stage(0, 0);
    CPA_COMMIT;

    unsigned qhB = smaddr(Qh) + warp * 16 * 72 * 2 + q_off;
    unsigned qlB = qhB + QARR * 2;

    for (int kt = 0; kt < nkt; kt++) {
        CPA_WAIT0;
        __syncthreads();
        if (kt + 1 < nkt) {
            stage((kt + 1) & 1, kt + 1);
            CPA_COMMIT;
        }
        int k0 = kt * 64;
        unsigned khiB = smaddr(KV + (kt & 1) * FBUF) + ldsm_off;
        unsigned kloB = khiB + FARR * 2;
        unsigned vB = khiB + 2 * FARR * 2;

        float s[8][4];
#pragma unroll
        for (int nf = 0; nf < 8; nf++)
#pragma unroll
            for (int q = 0; q < 4; q++) s[nf][q] = 0.f;

#pragma unroll
        for (int ks = 0; ks < 4; ks++) {
            unsigned qh4[4], ql4[4];
            ldsm_x4(qh4[0], qh4[1], qh4[2], qh4[3], qhB + ks * 32);
            ldsm_x4(ql4[0], ql4[1], ql4[2], ql4[3], qlB + ks * 32);
#pragma unroll
            for (int q = 0; q < 4; q++) {
                unsigned off = (q * 16 * 72 + ks * 16) * 2;
                unsigned bh0[2], bh1[2], bl0[2], bl1[2];
                ldsm_x4(bh0[0], bh0[1], bh1[0], bh1[1], khiB + off);
                ldsm_x4(bl0[0], bl0[1], bl1[0], bl1[1], kloB + off);
                mma_bf16(s[2 * q], qh4, bh0);
                mma_bf16(s[2 * q], qh4, bl0);
                mma_bf16(s[2 * q], ql4, bh0);
                mma_bf16(s[2 * q + 1], qh4, bh1);
                mma_bf16(s[2 * q + 1], qh4, bl1);
                mma_bf16(s[2 * q + 1], ql4, bh1);
            }
        }

#pragma unroll
        for (int nf = 0; nf < 8; nf++) {
            int c = k0 + nf * 8 + 2 * t;
            if (c >= Lq) s[nf][0] = s[nf][2] = -1e30f;
            if (c + 1 >= Lq) s[nf][1] = s[nf][3] = -1e30f;
        }
        float mx0 = -1e30f, mx1 = -1e30f;
#pragma unroll
        for (int nf = 0; nf < 8; nf++) {
            mx0 = fmaxf(mx0, fmaxf(s[nf][0], s[nf][1]));
            mx1 = fmaxf(mx1, fmaxf(s[nf][2], s[nf][3]));
        }
        mx0 = fmaxf(mx0, __shfl_xor_sync(0xffffffffu, mx0, 1));
        mx0 = fmaxf(mx0, __shfl_xor_sync(0xffffffffu, mx0, 2));
        mx1 = fmaxf(mx1, __shfl_xor_sync(0xffffffffu, mx1, 1));
        mx1 = fmaxf(mx1, __shfl_xor_sync(0xffffffffu, mx1, 2));
        float mn0 = fmaxf(m0, mx0), mn1 = fmaxf(m1, mx1);
        float a0 = ex2f(m0 - mn0), a1 = ex2f(m1 - mn1);
        m0 = mn0;
        m1 = mn1;
        float rs0 = 0.f, rs1 = 0.f;
#pragma unroll
        for (int nf = 0; nf < 8; nf++) {
            s[nf][0] = ex2f(s[nf][0] - mn0);
            s[nf][1] = ex2f(s[nf][1] - mn0);
            s[nf][2] = ex2f(s[nf][2] - mn1);
            s[nf][3] = ex2f(s[nf][3] - mn1);
            rs0 += s[nf][0] + s[nf][1];
            rs1 += s[nf][2] + s[nf][3];
        }
        rs0 += __shfl_xor_sync(0xffffffffu, rs0, 1);
        rs0 += __shfl_xor_sync(0xffffffffu, rs0, 2);
        rs1 += __shfl_xor_sync(0xffffffffu, rs1, 1);
        rs1 += __shfl_xor_sync(0xffffffffu, rs1, 2);
        l0 = l0 * a0 + rs0;
        l1 = l1 * a1 + rs1;
#pragma unroll
        for (int nf = 0; nf < 8; nf++) {
            o[nf][0] *= a0;
            o[nf][1] *= a0;
            o[nf][2] *= a1;
            o[nf][3] *= a1;
        }

#pragma unroll
        for (int ks = 0; ks < 4; ks++) {
            unsigned ph[4], pl[4];
            split2h(s[2 * ks][0], s[2 * ks][1], ph[0], pl[0]);
            split2h(s[2 * ks][2], s[2 * ks][3], ph[1], pl[1]);
            split2h(s[2 * ks + 1][0], s[2 * ks + 1][1], ph[2], pl[2]);
            split2h(s[2 * ks + 1][2], s[2 * ks + 1][3], ph[3], pl[3]);
#pragma unroll
            for (int q = 0; q < 4; q++) {
                unsigned off = (q * 16 * 72 + ks * 16) * 2;
                unsigned vh0[2], vh1[2];
                ldsm_x4(vh0[0], vh0[1], vh1[0], vh1[1], vB + off);
                mma_f16(o[2 * q], ph, vh0);
                mma_f16(o[2 * q], pl, vh0);
                mma_f16(o[2 * q + 1], ph, vh1);
                mma_f16(o[2 * q + 1], pl, vh1);
            }
        }
    }

    float inv0 = 1.f / l0, inv1 = 1.f / l1;
#pragma unroll
    for (int nf = 0; nf < 8; nf++) {
        int col = h * Dd + nf * 8 + 2 * t;
        if (r0 < Lq)
            *(float2*)&O[((size_t)b * Lq + r0) * Cc + col] =
                make_float2(o[nf][0] * inv0, o[nf][1] * inv0);
        if (r1 < Lq)
            *(float2*)&O[((size_t)b * Lq + r1) * Cc + col] =
                make_float2(o[nf][2] * inv1, o[nf][3] * inv1);
    }
}

// ---------------------------------------------------------------------------
// LayerNorm; output rounded to tf32 (unchanged)
// ---------------------------------------------------------------------------
__global__ void ln_kernel(const float* __restrict__ in,
                          const float* __restrict__ gamma,
                          const float* __restrict__ beta,
                          float* __restrict__ out) {
    int row = blockIdx.x;
    int tid = threadIdx.x;
    const float* r = in + (size_t)row * Cc;
    float4 v = *(const float4*)&r[tid * 4];
    float s = v.x + v.y + v.z + v.w;
    float s2 = v.x * v.x + v.y * v.y + v.z * v.z + v.w * v.w;
#pragma unroll
    for (int off = 16; off >= 1; off >>= 1) {
        s += __shfl_xor_sync(0xffffffffu, s, off);
        s2 += __shfl_xor_sync(0xffffffffu, s2, off);
    }
    __shared__ float ws[8], ws2[8];
    __shared__ float mean_s, rstd_s;
    int wid = tid >> 5, lane = tid & 31;
    if (lane == 0) {
        ws[wid] = s;
        ws2[wid] = s2;
    }
    __syncthreads();
    if (tid == 0) {
        float S = 0.f, S2 = 0.f;
#pragma unroll
        for (int i = 0; i < 8; i++) {
            S += ws[i];
            S2 += ws2[i];
        }
        float mean = S * (1.f / Cc);
        float var = S2 * (1.f / Cc) - mean * mean;
        mean_s = mean;
        rstd_s = rsqrtf(var + 1e-5f);
    }
    __syncthreads();
    float mean = mean_s, rstd = rstd_s;
    float4 g = *(const float4*)&gamma[tid * 4];
    float4 bt = *(const float4*)&beta[tid * 4];
    float4 o;
    o.x = __uint_as_float(f2tf32((v.x - mean) * rstd * g.x + bt.x));
    o.y = __uint_as_float(f2tf32((v.y - mean) * rstd * g.y + bt.y));
    o.z = __uint_as_float(f2tf32((v.z - mean) * rstd * g.z + bt.z));
    o.w = __uint_as_float(f2tf32((v.w - mean) * rstd * g.w + bt.w));
    *(float4*)&out[(size_t)row * Cc + tid * 4] = o;
}

// ---------------------------------------------------------------------------
extern "C" void kernel_launch(void* const* d_in, const int* in_sizes, int n_in,
                              void* d_out, int out_size) {
    const float* x = (const float*)d_in[0];
    const float* rope = (const float*)d_in[1];
    const float* Wqkv = (const float*)d_in[2];
    const float* bqkv = (const float*)d_in[3];
    const float* Wproj = (const float*)d_in[4];
    const float* bproj = (const float*)d_in[5];
    const float* gamma = (const float*)d_in[6];
    const float* beta = (const float*)d_in[7];
    float* out = (float*)d_out;

    float *qkv, *q, *attn, *ln, *xr, *wqkvT, *wprojT;
    __nv_bfloat16 *khi, *klo;
    __half* vt;
    cudaGetSymbolAddress((void**)&qkv, g_qkv);
    cudaGetSymbolAddress((void**)&q, g_q);
    cudaGetSymbolAddress((void**)&khi, g_khi);
    cudaGetSymbolAddress((void**)&klo, g_klo);
    cudaGetSymbolAddress((void**)&vt, g_vt);
    cudaGetSymbolAddress((void**)&attn, g_attn);
    cudaGetSymbolAddress((void**)&ln, g_ln);
    cudaGetSymbolAddress((void**)&xr, g_xr);
    cudaGetSymbolAddress((void**)&wqkvT, g_wqkvT);
    cudaGetSymbolAddress((void**)&wprojT, g_wprojT);

    const int M = ROWS;  // 8208

    // 0) pre-round x; transpose+round weights to [N][K]
    int nx4 = ROWS * Cc / 4;
    round_tf32_kernel<<<(nx4 + 255) / 256, 256>>>(x, xr, nx4);
    transpose_round_kernel<<<dim3(3 * Cc / 32, Cc / 32), dim3(32, 8)>>>(
        Wqkv, wqkvT, Cc, 3 * Cc);
    transpose_round_kernel<<<dim3(Cc / 32, Cc / 32), dim3(32, 8)>>>(
        Wproj, wprojT, Cc, Cc);

    // 1) QKV GEMM: [8208,1024] @ [1024,3072] + bqkv  (tiles 128x256)
    cudaFuncSetAttribute(gemm_tf32_db, cudaFuncAttributeMaxDynamicSharedMemorySize,
                         GEMM_SMEM);
    gemm_tf32_db<<<dim3(3 * Cc / 256, (M + 127) / 128), 256, GEMM_SMEM>>>(
        xr, wqkvT, bqkv, qkv, M, 3 * Cc, Cc);

    // 2) RoPE + split + transpose
    rope_split_kernel<<<dim3((Lq + 63) / 64, Hh, Bb), 256>>>(
        qkv, rope, q, khi, klo, vt);

    // 3) Flash attention
    cudaFuncSetAttribute(flash_mma_db, cudaFuncAttributeMaxDynamicSharedMemorySize,
                         FLASH_SMEM);
    flash_mma_db<<<dim3((Lq + 127) / 128, Hh, Bb), 256, FLASH_SMEM>>>(
        q, khi, klo, vt, attn);

    // 4) LayerNorm (emits tf32-rounded)
    ln_kernel<<<M, 256>>>(attn, gamma, beta, ln);

    // 5) Projection GEMM: [8208,1024] @ [1024,1024] + bproj
    gemm_tf32_db<<<dim3(Cc / 256, (M + 127) / 128), 256, GEMM_SMEM>>>(
        ln, wprojT, bproj, out, M, Cc, Cc);
}